// round 1
// baseline (speedup 1.0000x reference)
#include <cuda_runtime.h>
#include <math.h>
#include <stdint.h>

// Problem constants
#define MTOK   8192      // B*S = 4*2048 tokens
#define DMODEL 1024
#define DFF    4096
#define SEQ    2048
#define NH     16
#define HD     64

// ---------------------------------------------------------------------------
// Scratch (static device globals; no runtime allocation allowed)
// ---------------------------------------------------------------------------
__device__ float g_normed[(size_t)MTOK * DMODEL];
__device__ float g_q     [(size_t)MTOK * DMODEL];
__device__ float g_k     [(size_t)MTOK * DMODEL];
__device__ float g_v     [(size_t)MTOK * DMODEL];
__device__ float g_attn  [(size_t)MTOK * DMODEL];
__device__ float g_x1    [(size_t)MTOK * DMODEL];
__device__ float g_hbuf  [(size_t)MTOK * DFF];

// ---------------------------------------------------------------------------
// LayerNorm: one block per row (1024 cols), 256 threads, float4 per thread
// ---------------------------------------------------------------------------
__global__ __launch_bounds__(256)
void ln_kernel(const float* __restrict__ x, const float* __restrict__ g,
               const float* __restrict__ b, float* __restrict__ out)
{
    int row = blockIdx.x;
    int t   = threadIdx.x;
    const float4 v = ((const float4*)(x + (size_t)row * DMODEL))[t];

    float s  = v.x + v.y + v.z + v.w;
    float ss = v.x * v.x + v.y * v.y + v.z * v.z + v.w * v.w;

    #pragma unroll
    for (int o = 16; o > 0; o >>= 1) {
        s  += __shfl_xor_sync(0xffffffffu, s,  o);
        ss += __shfl_xor_sync(0xffffffffu, ss, o);
    }
    __shared__ float rs[8], rss[8];
    if ((t & 31) == 0) { rs[t >> 5] = s; rss[t >> 5] = ss; }
    __syncthreads();
    if (t < 32) {
        s  = (t < 8) ? rs[t]  : 0.f;
        ss = (t < 8) ? rss[t] : 0.f;
        #pragma unroll
        for (int o = 4; o > 0; o >>= 1) {
            s  += __shfl_xor_sync(0xffffffffu, s,  o);
            ss += __shfl_xor_sync(0xffffffffu, ss, o);
        }
        if (t == 0) { rs[0] = s; rss[0] = ss; }
    }
    __syncthreads();
    const float mu  = rs[0]  * (1.0f / DMODEL);
    const float var = rss[0] * (1.0f / DMODEL) - mu * mu;
    const float inv = rsqrtf(var + 1e-5f);

    const float4 gv = ((const float4*)g)[t];
    const float4 bv = ((const float4*)b)[t];
    float4 o;
    o.x = (v.x - mu) * inv * gv.x + bv.x;
    o.y = (v.y - mu) * inv * gv.y + bv.y;
    o.z = (v.z - mu) * inv * gv.z + bv.z;
    o.w = (v.w - mu) * inv * gv.w + bv.w;
    ((float4*)(out + (size_t)row * DMODEL))[t] = o;
}

// ---------------------------------------------------------------------------
// SGEMM: C[M,N] = A[M,K] @ B[K,N] + bias[N]  (+ optional residual, + GELU)
// 128x128x16 block tile, 256 threads, 8x8 per-thread microtile.
// M,N multiples of 128; K multiple of 16 (true for all shapes here).
// ---------------------------------------------------------------------------
__device__ __forceinline__ float gelu_exact(float x)
{
    return 0.5f * x * (1.0f + erff(x * 0.70710678118654752f));
}

template <int ACT>  // 0 = none, 1 = exact GELU
__global__ __launch_bounds__(256)
void gemm_kernel(const float* __restrict__ A, const float* __restrict__ B,
                 const float* __restrict__ bias, const float* __restrict__ res,
                 float* __restrict__ C, int M, int N, int K)
{
    __shared__ float As[16 * 128];   // transposed: As[k][m]
    __shared__ float Bs[16 * 128];   // Bs[k][n]

    const int t  = threadIdx.x;
    const int a0 = blockIdx.y * 128;
    const int b0 = blockIdx.x * 128;

    const int ar = t >> 2;            // 0..63 (A tile row)
    const int ac = (t & 3) << 2;      // 0,4,8,12 (A tile col, float4)
    const int br = t >> 5;            // 0..7 (B tile row)
    const int bc = (t & 31) << 2;     // 0..124 step 4
    const int tr = t >> 4;            // 0..15
    const int tc = t & 15;            // 0..15

    float acc[8][8];
    #pragma unroll
    for (int i = 0; i < 8; i++)
        #pragma unroll
        for (int j = 0; j < 8; j++) acc[i][j] = 0.f;

    const float* Ap0 = A + (size_t)(a0 + ar) * K + ac;
    const float* Ap1 = Ap0 + (size_t)64 * K;
    const float* Bp0 = B + (size_t)br * N + b0 + bc;
    const float* Bp1 = Bp0 + (size_t)8 * N;

    for (int k0 = 0; k0 < K; k0 += 16) {
        const float4 av0 = *(const float4*)(Ap0 + k0);
        const float4 av1 = *(const float4*)(Ap1 + k0);
        const float4 bv0 = *(const float4*)(Bp0 + (size_t)k0 * N);
        const float4 bv1 = *(const float4*)(Bp1 + (size_t)k0 * N);

        __syncthreads();
        As[(ac + 0) * 128 + ar] = av0.x;
        As[(ac + 1) * 128 + ar] = av0.y;
        As[(ac + 2) * 128 + ar] = av0.z;
        As[(ac + 3) * 128 + ar] = av0.w;
        As[(ac + 0) * 128 + ar + 64] = av1.x;
        As[(ac + 1) * 128 + ar + 64] = av1.y;
        As[(ac + 2) * 128 + ar + 64] = av1.z;
        As[(ac + 3) * 128 + ar + 64] = av1.w;
        *(float4*)&Bs[br * 128 + bc]       = bv0;
        *(float4*)&Bs[(br + 8) * 128 + bc] = bv1;
        __syncthreads();

        #pragma unroll
        for (int k = 0; k < 16; k++) {
            const float4 a_0 = *(const float4*)&As[k * 128 + tr * 8];
            const float4 a_1 = *(const float4*)&As[k * 128 + tr * 8 + 4];
            const float4 b_0 = *(const float4*)&Bs[k * 128 + tc * 8];
            const float4 b_1 = *(const float4*)&Bs[k * 128 + tc * 8 + 4];
            const float ra[8] = {a_0.x, a_0.y, a_0.z, a_0.w, a_1.x, a_1.y, a_1.z, a_1.w};
            const float rb[8] = {b_0.x, b_0.y, b_0.z, b_0.w, b_1.x, b_1.y, b_1.z, b_1.w};
            #pragma unroll
            for (int i = 0; i < 8; i++)
                #pragma unroll
                for (int j = 0; j < 8; j++)
                    acc[i][j] = fmaf(ra[i], rb[j], acc[i][j]);
        }
    }

    #pragma unroll
    for (int i = 0; i < 8; i++) {
        const int row = a0 + tr * 8 + i;
        #pragma unroll
        for (int jj = 0; jj < 8; jj += 4) {
            const int col = b0 + tc * 8 + jj;
            const float4 b4 = *(const float4*)&bias[col];
            float4 c;
            c.x = acc[i][jj + 0] + b4.x;
            c.y = acc[i][jj + 1] + b4.y;
            c.z = acc[i][jj + 2] + b4.z;
            c.w = acc[i][jj + 3] + b4.w;
            if (ACT == 1) {
                c.x = gelu_exact(c.x); c.y = gelu_exact(c.y);
                c.z = gelu_exact(c.z); c.w = gelu_exact(c.w);
            }
            if (res) {
                const float4 r4 = *(const float4*)&res[(size_t)row * N + col];
                c.x += r4.x; c.y += r4.y; c.z += r4.z; c.w += r4.w;
            }
            *(float4*)&C[(size_t)row * N + col] = c;
        }
    }
}

// ---------------------------------------------------------------------------
// Causal flash attention.
// Grid: (SEQ/128, NH, B). Block: 128 threads, one query row per thread.
// Q stored transposed in smem [HD][128] (conflict-free per-thread reads).
// K/V tiles of 32 rows. Online softmax per row.
// Dynamic smem = (64*128 + 32*64 + 32*64) * 4 = 49152 bytes.
// ---------------------------------------------------------------------------
__global__ __launch_bounds__(128)
void attn_kernel(const float* __restrict__ Q, const float* __restrict__ K,
                 const float* __restrict__ V, float* __restrict__ O)
{
    extern __shared__ float smem[];
    float* Qs = smem;               // [HD][128] transposed
    float* Ks = smem + 64 * 128;    // [32][64]
    float* Vs = Ks + 32 * 64;       // [32][64]

    const int r  = threadIdx.x;     // query row within tile
    const int qt = blockIdx.x;
    const int h  = blockIdx.y;
    const int b  = blockIdx.z;
    const int q0 = qt * 128;
    const int qg = q0 + r;                        // global query index in sequence
    const size_t tokq = (size_t)b * SEQ + q0 + r; // token index

    // Load own Q row into transposed smem (written & read by same thread)
    {
        const float* qrow = Q + tokq * DMODEL + h * HD;
        #pragma unroll
        for (int k4 = 0; k4 < HD; k4 += 4) {
            const float4 qv = *(const float4*)(qrow + k4);
            Qs[(k4 + 0) * 128 + r] = qv.x;
            Qs[(k4 + 1) * 128 + r] = qv.y;
            Qs[(k4 + 2) * 128 + r] = qv.z;
            Qs[(k4 + 3) * 128 + r] = qv.w;
        }
    }

    float acc[HD];
    #pragma unroll
    for (int d = 0; d < HD; d++) acc[d] = 0.f;
    float m = -1e30f, l = 0.f;
    const float scale = 0.125f;  // 1/sqrt(64)

    const int ntiles = (q0 + 128) / 32;  // key tiles needed for this query block

    for (int kt = 0; kt < ntiles; kt++) {
        const size_t kbase = (size_t)b * SEQ + kt * 32;

        __syncthreads();  // protect previous tile reads
        #pragma unroll
        for (int p = 0; p < 4; p++) {
            const int f   = threadIdx.x + 128 * p;   // 0..511 float4 slots
            const int row = f >> 4;                  // 0..31
            const int c4  = (f & 15) << 2;           // 0..60 step 4
            *(float4*)&Ks[row * 64 + c4] =
                *(const float4*)(K + (kbase + row) * DMODEL + h * HD + c4);
            *(float4*)&Vs[row * 64 + c4] =
                *(const float4*)(V + (kbase + row) * DMODEL + h * HD + c4);
        }
        __syncthreads();

        // Dot products: s[j] = Q[r] . K[j]
        float s[32];
        #pragma unroll
        for (int j = 0; j < 32; j++) s[j] = 0.f;
        #pragma unroll 4
        for (int k = 0; k < HD; k++) {
            const float qk = Qs[k * 128 + r];
            #pragma unroll
            for (int j = 0; j < 32; j++)
                s[j] = fmaf(qk, Ks[j * 64 + k], s[j]);
        }

        // Mask + scale + tile max
        const int kt0 = kt * 32;
        float tmax = -1e30f;
        #pragma unroll
        for (int j = 0; j < 32; j++) {
            s[j] = (kt0 + j <= qg) ? s[j] * scale : -1e30f;
            tmax = fmaxf(tmax, s[j]);
        }

        const float mnew = fmaxf(m, tmax);
        const float corr = __expf(m - mnew);
        l *= corr;
        #pragma unroll
        for (int d = 0; d < HD; d++) acc[d] *= corr;

        #pragma unroll
        for (int j = 0; j < 32; j++) {
            const float p = __expf(s[j] - mnew);
            l += p;
            #pragma unroll
            for (int d = 0; d < HD; d++)
                acc[d] = fmaf(p, Vs[j * 64 + d], acc[d]);
        }
        m = mnew;
    }

    const float inv = 1.0f / l;
    float* orow = O + tokq * DMODEL + h * HD;
    #pragma unroll
    for (int d = 0; d < HD; d += 4) {
        float4 o;
        o.x = acc[d + 0] * inv;
        o.y = acc[d + 1] * inv;
        o.z = acc[d + 2] * inv;
        o.w = acc[d + 3] * inv;
        *(float4*)(orow + d) = o;
    }
}

// ---------------------------------------------------------------------------
// Launch: LN1 -> Q/K/V GEMMs -> attention -> O GEMM(+res) -> LN2
//         -> FF1 GEMM(GELU) -> FF2 GEMM(+res) -> d_out
// ---------------------------------------------------------------------------
extern "C" void kernel_launch(void* const* d_in, const int* in_sizes, int n_in,
                              void* d_out, int out_size)
{
    const float* x     = (const float*)d_in[0];
    const float* wq    = (const float*)d_in[1];
    const float* bq    = (const float*)d_in[2];
    const float* wk    = (const float*)d_in[3];
    const float* bk    = (const float*)d_in[4];
    const float* wv    = (const float*)d_in[5];
    const float* bv    = (const float*)d_in[6];
    const float* wo    = (const float*)d_in[7];
    const float* bo    = (const float*)d_in[8];
    const float* w1    = (const float*)d_in[9];
    const float* b1    = (const float*)d_in[10];
    const float* w2    = (const float*)d_in[11];
    const float* b2    = (const float*)d_in[12];
    const float* ln1_g = (const float*)d_in[13];
    const float* ln1_b = (const float*)d_in[14];
    const float* ln2_g = (const float*)d_in[15];
    const float* ln2_b = (const float*)d_in[16];
    float* out = (float*)d_out;

    float *normed, *q, *k, *v, *attn, *x1, *h;
    cudaGetSymbolAddress((void**)&normed, g_normed);
    cudaGetSymbolAddress((void**)&q,      g_q);
    cudaGetSymbolAddress((void**)&k,      g_k);
    cudaGetSymbolAddress((void**)&v,      g_v);
    cudaGetSymbolAddress((void**)&attn,   g_attn);
    cudaGetSymbolAddress((void**)&x1,     g_x1);
    cudaGetSymbolAddress((void**)&h,      g_hbuf);

    cudaFuncSetAttribute(attn_kernel,
                         cudaFuncAttributeMaxDynamicSharedMemorySize, 65536);

    // LN1
    ln_kernel<<<MTOK, 256>>>(x, ln1_g, ln1_b, normed);

    // Q/K/V projections
    dim3 gQ(DMODEL / 128, MTOK / 128);
    gemm_kernel<0><<<gQ, 256>>>(normed, wq, bq, nullptr, q, MTOK, DMODEL, DMODEL);
    gemm_kernel<0><<<gQ, 256>>>(normed, wk, bk, nullptr, k, MTOK, DMODEL, DMODEL);
    gemm_kernel<0><<<gQ, 256>>>(normed, wv, bv, nullptr, v, MTOK, DMODEL, DMODEL);

    // Causal attention
    attn_kernel<<<dim3(SEQ / 128, NH, 4), 128, 49152>>>(q, k, v, attn);

    // Output projection + residual
    gemm_kernel<0><<<gQ, 256>>>(attn, wo, bo, x, x1, MTOK, DMODEL, DMODEL);

    // LN2 (reuse normed buffer)
    ln_kernel<<<MTOK, 256>>>(x1, ln2_g, ln2_b, normed);

    // FF1 with exact GELU
    dim3 gF1(DFF / 128, MTOK / 128);
    gemm_kernel<1><<<gF1, 256>>>(normed, w1, b1, nullptr, h, MTOK, DFF, DMODEL);

    // FF2 + residual -> final output
    dim3 gF2(DMODEL / 128, MTOK / 128);
    gemm_kernel<0><<<gF2, 256>>>(h, w2, b2, x1, out, MTOK, DMODEL, DFF);
}

// round 4
// speedup vs baseline: 2.0347x; 2.0347x over previous
#include <cuda_runtime.h>
#include <cuda_bf16.h>
#include <math.h>
#include <stdint.h>

// Problem constants
#define MTOK   8192      // B*S
#define DMODEL 1024
#define DFF    4096
#define SEQ    2048
#define NH     16
#define HD     64

typedef __nv_bfloat16 bf16;

// ---------------------------------------------------------------------------
// Scratch (static device globals)
// ---------------------------------------------------------------------------
__device__ float g_q   [(size_t)MTOK * DMODEL];
__device__ float g_k   [(size_t)MTOK * DMODEL];
__device__ float g_v   [(size_t)MTOK * DMODEL];
__device__ float g_attn[(size_t)MTOK * DMODEL];
__device__ float g_x1  [(size_t)MTOK * DMODEL];

__device__ bf16 g_nhi[(size_t)MTOK * DMODEL];
__device__ bf16 g_nlo[(size_t)MTOK * DMODEL];
__device__ bf16 g_ahi[(size_t)MTOK * DMODEL];
__device__ bf16 g_alo[(size_t)MTOK * DMODEL];
__device__ bf16 g_hhi[(size_t)MTOK * DFF];
__device__ bf16 g_hlo[(size_t)MTOK * DFF];

// transposed+split weights [N,K]
__device__ bf16 g_wqh[(size_t)DMODEL * DMODEL];
__device__ bf16 g_wql[(size_t)DMODEL * DMODEL];
__device__ bf16 g_wkh[(size_t)DMODEL * DMODEL];
__device__ bf16 g_wkl[(size_t)DMODEL * DMODEL];
__device__ bf16 g_wvh[(size_t)DMODEL * DMODEL];
__device__ bf16 g_wvl[(size_t)DMODEL * DMODEL];
__device__ bf16 g_woh[(size_t)DMODEL * DMODEL];
__device__ bf16 g_wol[(size_t)DMODEL * DMODEL];
__device__ bf16 g_w1h[(size_t)DFF * DMODEL];
__device__ bf16 g_w1l[(size_t)DFF * DMODEL];
__device__ bf16 g_w2h[(size_t)DMODEL * DFF];
__device__ bf16 g_w2l[(size_t)DMODEL * DFF];

// ---------------------------------------------------------------------------
// PTX helpers (non-'a'-gated only: cp.async, ldmatrix, mma.sync)
// ---------------------------------------------------------------------------
__device__ __forceinline__ uint32_t smem_to_u32(const void* p) {
    uint32_t a;
    asm("{ .reg .u64 t; cvta.to.shared.u64 t, %1; cvt.u32.u64 %0, t; }" : "=r"(a) : "l"(p));
    return a;
}
#define CP_ASYNC_CG(dst, src) \
    asm volatile("cp.async.cg.shared.global [%0], [%1], 16;" :: "r"(dst), "l"(src) : "memory")
#define CP_ASYNC_COMMIT() asm volatile("cp.async.commit_group;" ::: "memory")
#define CP_ASYNC_WAIT(n)  asm volatile("cp.async.wait_group %0;" :: "n"(n) : "memory")

#define LDMATRIX_X4(r0, r1, r2, r3, addr) \
    asm volatile("ldmatrix.sync.aligned.m8n8.x4.shared.b16 {%0,%1,%2,%3}, [%4];" \
                 : "=r"(r0), "=r"(r1), "=r"(r2), "=r"(r3) : "r"(addr))

#define MMA_BF16(c, a, b) \
    asm volatile("mma.sync.aligned.m16n8k16.row.col.f32.bf16.bf16.f32 " \
                 "{%0,%1,%2,%3}, {%4,%5,%6,%7}, {%8,%9}, {%0,%1,%2,%3};" \
                 : "+f"((c)[0]), "+f"((c)[1]), "+f"((c)[2]), "+f"((c)[3]) \
                 : "r"((a)[0]), "r"((a)[1]), "r"((a)[2]), "r"((a)[3]), \
                   "r"((b)[0]), "r"((b)[1]))

__device__ __forceinline__ float gelu_exact(float x) {
    return 0.5f * x * (1.0f + erff(x * 0.70710678118654752f));
}

extern __shared__ char dynsmem[];

// ---------------------------------------------------------------------------
// bf16 mma.sync GEMM: C[M,N] = (Ahi+Alo)[M,K] @ (Bhi+Blo)[N,K]^T + bias
// (3-term split: hi*hi + lo*hi + hi*lo, fp32 accum)
// CTA 128x128, 8 warps (warp tile 32x64), K-chunk 64, 3-stage cp.async.
// Smem layout per 64KB stage: Ahi[128][64] | Alo | Bhi[128][64] | Blo
// (rows = 128B, SW128-swizzled quads).
// ---------------------------------------------------------------------------
#define BK 64
#define STAGES 3
#define STAGE_BYTES 65536
#define TGEMM_SMEM (STAGES * STAGE_BYTES)

__device__ __forceinline__ void issue_stage(
    const bf16* __restrict__ Ahi, const bf16* __restrict__ Alo,
    const bf16* __restrict__ Bhi, const bf16* __restrict__ Blo,
    int K, int k0, uint32_t stage_base, int tid)
{
    #pragma unroll
    for (int i = 0; i < 16; i++) {
        const int idx  = i * 256 + tid;
        const int tile = idx >> 10;          // 0..3 (compile-time per i)
        const int rem  = idx & 1023;
        const int row  = rem >> 3;           // 0..127
        const int quad = rem & 7;            // 0..7
        const bf16* src;
        if      (tile == 0) src = Ahi;
        else if (tile == 1) src = Alo;
        else if (tile == 2) src = Bhi;
        else                src = Blo;
        src += (size_t)row * K + k0 + quad * 8;
        const uint32_t dst = stage_base + tile * 16384 + row * 128 +
                             ((quad ^ (row & 7)) * 16);
        CP_ASYNC_CG(dst, src);
    }
}

template <bool GELU, bool RES, bool SPLITOUT>
__global__ __launch_bounds__(256, 1)
void tgemm_kernel(const bf16* __restrict__ Ahi, const bf16* __restrict__ Alo,
                  const bf16* __restrict__ Bhi, const bf16* __restrict__ Blo,
                  const float* __restrict__ bias, const float* __restrict__ res,
                  float* __restrict__ Cf, bf16* __restrict__ Chi, bf16* __restrict__ Clo,
                  int M, int N, int K)
{
    const uint32_t sb = smem_to_u32(dynsmem);
    const int tid = threadIdx.x;
    const int wid = tid >> 5;
    const int lid = tid & 31;

    const int a0 = blockIdx.y * 128;
    const int b0 = blockIdx.x * 128;
    const int m_w = (wid & 3) * 32;   // warp M origin in tile
    const int n_w = (wid >> 2) * 64;  // warp N origin in tile

    const bf16* Ah = Ahi + (size_t)a0 * K;
    const bf16* Al = Alo + (size_t)a0 * K;
    const bf16* Bh = Bhi + (size_t)b0 * K;
    const bf16* Bl = Blo + (size_t)b0 * K;

    const int nch = K / BK;

    // Prologue: fill STAGES-1 stages
    #pragma unroll
    for (int s = 0; s < STAGES - 1; s++) {
        issue_stage(Ah, Al, Bh, Bl, K, s * BK, sb + s * STAGE_BYTES, tid);
        CP_ASYNC_COMMIT();
    }

    float acc[2][8][4];
    #pragma unroll
    for (int i = 0; i < 2; i++)
        #pragma unroll
        for (int j = 0; j < 8; j++)
            #pragma unroll
            for (int c = 0; c < 4; c++) acc[i][j][c] = 0.f;

    // Precomputed ldmatrix lane offsets
    const int bA  = lid >> 3;          // block index 0..3
    const int r8  = lid & 7;
    const int rowA_off = ((bA & 1) * 8) + r8;   // A: row within m16
    const int qA_off   = bA >> 1;               // A: quad within k16
    const int rowB_off = ((bA >> 1) * 8) + r8;  // B: row within n16
    const int qB_off   = bA & 1;                // B: quad within k16

    for (int i = 0; i < nch; i++) {
        if (i + 1 < nch) { CP_ASYNC_WAIT(1); } else { CP_ASYNC_WAIT(0); }
        __syncthreads();

        if (i + STAGES - 1 < nch)
            issue_stage(Ah, Al, Bh, Bl, K, (i + STAGES - 1) * BK,
                        sb + ((i + STAGES - 1) % STAGES) * STAGE_BYTES, tid);
        CP_ASYNC_COMMIT();

        const uint32_t st = sb + (i % STAGES) * STAGE_BYTES;
        const uint32_t sAh = st,           sAl = st + 16384;
        const uint32_t sBh = st + 32768,   sBl = st + 49152;

        #pragma unroll
        for (int ks = 0; ks < 4; ks++) {
            const int kq = ks * 2;
            uint32_t ah[2][4], al[2][4], bh[8][2], bl[8][2];

            #pragma unroll
            for (int mt = 0; mt < 2; mt++) {
                const int row  = m_w + mt * 16 + rowA_off;
                const int quad = kq + qA_off;
                const uint32_t off = row * 128 + ((quad ^ (row & 7)) * 16);
                LDMATRIX_X4(ah[mt][0], ah[mt][1], ah[mt][2], ah[mt][3], sAh + off);
                LDMATRIX_X4(al[mt][0], al[mt][1], al[mt][2], al[mt][3], sAl + off);
            }
            #pragma unroll
            for (int np = 0; np < 4; np++) {
                const int row  = n_w + np * 16 + rowB_off;
                const int quad = kq + qB_off;
                const uint32_t off = row * 128 + ((quad ^ (row & 7)) * 16);
                LDMATRIX_X4(bh[np * 2][0], bh[np * 2][1], bh[np * 2 + 1][0], bh[np * 2 + 1][1], sBh + off);
                LDMATRIX_X4(bl[np * 2][0], bl[np * 2][1], bl[np * 2 + 1][0], bl[np * 2 + 1][1], sBl + off);
            }

            #pragma unroll
            for (int mt = 0; mt < 2; mt++)
                #pragma unroll
                for (int nt = 0; nt < 8; nt++) {
                    MMA_BF16(acc[mt][nt], ah[mt], bh[nt]);
                    MMA_BF16(acc[mt][nt], al[mt], bh[nt]);
                    MMA_BF16(acc[mt][nt], ah[mt], bl[nt]);
                }
        }
    }

    // Epilogue straight from registers
    const int gl  = lid >> 2;   // group 0..7
    const int tg  = lid & 3;    // thread-in-group
    #pragma unroll
    for (int mt = 0; mt < 2; mt++) {
        #pragma unroll
        for (int half = 0; half < 2; half++) {
            const int row = a0 + m_w + mt * 16 + gl + half * 8;
            #pragma unroll
            for (int nt = 0; nt < 8; nt++) {
                const int col = b0 + n_w + nt * 8 + tg * 2;
                float v0 = acc[mt][nt][half * 2 + 0];
                float v1 = acc[mt][nt][half * 2 + 1];
                const float2 bb = *(const float2*)&bias[col];
                v0 += bb.x; v1 += bb.y;
                if (GELU) { v0 = gelu_exact(v0); v1 = gelu_exact(v1); }
                if (RES) {
                    const float2 r2 = *(const float2*)&res[(size_t)row * N + col];
                    v0 += r2.x; v1 += r2.y;
                }
                if (SPLITOUT) {
                    const bf16 h0 = __float2bfloat16(v0);
                    const bf16 h1 = __float2bfloat16(v1);
                    const bf16 l0 = __float2bfloat16(v0 - __bfloat162float(h0));
                    const bf16 l1 = __float2bfloat16(v1 - __bfloat162float(h1));
                    __nv_bfloat162 hp; hp.x = h0; hp.y = h1;
                    __nv_bfloat162 lp; lp.x = l0; lp.y = l1;
                    *(__nv_bfloat162*)&Chi[(size_t)row * N + col] = hp;
                    *(__nv_bfloat162*)&Clo[(size_t)row * N + col] = lp;
                } else {
                    float2 o; o.x = v0; o.y = v1;
                    *(float2*)&Cf[(size_t)row * N + col] = o;
                }
            }
        }
    }
}

// ---------------------------------------------------------------------------
// LayerNorm with split bf16 output (hi/lo)
// ---------------------------------------------------------------------------
__global__ __launch_bounds__(256)
void ln_split_kernel(const float* __restrict__ x, const float* __restrict__ g,
                     const float* __restrict__ b, bf16* __restrict__ ohi, bf16* __restrict__ olo)
{
    const int row = blockIdx.x;
    const int t   = threadIdx.x;
    const float4 v = ((const float4*)(x + (size_t)row * DMODEL))[t];

    float s  = v.x + v.y + v.z + v.w;
    float ss = v.x * v.x + v.y * v.y + v.z * v.z + v.w * v.w;
    #pragma unroll
    for (int o = 16; o > 0; o >>= 1) {
        s  += __shfl_xor_sync(0xffffffffu, s,  o);
        ss += __shfl_xor_sync(0xffffffffu, ss, o);
    }
    __shared__ float rs[8], rss[8];
    if ((t & 31) == 0) { rs[t >> 5] = s; rss[t >> 5] = ss; }
    __syncthreads();
    if (t < 32) {
        s  = (t < 8) ? rs[t]  : 0.f;
        ss = (t < 8) ? rss[t] : 0.f;
        #pragma unroll
        for (int o = 4; o > 0; o >>= 1) {
            s  += __shfl_xor_sync(0xffffffffu, s,  o);
            ss += __shfl_xor_sync(0xffffffffu, ss, o);
        }
        if (t == 0) { rs[0] = s; rss[0] = ss; }
    }
    __syncthreads();
    const float mu  = rs[0]  * (1.0f / DMODEL);
    const float var = rss[0] * (1.0f / DMODEL) - mu * mu;
    const float inv = rsqrtf(var + 1e-5f);

    const float4 gv = ((const float4*)g)[t];
    const float4 bv = ((const float4*)b)[t];
    float o[4];
    o[0] = (v.x - mu) * inv * gv.x + bv.x;
    o[1] = (v.y - mu) * inv * gv.y + bv.y;
    o[2] = (v.z - mu) * inv * gv.z + bv.z;
    o[3] = (v.w - mu) * inv * gv.w + bv.w;

    uint32_t hp[2], lp[2];
    #pragma unroll
    for (int i = 0; i < 2; i++) {
        const bf16 h0 = __float2bfloat16(o[2 * i]);
        const bf16 h1 = __float2bfloat16(o[2 * i + 1]);
        const bf16 l0 = __float2bfloat16(o[2 * i] - __bfloat162float(h0));
        const bf16 l1 = __float2bfloat16(o[2 * i + 1] - __bfloat162float(h1));
        __nv_bfloat162 h2; h2.x = h0; h2.y = h1;
        __nv_bfloat162 l2; l2.x = l0; l2.y = l1;
        hp[i] = *(uint32_t*)&h2; lp[i] = *(uint32_t*)&l2;
    }
    ((uint2*)(ohi + (size_t)row * DMODEL))[t] = make_uint2(hp[0], hp[1]);
    ((uint2*)(olo + (size_t)row * DMODEL))[t] = make_uint2(lp[0], lp[1]);
}

// elementwise fp32 -> (hi, lo) bf16
__global__ __launch_bounds__(256)
void split_kernel(const float* __restrict__ in, bf16* __restrict__ hi, bf16* __restrict__ lo)
{
    const size_t i4 = (size_t)blockIdx.x * 256 + threadIdx.x;
    const float4 v = ((const float4*)in)[i4];
    const float o[4] = {v.x, v.y, v.z, v.w};
    uint32_t hp[2], lp[2];
    #pragma unroll
    for (int i = 0; i < 2; i++) {
        const bf16 h0 = __float2bfloat16(o[2 * i]);
        const bf16 h1 = __float2bfloat16(o[2 * i + 1]);
        const bf16 l0 = __float2bfloat16(o[2 * i] - __bfloat162float(h0));
        const bf16 l1 = __float2bfloat16(o[2 * i + 1] - __bfloat162float(h1));
        __nv_bfloat162 h2; h2.x = h0; h2.y = h1;
        __nv_bfloat162 l2; l2.x = l0; l2.y = l1;
        hp[i] = *(uint32_t*)&h2; lp[i] = *(uint32_t*)&l2;
    }
    ((uint2*)hi)[i4] = make_uint2(hp[0], hp[1]);
    ((uint2*)lo)[i4] = make_uint2(lp[0], lp[1]);
}

// W[K,N] fp32 -> T[N,K] bf16 hi/lo (tiled transpose)
__global__ __launch_bounds__(256)
void tsplit_kernel(const float* __restrict__ W, bf16* __restrict__ Thi, bf16* __restrict__ Tlo,
                   int K, int N)
{
    __shared__ float tile[32][33];
    const int kx = blockIdx.y * 32;
    const int nx = blockIdx.x * 32;
    const int tx = threadIdx.x;   // 0..31
    const int ty = threadIdx.y;   // 0..7

    #pragma unroll
    for (int j = ty; j < 32; j += 8)
        tile[j][tx] = W[(size_t)(kx + j) * N + nx + tx];
    __syncthreads();

    #pragma unroll
    for (int b = ty; b < 32; b += 8) {
        const float v = tile[tx][b];
        const bf16 h = __float2bfloat16(v);
        const bf16 l = __float2bfloat16(v - __bfloat162float(h));
        Thi[(size_t)(nx + b) * K + kx + tx] = h;
        Tlo[(size_t)(nx + b) * K + kx + tx] = l;
    }
}

// ---------------------------------------------------------------------------
// Causal flash attention (fp32)
// ---------------------------------------------------------------------------
__global__ __launch_bounds__(128)
void attn_kernel(const float* __restrict__ Q, const float* __restrict__ K,
                 const float* __restrict__ V, float* __restrict__ O)
{
    float* smem = (float*)dynsmem;
    float* Qs = smem;               // [HD][128] transposed
    float* Ks = smem + 64 * 128;    // [32][64]
    float* Vs = Ks + 32 * 64;       // [32][64]

    const int r  = threadIdx.x;
    const int qt = blockIdx.x;
    const int h  = blockIdx.y;
    const int b  = blockIdx.z;
    const int q0 = qt * 128;
    const int qg = q0 + r;
    const size_t tokq = (size_t)b * SEQ + q0 + r;

    {
        const float* qrow = Q + tokq * DMODEL + h * HD;
        #pragma unroll
        for (int k4 = 0; k4 < HD; k4 += 4) {
            const float4 qv = *(const float4*)(qrow + k4);
            Qs[(k4 + 0) * 128 + r] = qv.x;
            Qs[(k4 + 1) * 128 + r] = qv.y;
            Qs[(k4 + 2) * 128 + r] = qv.z;
            Qs[(k4 + 3) * 128 + r] = qv.w;
        }
    }

    float acc[HD];
    #pragma unroll
    for (int d = 0; d < HD; d++) acc[d] = 0.f;
    float m = -1e30f, l = 0.f;
    const float scale = 0.125f;

    const int ntiles = (q0 + 128) / 32;

    for (int kt = 0; kt < ntiles; kt++) {
        const size_t kbase = (size_t)b * SEQ + kt * 32;
        __syncthreads();
        #pragma unroll
        for (int p = 0; p < 4; p++) {
            const int f   = threadIdx.x + 128 * p;
            const int row = f >> 4;
            const int c4  = (f & 15) << 2;
            *(float4*)&Ks[row * 64 + c4] =
                *(const float4*)(K + (kbase + row) * DMODEL + h * HD + c4);
            *(float4*)&Vs[row * 64 + c4] =
                *(const float4*)(V + (kbase + row) * DMODEL + h * HD + c4);
        }
        __syncthreads();

        float s[32];
        #pragma unroll
        for (int j = 0; j < 32; j++) s[j] = 0.f;
        #pragma unroll 4
        for (int k = 0; k < HD; k++) {
            const float qk = Qs[k * 128 + r];
            #pragma unroll
            for (int j = 0; j < 32; j++)
                s[j] = fmaf(qk, Ks[j * 64 + k], s[j]);
        }

        const int kt0 = kt * 32;
        float tmax = -1e30f;
        #pragma unroll
        for (int j = 0; j < 32; j++) {
            s[j] = (kt0 + j <= qg) ? s[j] * scale : -1e30f;
            tmax = fmaxf(tmax, s[j]);
        }

        const float mnew = fmaxf(m, tmax);
        const float corr = __expf(m - mnew);
        l *= corr;
        #pragma unroll
        for (int d = 0; d < HD; d++) acc[d] *= corr;

        #pragma unroll
        for (int j = 0; j < 32; j++) {
            const float p = __expf(s[j] - mnew);
            l += p;
            #pragma unroll
            for (int d = 0; d < HD; d++)
                acc[d] = fmaf(p, Vs[j * 64 + d], acc[d]);
        }
        m = mnew;
    }

    const float inv = 1.0f / l;
    float* orow = O + tokq * DMODEL + h * HD;
    #pragma unroll
    for (int d = 0; d < HD; d += 4) {
        float4 o;
        o.x = acc[d + 0] * inv;
        o.y = acc[d + 1] * inv;
        o.z = acc[d + 2] * inv;
        o.w = acc[d + 3] * inv;
        *(float4*)(orow + d) = o;
    }
}

// ---------------------------------------------------------------------------
// Orchestration
// ---------------------------------------------------------------------------
extern "C" void kernel_launch(void* const* d_in, const int* in_sizes, int n_in,
                              void* d_out, int out_size)
{
    const float* x     = (const float*)d_in[0];
    const float* wq    = (const float*)d_in[1];
    const float* bq    = (const float*)d_in[2];
    const float* wk    = (const float*)d_in[3];
    const float* bk    = (const float*)d_in[4];
    const float* wv    = (const float*)d_in[5];
    const float* bv    = (const float*)d_in[6];
    const float* wo    = (const float*)d_in[7];
    const float* bo    = (const float*)d_in[8];
    const float* w1    = (const float*)d_in[9];
    const float* b1    = (const float*)d_in[10];
    const float* w2    = (const float*)d_in[11];
    const float* b2    = (const float*)d_in[12];
    const float* ln1_g = (const float*)d_in[13];
    const float* ln1_b = (const float*)d_in[14];
    const float* ln2_g = (const float*)d_in[15];
    const float* ln2_b = (const float*)d_in[16];
    float* out = (float*)d_out;

    float *q, *k, *v, *attn, *x1;
    bf16 *nhi, *nlo, *ahi, *alo, *hhi, *hlo;
    bf16 *wqh, *wql, *wkh, *wkl, *wvh, *wvl, *woh, *wol, *w1h, *w1l, *w2h, *w2l;
    cudaGetSymbolAddress((void**)&q,    g_q);
    cudaGetSymbolAddress((void**)&k,    g_k);
    cudaGetSymbolAddress((void**)&v,    g_v);
    cudaGetSymbolAddress((void**)&attn, g_attn);
    cudaGetSymbolAddress((void**)&x1,   g_x1);
    cudaGetSymbolAddress((void**)&nhi,  g_nhi);
    cudaGetSymbolAddress((void**)&nlo,  g_nlo);
    cudaGetSymbolAddress((void**)&ahi,  g_ahi);
    cudaGetSymbolAddress((void**)&alo,  g_alo);
    cudaGetSymbolAddress((void**)&hhi,  g_hhi);
    cudaGetSymbolAddress((void**)&hlo,  g_hlo);
    cudaGetSymbolAddress((void**)&wqh,  g_wqh);
    cudaGetSymbolAddress((void**)&wql,  g_wql);
    cudaGetSymbolAddress((void**)&wkh,  g_wkh);
    cudaGetSymbolAddress((void**)&wkl,  g_wkl);
    cudaGetSymbolAddress((void**)&wvh,  g_wvh);
    cudaGetSymbolAddress((void**)&wvl,  g_wvl);
    cudaGetSymbolAddress((void**)&woh,  g_woh);
    cudaGetSymbolAddress((void**)&wol,  g_wol);
    cudaGetSymbolAddress((void**)&w1h,  g_w1h);
    cudaGetSymbolAddress((void**)&w1l,  g_w1l);
    cudaGetSymbolAddress((void**)&w2h,  g_w2h);
    cudaGetSymbolAddress((void**)&w2l,  g_w2l);

    cudaFuncSetAttribute(attn_kernel, cudaFuncAttributeMaxDynamicSharedMemorySize, 65536);
    cudaFuncSetAttribute(tgemm_kernel<false, false, false>,
                         cudaFuncAttributeMaxDynamicSharedMemorySize, TGEMM_SMEM);
    cudaFuncSetAttribute(tgemm_kernel<false, true, false>,
                         cudaFuncAttributeMaxDynamicSharedMemorySize, TGEMM_SMEM);
    cudaFuncSetAttribute(tgemm_kernel<true, false, true>,
                         cudaFuncAttributeMaxDynamicSharedMemorySize, TGEMM_SMEM);

    // Weight transpose + split
    dim3 tb(32, 8);
    tsplit_kernel<<<dim3(32, 32),  tb>>>(wq, wqh, wql, DMODEL, DMODEL);
    tsplit_kernel<<<dim3(32, 32),  tb>>>(wk, wkh, wkl, DMODEL, DMODEL);
    tsplit_kernel<<<dim3(32, 32),  tb>>>(wv, wvh, wvl, DMODEL, DMODEL);
    tsplit_kernel<<<dim3(32, 32),  tb>>>(wo, woh, wol, DMODEL, DMODEL);
    tsplit_kernel<<<dim3(128, 32), tb>>>(w1, w1h, w1l, DMODEL, DFF);
    tsplit_kernel<<<dim3(32, 128), tb>>>(w2, w2h, w2l, DFF, DMODEL);

    // LN1 -> split
    ln_split_kernel<<<MTOK, 256>>>(x, ln1_g, ln1_b, nhi, nlo);

    // Q/K/V projections
    dim3 gP(DMODEL / 128, MTOK / 128);
    tgemm_kernel<false, false, false><<<gP, 256, TGEMM_SMEM>>>(
        nhi, nlo, wqh, wql, bq, nullptr, q, nullptr, nullptr, MTOK, DMODEL, DMODEL);
    tgemm_kernel<false, false, false><<<gP, 256, TGEMM_SMEM>>>(
        nhi, nlo, wkh, wkl, bk, nullptr, k, nullptr, nullptr, MTOK, DMODEL, DMODEL);
    tgemm_kernel<false, false, false><<<gP, 256, TGEMM_SMEM>>>(
        nhi, nlo, wvh, wvl, bv, nullptr, v, nullptr, nullptr, MTOK, DMODEL, DMODEL);

    // Causal attention (fp32)
    attn_kernel<<<dim3(SEQ / 128, NH, 4), 128, 49152>>>(q, k, v, attn);

    // Split attention output, O-projection + residual
    split_kernel<<<(MTOK * DMODEL) / 1024, 256>>>(attn, ahi, alo);
    tgemm_kernel<false, true, false><<<gP, 256, TGEMM_SMEM>>>(
        ahi, alo, woh, wol, bo, x, x1, nullptr, nullptr, MTOK, DMODEL, DMODEL);

    // LN2 -> split
    ln_split_kernel<<<MTOK, 256>>>(x1, ln2_g, ln2_b, nhi, nlo);

    // FF1 with GELU -> split bf16 out
    dim3 gF1(DFF / 128, MTOK / 128);
    tgemm_kernel<true, false, true><<<gF1, 256, TGEMM_SMEM>>>(
        nhi, nlo, w1h, w1l, b1, nullptr, nullptr, hhi, hlo, MTOK, DFF, DMODEL);

    // FF2 + residual -> final fp32 output
    dim3 gF2(DMODEL / 128, MTOK / 128);
    tgemm_kernel<false, true, false><<<gF2, 256, TGEMM_SMEM>>>(
        hhi, hlo, w2h, w2l, b2, x1, out, nullptr, nullptr, MTOK, DMODEL, DFF);
}

// round 6
// speedup vs baseline: 3.2011x; 1.5732x over previous
#include <cuda_runtime.h>
#include <cuda_bf16.h>
#include <math.h>
#include <stdint.h>

// Problem constants
#define MTOK   8192      // B*S
#define DMODEL 1024
#define DFF    4096
#define SEQ    2048
#define NH     16
#define HD     64

typedef __nv_bfloat16 bf16;

// ---------------------------------------------------------------------------
// Scratch (static device globals)
// ---------------------------------------------------------------------------
__device__ float g_x1  [(size_t)MTOK * DMODEL];

__device__ bf16 g_nhi[(size_t)MTOK * DMODEL];
__device__ bf16 g_nlo[(size_t)MTOK * DMODEL];
__device__ bf16 g_qhi[(size_t)MTOK * DMODEL];
__device__ bf16 g_qlo[(size_t)MTOK * DMODEL];
__device__ bf16 g_khi[(size_t)MTOK * DMODEL];
__device__ bf16 g_klo[(size_t)MTOK * DMODEL];
__device__ bf16 g_vhi[(size_t)MTOK * DMODEL];
__device__ bf16 g_vlo[(size_t)MTOK * DMODEL];
__device__ bf16 g_ahi[(size_t)MTOK * DMODEL];
__device__ bf16 g_alo[(size_t)MTOK * DMODEL];
__device__ bf16 g_hhi[(size_t)MTOK * DFF];
__device__ bf16 g_hlo[(size_t)MTOK * DFF];

// transposed+split weights [N,K]
__device__ bf16 g_wqh[(size_t)DMODEL * DMODEL];
__device__ bf16 g_wql[(size_t)DMODEL * DMODEL];
__device__ bf16 g_wkh[(size_t)DMODEL * DMODEL];
__device__ bf16 g_wkl[(size_t)DMODEL * DMODEL];
__device__ bf16 g_wvh[(size_t)DMODEL * DMODEL];
__device__ bf16 g_wvl[(size_t)DMODEL * DMODEL];
__device__ bf16 g_woh[(size_t)DMODEL * DMODEL];
__device__ bf16 g_wol[(size_t)DMODEL * DMODEL];
__device__ bf16 g_w1h[(size_t)DFF * DMODEL];
__device__ bf16 g_w1l[(size_t)DFF * DMODEL];
__device__ bf16 g_w2h[(size_t)DMODEL * DFF];
__device__ bf16 g_w2l[(size_t)DMODEL * DFF];

// ---------------------------------------------------------------------------
// PTX helpers (non-'a'-gated only: cp.async, ldmatrix, mma.sync)
// ---------------------------------------------------------------------------
__device__ __forceinline__ uint32_t smem_to_u32(const void* p) {
    uint32_t a;
    asm("{ .reg .u64 t; cvta.to.shared.u64 t, %1; cvt.u32.u64 %0, t; }" : "=r"(a) : "l"(p));
    return a;
}
#define CP_ASYNC_CG(dst, src) \
    asm volatile("cp.async.cg.shared.global [%0], [%1], 16;" :: "r"(dst), "l"(src) : "memory")
#define CP_ASYNC_COMMIT() asm volatile("cp.async.commit_group;" ::: "memory")
#define CP_ASYNC_WAIT(n)  asm volatile("cp.async.wait_group %0;" :: "n"(n) : "memory")

#define LDMATRIX_X4(r0, r1, r2, r3, addr) \
    asm volatile("ldmatrix.sync.aligned.m8n8.x4.shared.b16 {%0,%1,%2,%3}, [%4];" \
                 : "=r"(r0), "=r"(r1), "=r"(r2), "=r"(r3) : "r"(addr))

#define LDMATRIX_X4_TRANS(r0, r1, r2, r3, addr) \
    asm volatile("ldmatrix.sync.aligned.m8n8.x4.trans.shared.b16 {%0,%1,%2,%3}, [%4];" \
                 : "=r"(r0), "=r"(r1), "=r"(r2), "=r"(r3) : "r"(addr))

#define MMA_BF16(c, a, b) \
    asm volatile("mma.sync.aligned.m16n8k16.row.col.f32.bf16.bf16.f32 " \
                 "{%0,%1,%2,%3}, {%4,%5,%6,%7}, {%8,%9}, {%0,%1,%2,%3};" \
                 : "+f"((c)[0]), "+f"((c)[1]), "+f"((c)[2]), "+f"((c)[3]) \
                 : "r"((a)[0]), "r"((a)[1]), "r"((a)[2]), "r"((a)[3]), \
                   "r"((b)[0]), "r"((b)[1]))

__device__ __forceinline__ float gelu_exact(float x) {
    return 0.5f * x * (1.0f + erff(x * 0.70710678118654752f));
}
__device__ __forceinline__ uint32_t pack_bf2(bf16 a, bf16 b) {
    __nv_bfloat162 t; t.x = a; t.y = b;
    return *(uint32_t*)&t;
}

extern __shared__ char dynsmem[];

// ---------------------------------------------------------------------------
// bf16 mma.sync GEMM: C[M,N] = (Ahi+Alo)[M,K] @ (Bhi+Blo)[N,K]^T + bias
// (3-term split, fp32 accum). CTA 128x128, 8 warps, K-chunk 64, 3-stage cp.async.
// ---------------------------------------------------------------------------
#define BK 64
#define STAGES 3
#define STAGE_BYTES 65536
#define TGEMM_SMEM (STAGES * STAGE_BYTES)

__device__ __forceinline__ void issue_stage(
    const bf16* __restrict__ Ahi, const bf16* __restrict__ Alo,
    const bf16* __restrict__ Bhi, const bf16* __restrict__ Blo,
    int K, int k0, uint32_t stage_base, int tid)
{
    #pragma unroll
    for (int i = 0; i < 16; i++) {
        const int idx  = i * 256 + tid;
        const int tile = idx >> 10;
        const int rem  = idx & 1023;
        const int row  = rem >> 3;
        const int quad = rem & 7;
        const bf16* src;
        if      (tile == 0) src = Ahi;
        else if (tile == 1) src = Alo;
        else if (tile == 2) src = Bhi;
        else                src = Blo;
        src += (size_t)row * K + k0 + quad * 8;
        const uint32_t dst = stage_base + tile * 16384 + row * 128 +
                             ((quad ^ (row & 7)) * 16);
        CP_ASYNC_CG(dst, src);
    }
}

template <bool GELU, bool RES, bool SPLITOUT>
__global__ __launch_bounds__(256, 1)
void tgemm_kernel(const bf16* __restrict__ Ahi, const bf16* __restrict__ Alo,
                  const bf16* __restrict__ Bhi, const bf16* __restrict__ Blo,
                  const float* __restrict__ bias, const float* __restrict__ res,
                  float* __restrict__ Cf, bf16* __restrict__ Chi, bf16* __restrict__ Clo,
                  int M, int N, int K)
{
    const uint32_t sb = smem_to_u32(dynsmem);
    const int tid = threadIdx.x;
    const int wid = tid >> 5;
    const int lid = tid & 31;

    const int a0 = blockIdx.y * 128;
    const int b0 = blockIdx.x * 128;
    const int m_w = (wid & 3) * 32;
    const int n_w = (wid >> 2) * 64;

    const bf16* Ah = Ahi + (size_t)a0 * K;
    const bf16* Al = Alo + (size_t)a0 * K;
    const bf16* Bh = Bhi + (size_t)b0 * K;
    const bf16* Bl = Blo + (size_t)b0 * K;

    const int nch = K / BK;

    #pragma unroll
    for (int s = 0; s < STAGES - 1; s++) {
        issue_stage(Ah, Al, Bh, Bl, K, s * BK, sb + s * STAGE_BYTES, tid);
        CP_ASYNC_COMMIT();
    }

    float acc[2][8][4];
    #pragma unroll
    for (int i = 0; i < 2; i++)
        #pragma unroll
        for (int j = 0; j < 8; j++)
            #pragma unroll
            for (int c = 0; c < 4; c++) acc[i][j][c] = 0.f;

    const int bA  = lid >> 3;
    const int r8  = lid & 7;
    const int rowA_off = ((bA & 1) * 8) + r8;
    const int qA_off   = bA >> 1;
    const int rowB_off = ((bA >> 1) * 8) + r8;
    const int qB_off   = bA & 1;

    for (int i = 0; i < nch; i++) {
        if (i + 1 < nch) { CP_ASYNC_WAIT(1); } else { CP_ASYNC_WAIT(0); }
        __syncthreads();

        if (i + STAGES - 1 < nch)
            issue_stage(Ah, Al, Bh, Bl, K, (i + STAGES - 1) * BK,
                        sb + ((i + STAGES - 1) % STAGES) * STAGE_BYTES, tid);
        CP_ASYNC_COMMIT();

        const uint32_t st = sb + (i % STAGES) * STAGE_BYTES;
        const uint32_t sAh = st,           sAl = st + 16384;
        const uint32_t sBh = st + 32768,   sBl = st + 49152;

        #pragma unroll
        for (int ks = 0; ks < 4; ks++) {
            const int kq = ks * 2;
            uint32_t ah[2][4], al[2][4], bh[8][2], bl[8][2];

            #pragma unroll
            for (int mt = 0; mt < 2; mt++) {
                const int row  = m_w + mt * 16 + rowA_off;
                const int quad = kq + qA_off;
                const uint32_t off = row * 128 + ((quad ^ (row & 7)) * 16);
                LDMATRIX_X4(ah[mt][0], ah[mt][1], ah[mt][2], ah[mt][3], sAh + off);
                LDMATRIX_X4(al[mt][0], al[mt][1], al[mt][2], al[mt][3], sAl + off);
            }
            #pragma unroll
            for (int np = 0; np < 4; np++) {
                const int row  = n_w + np * 16 + rowB_off;
                const int quad = kq + qB_off;
                const uint32_t off = row * 128 + ((quad ^ (row & 7)) * 16);
                LDMATRIX_X4(bh[np * 2][0], bh[np * 2][1], bh[np * 2 + 1][0], bh[np * 2 + 1][1], sBh + off);
                LDMATRIX_X4(bl[np * 2][0], bl[np * 2][1], bl[np * 2 + 1][0], bl[np * 2 + 1][1], sBl + off);
            }

            #pragma unroll
            for (int mt = 0; mt < 2; mt++)
                #pragma unroll
                for (int nt = 0; nt < 8; nt++) {
                    MMA_BF16(acc[mt][nt], ah[mt], bh[nt]);
                    MMA_BF16(acc[mt][nt], al[mt], bh[nt]);
                    MMA_BF16(acc[mt][nt], ah[mt], bl[nt]);
                }
        }
    }

    const int gl  = lid >> 2;
    const int tg  = lid & 3;
    #pragma unroll
    for (int mt = 0; mt < 2; mt++) {
        #pragma unroll
        for (int half = 0; half < 2; half++) {
            const int row = a0 + m_w + mt * 16 + gl + half * 8;
            #pragma unroll
            for (int nt = 0; nt < 8; nt++) {
                const int col = b0 + n_w + nt * 8 + tg * 2;
                float v0 = acc[mt][nt][half * 2 + 0];
                float v1 = acc[mt][nt][half * 2 + 1];
                const float2 bb = *(const float2*)&bias[col];
                v0 += bb.x; v1 += bb.y;
                if (GELU) { v0 = gelu_exact(v0); v1 = gelu_exact(v1); }
                if (RES) {
                    const float2 r2 = *(const float2*)&res[(size_t)row * N + col];
                    v0 += r2.x; v1 += r2.y;
                }
                if (SPLITOUT) {
                    const bf16 h0 = __float2bfloat16(v0);
                    const bf16 h1 = __float2bfloat16(v1);
                    const bf16 l0 = __float2bfloat16(v0 - __bfloat162float(h0));
                    const bf16 l1 = __float2bfloat16(v1 - __bfloat162float(h1));
                    *(uint32_t*)&Chi[(size_t)row * N + col] = pack_bf2(h0, h1);
                    *(uint32_t*)&Clo[(size_t)row * N + col] = pack_bf2(l0, l1);
                } else {
                    float2 o; o.x = v0; o.y = v1;
                    *(float2*)&Cf[(size_t)row * N + col] = o;
                }
            }
        }
    }
}

// ---------------------------------------------------------------------------
// Tensor-core causal flash attention (split bf16, 3-term mma).
// Grid (SEQ/128, NH, B), 8 warps; warp w owns query rows [16w, 16w+16).
// smem: Qhi|Qlo (32KB) + 3 stages x {Khi,Klo,Vhi,Vlo} (32KB each) = 128KB.
// ---------------------------------------------------------------------------
#define ATT_SMEM (32768 + 3 * 32768)

__global__ __launch_bounds__(256, 1)
void fattn_kernel(const bf16* __restrict__ Qhi, const bf16* __restrict__ Qlo,
                  const bf16* __restrict__ Khi, const bf16* __restrict__ Klo,
                  const bf16* __restrict__ Vhi, const bf16* __restrict__ Vlo,
                  bf16* __restrict__ Ohi, bf16* __restrict__ Olo)
{
    const uint32_t sb = smem_to_u32(dynsmem);
    const int tid = threadIdx.x;
    const int wid = tid >> 5;
    const int lid = tid & 31;
    const int qt = blockIdx.x, h = blockIdx.y, b = blockIdx.z;
    const int q0 = qt * 128;
    const size_t base = ((size_t)b * SEQ) * DMODEL + h * HD;

    const uint32_t sQh = sb, sQl = sb + 16384;
    const int nkt = 2 * qt + 2;   // 64-key tiles

    // ldmatrix lane offsets (same conventions as GEMM)
    const int bA  = lid >> 3;
    const int r8  = lid & 7;
    const int rowA_off = ((bA & 1) * 8) + r8;
    const int qA_off   = bA >> 1;
    const int rowB_off = ((bA >> 1) * 8) + r8;
    const int qB_off   = bA & 1;
    const int gl = lid >> 2;
    const int tg = lid & 3;

    // ---- prologue: Q + stage0 in group0; stage1 in group1 ----
    #pragma unroll
    for (int i = 0; i < 8; i++) {               // Q: 2048 quads
        const int idx = i * 256 + tid;
        const int arr = idx >> 10;              // 0 hi, 1 lo
        const int rem = idx & 1023;
        const int row = rem >> 3, quad = rem & 7;
        const bf16* src = (arr ? Qlo : Qhi) + base + (size_t)(q0 + row) * DMODEL + quad * 8;
        const uint32_t dst = (arr ? sQl : sQh) + row * 128 + ((quad ^ (row & 7)) * 16);
        CP_ASYNC_CG(dst, src);
    }
    {   // stage 0 (keys 0..63)
        const uint32_t st = sb + 32768;
        #pragma unroll
        for (int i = 0; i < 8; i++) {
            const int idx = i * 256 + tid;      // 2048 quads: Kh,Kl,Vh,Vl
            const int arr = idx >> 9;
            const int rem = idx & 511;
            const int row = rem >> 3, quad = rem & 7;
            const bf16* src;
            if      (arr == 0) src = Khi;
            else if (arr == 1) src = Klo;
            else if (arr == 2) src = Vhi;
            else               src = Vlo;
            src += base + (size_t)row * DMODEL + quad * 8;
            const uint32_t dst = st + arr * 8192 + row * 128 + ((quad ^ (row & 7)) * 16);
            CP_ASYNC_CG(dst, src);
        }
    }
    CP_ASYNC_COMMIT();
    {   // stage 1 (keys 64..127)
        const uint32_t st = sb + 32768 + 32768;
        #pragma unroll
        for (int i = 0; i < 8; i++) {
            const int idx = i * 256 + tid;
            const int arr = idx >> 9;
            const int rem = idx & 511;
            const int row = rem >> 3, quad = rem & 7;
            const bf16* src;
            if      (arr == 0) src = Khi;
            else if (arr == 1) src = Klo;
            else if (arr == 2) src = Vhi;
            else               src = Vlo;
            src += base + (size_t)(64 + row) * DMODEL + quad * 8;
            const uint32_t dst = st + arr * 8192 + row * 128 + ((quad ^ (row & 7)) * 16);
            CP_ASYNC_CG(dst, src);
        }
    }
    CP_ASYNC_COMMIT();

    CP_ASYNC_WAIT(1);
    __syncthreads();

    // ---- hoist Q fragments (per warp: m16 x k64, hi+lo) ----
    uint32_t qh[4][4], ql[4][4];
    #pragma unroll
    for (int ks = 0; ks < 4; ks++) {
        const int row  = wid * 16 + rowA_off;
        const int quad = ks * 2 + qA_off;
        const uint32_t off = row * 128 + ((quad ^ (row & 7)) * 16);
        LDMATRIX_X4(qh[ks][0], qh[ks][1], qh[ks][2], qh[ks][3], sQh + off);
        LDMATRIX_X4(ql[ks][0], ql[ks][1], ql[ks][2], ql[ks][3], sQl + off);
    }

    float o[8][4];
    #pragma unroll
    for (int d = 0; d < 8; d++)
        #pragma unroll
        for (int c = 0; c < 4; c++) o[d][c] = 0.f;
    float m0 = -1e30f, m1 = -1e30f, l0 = 0.f, l1 = 0.f;

    const int rowg0 = q0 + wid * 16 + gl;   // global q row (half 0)
    const int rowg1 = rowg0 + 8;

    for (int kt = 0; kt < nkt; kt++) {
        if (kt > 0) {
            if (kt + 1 < nkt) { CP_ASYNC_WAIT(1); } else { CP_ASYNC_WAIT(0); }
            __syncthreads();
        }
        // prefetch stage kt+2
        if (kt + 2 < nkt) {
            const uint32_t st = sb + 32768 + ((kt + 2) % 3) * 32768;
            const int key0 = (kt + 2) * 64;
            #pragma unroll
            for (int i = 0; i < 8; i++) {
                const int idx = i * 256 + tid;
                const int arr = idx >> 9;
                const int rem = idx & 511;
                const int row = rem >> 3, quad = rem & 7;
                const bf16* src;
                if      (arr == 0) src = Khi;
                else if (arr == 1) src = Klo;
                else if (arr == 2) src = Vhi;
                else               src = Vlo;
                src += base + (size_t)(key0 + row) * DMODEL + quad * 8;
                const uint32_t dst = st + arr * 8192 + row * 128 + ((quad ^ (row & 7)) * 16);
                CP_ASYNC_CG(dst, src);
            }
            CP_ASYNC_COMMIT();
        }

        const uint32_t st = sb + 32768 + (kt % 3) * 32768;
        const uint32_t sKh = st, sKl = st + 8192, sVh = st + 16384, sVl = st + 24576;

        // ---- S = Q K^T (3-term split) ----
        float p[8][4];
        #pragma unroll
        for (int nt = 0; nt < 8; nt++)
            #pragma unroll
            for (int c = 0; c < 4; c++) p[nt][c] = 0.f;

        #pragma unroll
        for (int ks = 0; ks < 4; ks++) {
            const int kq = ks * 2;
            uint32_t kh[8][2], kl[8][2];
            #pragma unroll
            for (int np = 0; np < 4; np++) {
                const int row  = np * 16 + rowB_off;
                const int quad = kq + qB_off;
                const uint32_t off = row * 128 + ((quad ^ (row & 7)) * 16);
                LDMATRIX_X4(kh[np * 2][0], kh[np * 2][1], kh[np * 2 + 1][0], kh[np * 2 + 1][1], sKh + off);
                LDMATRIX_X4(kl[np * 2][0], kl[np * 2][1], kl[np * 2 + 1][0], kl[np * 2 + 1][1], sKl + off);
            }
            #pragma unroll
            for (int nt = 0; nt < 8; nt++) {
                MMA_BF16(p[nt], qh[ks], kh[nt]);
                MMA_BF16(p[nt], ql[ks], kh[nt]);
                MMA_BF16(p[nt], qh[ks], kl[nt]);
            }
        }

        // ---- scale + mask + online softmax ----
        const int kt0 = kt * 64;
        const bool msk = (kt >= nkt - 2);
        float tmax0 = -1e30f, tmax1 = -1e30f;
        #pragma unroll
        for (int nt = 0; nt < 8; nt++) {
            #pragma unroll
            for (int c = 0; c < 4; c++) {
                float v = p[nt][c] * 0.125f;
                if (msk) {
                    const int col = kt0 + nt * 8 + tg * 2 + (c & 1);
                    const int rg  = (c < 2) ? rowg0 : rowg1;
                    if (col > rg) v = -1e30f;
                }
                p[nt][c] = v;
                if (c < 2) tmax0 = fmaxf(tmax0, v); else tmax1 = fmaxf(tmax1, v);
            }
        }
        tmax0 = fmaxf(tmax0, __shfl_xor_sync(0xffffffffu, tmax0, 1));
        tmax0 = fmaxf(tmax0, __shfl_xor_sync(0xffffffffu, tmax0, 2));
        tmax1 = fmaxf(tmax1, __shfl_xor_sync(0xffffffffu, tmax1, 1));
        tmax1 = fmaxf(tmax1, __shfl_xor_sync(0xffffffffu, tmax1, 2));

        const float mn0 = fmaxf(m0, tmax0);
        const float mn1 = fmaxf(m1, tmax1);
        const float cr0 = __expf(m0 - mn0);
        const float cr1 = __expf(m1 - mn1);
        m0 = mn0; m1 = mn1;
        l0 *= cr0; l1 *= cr1;
        #pragma unroll
        for (int d = 0; d < 8; d++) {
            o[d][0] *= cr0; o[d][1] *= cr0;
            o[d][2] *= cr1; o[d][3] *= cr1;
        }
        #pragma unroll
        for (int nt = 0; nt < 8; nt++) {
            p[nt][0] = __expf(p[nt][0] - mn0);
            p[nt][1] = __expf(p[nt][1] - mn0);
            p[nt][2] = __expf(p[nt][2] - mn1);
            p[nt][3] = __expf(p[nt][3] - mn1);
            l0 += p[nt][0] + p[nt][1];
            l1 += p[nt][2] + p[nt][3];
        }

        // ---- O += P V (3-term split) ----
        #pragma unroll
        for (int s = 0; s < 4; s++) {
            // pack P fragments (A layout) for key group 16s..16s+15
            uint32_t pah[4], pal[4];
            {
                const float v00 = p[2 * s][0],     v01 = p[2 * s][1];
                const float v10 = p[2 * s][2],     v11 = p[2 * s][3];
                const float v20 = p[2 * s + 1][0], v21 = p[2 * s + 1][1];
                const float v30 = p[2 * s + 1][2], v31 = p[2 * s + 1][3];
                const bf16 h00 = __float2bfloat16(v00), h01 = __float2bfloat16(v01);
                const bf16 h10 = __float2bfloat16(v10), h11 = __float2bfloat16(v11);
                const bf16 h20 = __float2bfloat16(v20), h21 = __float2bfloat16(v21);
                const bf16 h30 = __float2bfloat16(v30), h31 = __float2bfloat16(v31);
                pah[0] = pack_bf2(h00, h01); pah[1] = pack_bf2(h10, h11);
                pah[2] = pack_bf2(h20, h21); pah[3] = pack_bf2(h30, h31);
                pal[0] = pack_bf2(__float2bfloat16(v00 - __bfloat162float(h00)),
                                  __float2bfloat16(v01 - __bfloat162float(h01)));
                pal[1] = pack_bf2(__float2bfloat16(v10 - __bfloat162float(h10)),
                                  __float2bfloat16(v11 - __bfloat162float(h11)));
                pal[2] = pack_bf2(__float2bfloat16(v20 - __bfloat162float(h20)),
                                  __float2bfloat16(v21 - __bfloat162float(h21)));
                pal[3] = pack_bf2(__float2bfloat16(v30 - __bfloat162float(h30)),
                                  __float2bfloat16(v31 - __bfloat162float(h31)));
            }
            // V fragments via ldmatrix.trans (B layout: n=d, k=key)
            uint32_t vh[8][2], vl[8][2];
            const int mi = lid >> 3;
            #pragma unroll
            for (int dp = 0; dp < 4; dp++) {
                const int row  = s * 16 + ((mi & 1) * 8) + r8;
                const int quad = dp * 2 + (mi >> 1);
                const uint32_t off = row * 128 + ((quad ^ (row & 7)) * 16);
                LDMATRIX_X4_TRANS(vh[dp * 2][0], vh[dp * 2][1], vh[dp * 2 + 1][0], vh[dp * 2 + 1][1], sVh + off);
                LDMATRIX_X4_TRANS(vl[dp * 2][0], vl[dp * 2][1], vl[dp * 2 + 1][0], vl[dp * 2 + 1][1], sVl + off);
            }
            #pragma unroll
            for (int dt = 0; dt < 8; dt++) {
                MMA_BF16(o[dt], pah, vh[dt]);
                MMA_BF16(o[dt], pal, vh[dt]);
                MMA_BF16(o[dt], pah, vl[dt]);
            }
        }
    }

    // ---- finalize: row sums, normalize, split-bf16 output ----
    l0 += __shfl_xor_sync(0xffffffffu, l0, 1);
    l0 += __shfl_xor_sync(0xffffffffu, l0, 2);
    l1 += __shfl_xor_sync(0xffffffffu, l1, 1);
    l1 += __shfl_xor_sync(0xffffffffu, l1, 2);
    const float inv0 = 1.0f / l0;
    const float inv1 = 1.0f / l1;

    const size_t tok0 = (size_t)b * SEQ + rowg0 + q0 * 0 + 0;  // rowg0 already includes q0
    const size_t tok1 = tok0 + 8;
    #pragma unroll
    for (int dt = 0; dt < 8; dt++) {
        const int col = h * HD + dt * 8 + tg * 2;
        {
            const float v0 = o[dt][0] * inv0, v1 = o[dt][1] * inv0;
            const bf16 h0 = __float2bfloat16(v0), h1 = __float2bfloat16(v1);
            *(uint32_t*)&Ohi[tok0 * DMODEL + col] = pack_bf2(h0, h1);
            *(uint32_t*)&Olo[tok0 * DMODEL + col] =
                pack_bf2(__float2bfloat16(v0 - __bfloat162float(h0)),
                         __float2bfloat16(v1 - __bfloat162float(h1)));
        }
        {
            const float v0 = o[dt][2] * inv1, v1 = o[dt][3] * inv1;
            const bf16 h0 = __float2bfloat16(v0), h1 = __float2bfloat16(v1);
            *(uint32_t*)&Ohi[tok1 * DMODEL + col] = pack_bf2(h0, h1);
            *(uint32_t*)&Olo[tok1 * DMODEL + col] =
                pack_bf2(__float2bfloat16(v0 - __bfloat162float(h0)),
                         __float2bfloat16(v1 - __bfloat162float(h1)));
        }
    }
}

// ---------------------------------------------------------------------------
// LayerNorm with split bf16 output (hi/lo)
// ---------------------------------------------------------------------------
__global__ __launch_bounds__(256)
void ln_split_kernel(const float* __restrict__ x, const float* __restrict__ g,
                     const float* __restrict__ b, bf16* __restrict__ ohi, bf16* __restrict__ olo)
{
    const int row = blockIdx.x;
    const int t   = threadIdx.x;
    const float4 v = ((const float4*)(x + (size_t)row * DMODEL))[t];

    float s  = v.x + v.y + v.z + v.w;
    float ss = v.x * v.x + v.y * v.y + v.z * v.z + v.w * v.w;
    #pragma unroll
    for (int o = 16; o > 0; o >>= 1) {
        s  += __shfl_xor_sync(0xffffffffu, s,  o);
        ss += __shfl_xor_sync(0xffffffffu, ss, o);
    }
    __shared__ float rs[8], rss[8];
    if ((t & 31) == 0) { rs[t >> 5] = s; rss[t >> 5] = ss; }
    __syncthreads();
    if (t < 32) {
        s  = (t < 8) ? rs[t]  : 0.f;
        ss = (t < 8) ? rss[t] : 0.f;
        #pragma unroll
        for (int o = 4; o > 0; o >>= 1) {
            s  += __shfl_xor_sync(0xffffffffu, s,  o);
            ss += __shfl_xor_sync(0xffffffffu, ss, o);
        }
        if (t == 0) { rs[0] = s; rss[0] = ss; }
    }
    __syncthreads();
    const float mu  = rs[0]  * (1.0f / DMODEL);
    const float var = rss[0] * (1.0f / DMODEL) - mu * mu;
    const float inv = rsqrtf(var + 1e-5f);

    const float4 gv = ((const float4*)g)[t];
    const float4 bv = ((const float4*)b)[t];
    float o[4];
    o[0] = (v.x - mu) * inv * gv.x + bv.x;
    o[1] = (v.y - mu) * inv * gv.y + bv.y;
    o[2] = (v.z - mu) * inv * gv.z + bv.z;
    o[3] = (v.w - mu) * inv * gv.w + bv.w;

    uint32_t hp[2], lp[2];
    #pragma unroll
    for (int i = 0; i < 2; i++) {
        const bf16 h0 = __float2bfloat16(o[2 * i]);
        const bf16 h1 = __float2bfloat16(o[2 * i + 1]);
        hp[i] = pack_bf2(h0, h1);
        lp[i] = pack_bf2(__float2bfloat16(o[2 * i] - __bfloat162float(h0)),
                         __float2bfloat16(o[2 * i + 1] - __bfloat162float(h1)));
    }
    ((uint2*)(ohi + (size_t)row * DMODEL))[t] = make_uint2(hp[0], hp[1]);
    ((uint2*)(olo + (size_t)row * DMODEL))[t] = make_uint2(lp[0], lp[1]);
}

// W[K,N] fp32 -> T[N,K] bf16 hi/lo (tiled transpose)
__global__ __launch_bounds__(256)
void tsplit_kernel(const float* __restrict__ W, bf16* __restrict__ Thi, bf16* __restrict__ Tlo,
                   int K, int N)
{
    __shared__ float tile[32][33];
    const int kx = blockIdx.y * 32;
    const int nx = blockIdx.x * 32;
    const int tx = threadIdx.x;
    const int ty = threadIdx.y;

    #pragma unroll
    for (int j = ty; j < 32; j += 8)
        tile[j][tx] = W[(size_t)(kx + j) * N + nx + tx];
    __syncthreads();

    #pragma unroll
    for (int b = ty; b < 32; b += 8) {
        const float v = tile[tx][b];
        const bf16 h = __float2bfloat16(v);
        const bf16 l = __float2bfloat16(v - __bfloat162float(h));
        Thi[(size_t)(nx + b) * K + kx + tx] = h;
        Tlo[(size_t)(nx + b) * K + kx + tx] = l;
    }
}

// ---------------------------------------------------------------------------
// Orchestration
// ---------------------------------------------------------------------------
extern "C" void kernel_launch(void* const* d_in, const int* in_sizes, int n_in,
                              void* d_out, int out_size)
{
    const float* x     = (const float*)d_in[0];
    const float* wq    = (const float*)d_in[1];
    const float* bq    = (const float*)d_in[2];
    const float* wk    = (const float*)d_in[3];
    const float* bk    = (const float*)d_in[4];
    const float* wv    = (const float*)d_in[5];
    const float* bv    = (const float*)d_in[6];
    const float* wo    = (const float*)d_in[7];
    const float* bo    = (const float*)d_in[8];
    const float* w1    = (const float*)d_in[9];
    const float* b1    = (const float*)d_in[10];
    const float* w2    = (const float*)d_in[11];
    const float* b2    = (const float*)d_in[12];
    const float* ln1_g = (const float*)d_in[13];
    const float* ln1_b = (const float*)d_in[14];
    const float* ln2_g = (const float*)d_in[15];
    const float* ln2_b = (const float*)d_in[16];
    float* out = (float*)d_out;

    float *x1;
    bf16 *nhi, *nlo, *qhi, *qlo, *khi, *klo, *vhi, *vlo, *ahi, *alo, *hhi, *hlo;
    bf16 *wqh, *wql, *wkh, *wkl, *wvh, *wvl, *woh, *wol, *w1h, *w1l, *w2h, *w2l;
    cudaGetSymbolAddress((void**)&x1,   g_x1);
    cudaGetSymbolAddress((void**)&nhi,  g_nhi);
    cudaGetSymbolAddress((void**)&nlo,  g_nlo);
    cudaGetSymbolAddress((void**)&qhi,  g_qhi);
    cudaGetSymbolAddress((void**)&qlo,  g_qlo);
    cudaGetSymbolAddress((void**)&khi,  g_khi);
    cudaGetSymbolAddress((void**)&klo,  g_klo);
    cudaGetSymbolAddress((void**)&vhi,  g_vhi);
    cudaGetSymbolAddress((void**)&vlo,  g_vlo);
    cudaGetSymbolAddress((void**)&ahi,  g_ahi);
    cudaGetSymbolAddress((void**)&alo,  g_alo);
    cudaGetSymbolAddress((void**)&hhi,  g_hhi);
    cudaGetSymbolAddress((void**)&hlo,  g_hlo);
    cudaGetSymbolAddress((void**)&wqh,  g_wqh);
    cudaGetSymbolAddress((void**)&wql,  g_wql);
    cudaGetSymbolAddress((void**)&wkh,  g_wkh);
    cudaGetSymbolAddress((void**)&wkl,  g_wkl);
    cudaGetSymbolAddress((void**)&wvh,  g_wvh);
    cudaGetSymbolAddress((void**)&wvl,  g_wvl);
    cudaGetSymbolAddress((void**)&woh,  g_woh);
    cudaGetSymbolAddress((void**)&wol,  g_wol);
    cudaGetSymbolAddress((void**)&w1h,  g_w1h);
    cudaGetSymbolAddress((void**)&w1l,  g_w1l);
    cudaGetSymbolAddress((void**)&w2h,  g_w2h);
    cudaGetSymbolAddress((void**)&w2l,  g_w2l);

    cudaFuncSetAttribute(fattn_kernel, cudaFuncAttributeMaxDynamicSharedMemorySize, ATT_SMEM);
    cudaFuncSetAttribute(tgemm_kernel<false, false, false>,
                         cudaFuncAttributeMaxDynamicSharedMemorySize, TGEMM_SMEM);
    cudaFuncSetAttribute(tgemm_kernel<false, false, true>,
                         cudaFuncAttributeMaxDynamicSharedMemorySize, TGEMM_SMEM);
    cudaFuncSetAttribute(tgemm_kernel<false, true, false>,
                         cudaFuncAttributeMaxDynamicSharedMemorySize, TGEMM_SMEM);
    cudaFuncSetAttribute(tgemm_kernel<true, false, true>,
                         cudaFuncAttributeMaxDynamicSharedMemorySize, TGEMM_SMEM);

    // Weight transpose + split
    dim3 tb(32, 8);
    tsplit_kernel<<<dim3(32, 32),  tb>>>(wq, wqh, wql, DMODEL, DMODEL);
    tsplit_kernel<<<dim3(32, 32),  tb>>>(wk, wkh, wkl, DMODEL, DMODEL);
    tsplit_kernel<<<dim3(32, 32),  tb>>>(wv, wvh, wvl, DMODEL, DMODEL);
    tsplit_kernel<<<dim3(32, 32),  tb>>>(wo, woh, wol, DMODEL, DMODEL);
    tsplit_kernel<<<dim3(128, 32), tb>>>(w1, w1h, w1l, DMODEL, DFF);
    tsplit_kernel<<<dim3(32, 128), tb>>>(w2, w2h, w2l, DFF, DMODEL);

    // LN1 -> split
    ln_split_kernel<<<MTOK, 256>>>(x, ln1_g, ln1_b, nhi, nlo);

    // Q/K/V projections -> split bf16 directly
    dim3 gP(DMODEL / 128, MTOK / 128);
    tgemm_kernel<false, false, true><<<gP, 256, TGEMM_SMEM>>>(
        nhi, nlo, wqh, wql, bq, nullptr, nullptr, qhi, qlo, MTOK, DMODEL, DMODEL);
    tgemm_kernel<false, false, true><<<gP, 256, TGEMM_SMEM>>>(
        nhi, nlo, wkh, wkl, bk, nullptr, nullptr, khi, klo, MTOK, DMODEL, DMODEL);
    tgemm_kernel<false, false, true><<<gP, 256, TGEMM_SMEM>>>(
        nhi, nlo, wvh, wvl, bv, nullptr, nullptr, vhi, vlo, MTOK, DMODEL, DMODEL);

    // Tensor-core causal flash attention -> split bf16
    fattn_kernel<<<dim3(SEQ / 128, NH, 4), 256, ATT_SMEM>>>(
        qhi, qlo, khi, klo, vhi, vlo, ahi, alo);

    // O-projection + residual (fp32 out)
    tgemm_kernel<false, true, false><<<gP, 256, TGEMM_SMEM>>>(
        ahi, alo, woh, wol, bo, x, x1, nullptr, nullptr, MTOK, DMODEL, DMODEL);

    // LN2 -> split
    ln_split_kernel<<<MTOK, 256>>>(x1, ln2_g, ln2_b, nhi, nlo);

    // FF1 with GELU -> split bf16 out
    dim3 gF1(DFF / 128, MTOK / 128);
    tgemm_kernel<true, false, true><<<gF1, 256, TGEMM_SMEM>>>(
        nhi, nlo, w1h, w1l, b1, nullptr, nullptr, hhi, hlo, MTOK, DFF, DMODEL);

    // FF2 + residual -> final fp32 output
    dim3 gF2(DMODEL / 128, MTOK / 128);
    tgemm_kernel<false, true, false><<<gF2, 256, TGEMM_SMEM>>>(
        hhi, hlo, w2h, w2l, b2, x1, out, nullptr, nullptr, MTOK, DMODEL, DFF);
}

// round 8
// speedup vs baseline: 3.2392x; 1.0119x over previous
#include <cuda_runtime.h>
#include <cuda_bf16.h>
#include <math.h>
#include <stdint.h>

// Problem constants
#define MTOK   8192      // B*S
#define DMODEL 1024
#define DFF    4096
#define SEQ    2048
#define NH     16
#define HD     64
#define LDQKV  3072      // packed q|k|v row stride

typedef __nv_bfloat16 bf16;

// ---------------------------------------------------------------------------
// Scratch (static device globals)
// ---------------------------------------------------------------------------
__device__ float g_x1  [(size_t)MTOK * DMODEL];

__device__ bf16 g_nhi [(size_t)MTOK * DMODEL];
__device__ bf16 g_nlo [(size_t)MTOK * DMODEL];
__device__ bf16 g_qkvh[(size_t)MTOK * LDQKV];
__device__ bf16 g_qkvl[(size_t)MTOK * LDQKV];
__device__ bf16 g_ahi [(size_t)MTOK * DMODEL];
__device__ bf16 g_alo [(size_t)MTOK * DMODEL];
__device__ bf16 g_hhi [(size_t)MTOK * DFF];
__device__ bf16 g_hlo [(size_t)MTOK * DFF];

// transposed+split weights [N,K]
__device__ bf16 g_wqkvh[(size_t)LDQKV * DMODEL];
__device__ bf16 g_wqkvl[(size_t)LDQKV * DMODEL];
__device__ bf16 g_woh[(size_t)DMODEL * DMODEL];
__device__ bf16 g_wol[(size_t)DMODEL * DMODEL];
__device__ bf16 g_w1h[(size_t)DFF * DMODEL];
__device__ bf16 g_w1l[(size_t)DFF * DMODEL];
__device__ bf16 g_w2h[(size_t)DMODEL * DFF];
__device__ bf16 g_w2l[(size_t)DMODEL * DFF];
__device__ float g_bqkv[LDQKV];

// ---------------------------------------------------------------------------
// PTX helpers (non-'a'-gated: cp.async, ldmatrix, mma.sync)
// ---------------------------------------------------------------------------
__device__ __forceinline__ uint32_t smem_to_u32(const void* p) {
    uint32_t a;
    asm("{ .reg .u64 t; cvta.to.shared.u64 t, %1; cvt.u32.u64 %0, t; }" : "=r"(a) : "l"(p));
    return a;
}
#define CP_ASYNC_CG(dst, src) \
    asm volatile("cp.async.cg.shared.global [%0], [%1], 16;" :: "r"(dst), "l"(src) : "memory")
#define CP_ASYNC_COMMIT() asm volatile("cp.async.commit_group;" ::: "memory")
#define CP_ASYNC_WAIT(n)  asm volatile("cp.async.wait_group %0;" :: "n"(n) : "memory")

#define LDMATRIX_X4(r0, r1, r2, r3, addr) \
    asm volatile("ldmatrix.sync.aligned.m8n8.x4.shared.b16 {%0,%1,%2,%3}, [%4];" \
                 : "=r"(r0), "=r"(r1), "=r"(r2), "=r"(r3) : "r"(addr))

#define LDMATRIX_X4_TRANS(r0, r1, r2, r3, addr) \
    asm volatile("ldmatrix.sync.aligned.m8n8.x4.trans.shared.b16 {%0,%1,%2,%3}, [%4];" \
                 : "=r"(r0), "=r"(r1), "=r"(r2), "=r"(r3) : "r"(addr))

#define MMA_BF16(c, a, b) \
    asm volatile("mma.sync.aligned.m16n8k16.row.col.f32.bf16.bf16.f32 " \
                 "{%0,%1,%2,%3}, {%4,%5,%6,%7}, {%8,%9}, {%0,%1,%2,%3};" \
                 : "+f"((c)[0]), "+f"((c)[1]), "+f"((c)[2]), "+f"((c)[3]) \
                 : "r"((a)[0]), "r"((a)[1]), "r"((a)[2]), "r"((a)[3]), \
                   "r"((b)[0]), "r"((b)[1]))

__device__ __forceinline__ float gelu_exact(float x) {
    return 0.5f * x * (1.0f + erff(x * 0.70710678118654752f));
}
__device__ __forceinline__ uint32_t pack_bf2(bf16 a, bf16 b) {
    __nv_bfloat162 t; t.x = a; t.y = b;
    return *(uint32_t*)&t;
}

extern __shared__ char dynsmem[];

// ---------------------------------------------------------------------------
// bf16 mma.sync GEMM: C[M,N] = (Ahi+Alo)[M,K] @ (Bhi+Blo)[N,K]^T + bias
// (3-term split, fp32 accum). CTA 128x128, 8 warps, K-chunk 64, 3-stage cp.async.
// MMAs issued TERM-MAJOR: 16 independent accumulators between dependent reuses.
// ---------------------------------------------------------------------------
#define BK 64
#define STAGES 3
#define STAGE_BYTES 65536
#define TGEMM_SMEM (STAGES * STAGE_BYTES)

__device__ __forceinline__ void issue_stage(
    const bf16* __restrict__ Ahi, const bf16* __restrict__ Alo,
    const bf16* __restrict__ Bhi, const bf16* __restrict__ Blo,
    int K, int k0, uint32_t stage_base, int tid)
{
    #pragma unroll
    for (int i = 0; i < 16; i++) {
        const int idx  = i * 256 + tid;
        const int tile = idx >> 10;
        const int rem  = idx & 1023;
        const int row  = rem >> 3;
        const int quad = rem & 7;
        const bf16* src;
        if      (tile == 0) src = Ahi;
        else if (tile == 1) src = Alo;
        else if (tile == 2) src = Bhi;
        else                src = Blo;
        src += (size_t)row * K + k0 + quad * 8;
        const uint32_t dst = stage_base + tile * 16384 + row * 128 +
                             ((quad ^ (row & 7)) * 16);
        CP_ASYNC_CG(dst, src);
    }
}

template <bool GELU, bool RES, bool SPLITOUT>
__global__ __launch_bounds__(256, 1)
void tgemm_kernel(const bf16* __restrict__ Ahi, const bf16* __restrict__ Alo,
                  const bf16* __restrict__ Bhi, const bf16* __restrict__ Blo,
                  const float* __restrict__ bias, const float* __restrict__ res,
                  float* __restrict__ Cf, bf16* __restrict__ Chi, bf16* __restrict__ Clo,
                  int M, int N, int K)
{
    const uint32_t sb = smem_to_u32(dynsmem);
    const int tid = threadIdx.x;
    const int wid = tid >> 5;
    const int lid = tid & 31;

    const int a0 = blockIdx.y * 128;
    const int b0 = blockIdx.x * 128;
    const int m_w = (wid & 3) * 32;
    const int n_w = (wid >> 2) * 64;

    const bf16* Ah = Ahi + (size_t)a0 * K;
    const bf16* Al = Alo + (size_t)a0 * K;
    const bf16* Bh = Bhi + (size_t)b0 * K;
    const bf16* Bl = Blo + (size_t)b0 * K;

    const int nch = K / BK;

    #pragma unroll
    for (int s = 0; s < STAGES - 1; s++) {
        issue_stage(Ah, Al, Bh, Bl, K, s * BK, sb + s * STAGE_BYTES, tid);
        CP_ASYNC_COMMIT();
    }

    float acc[2][8][4];
    #pragma unroll
    for (int i = 0; i < 2; i++)
        #pragma unroll
        for (int j = 0; j < 8; j++)
            #pragma unroll
            for (int c = 0; c < 4; c++) acc[i][j][c] = 0.f;

    const int bA  = lid >> 3;
    const int r8  = lid & 7;
    const int rowA_off = ((bA & 1) * 8) + r8;
    const int qA_off   = bA >> 1;
    const int rowB_off = ((bA >> 1) * 8) + r8;
    const int qB_off   = bA & 1;

    for (int i = 0; i < nch; i++) {
        if (i + 1 < nch) { CP_ASYNC_WAIT(1); } else { CP_ASYNC_WAIT(0); }
        __syncthreads();

        if (i + STAGES - 1 < nch)
            issue_stage(Ah, Al, Bh, Bl, K, (i + STAGES - 1) * BK,
                        sb + ((i + STAGES - 1) % STAGES) * STAGE_BYTES, tid);
        CP_ASYNC_COMMIT();

        const uint32_t st = sb + (i % STAGES) * STAGE_BYTES;
        const uint32_t sAh = st,           sAl = st + 16384;
        const uint32_t sBh = st + 32768,   sBl = st + 49152;

        #pragma unroll
        for (int ks = 0; ks < 4; ks++) {
            const int kq = ks * 2;
            uint32_t ah[2][4], al[2][4], bh[8][2], bl[8][2];

            #pragma unroll
            for (int mt = 0; mt < 2; mt++) {
                const int row  = m_w + mt * 16 + rowA_off;
                const int quad = kq + qA_off;
                const uint32_t off = row * 128 + ((quad ^ (row & 7)) * 16);
                LDMATRIX_X4(ah[mt][0], ah[mt][1], ah[mt][2], ah[mt][3], sAh + off);
                LDMATRIX_X4(al[mt][0], al[mt][1], al[mt][2], al[mt][3], sAl + off);
            }
            #pragma unroll
            for (int np = 0; np < 4; np++) {
                const int row  = n_w + np * 16 + rowB_off;
                const int quad = kq + qB_off;
                const uint32_t off = row * 128 + ((quad ^ (row & 7)) * 16);
                LDMATRIX_X4(bh[np * 2][0], bh[np * 2][1], bh[np * 2 + 1][0], bh[np * 2 + 1][1], sBh + off);
                LDMATRIX_X4(bl[np * 2][0], bl[np * 2][1], bl[np * 2 + 1][0], bl[np * 2 + 1][1], sBl + off);
            }

            // term-major: all 16 accumulators between dependent reuses
            #pragma unroll
            for (int mt = 0; mt < 2; mt++)
                #pragma unroll
                for (int nt = 0; nt < 8; nt++)
                    MMA_BF16(acc[mt][nt], ah[mt], bh[nt]);
            #pragma unroll
            for (int mt = 0; mt < 2; mt++)
                #pragma unroll
                for (int nt = 0; nt < 8; nt++)
                    MMA_BF16(acc[mt][nt], al[mt], bh[nt]);
            #pragma unroll
            for (int mt = 0; mt < 2; mt++)
                #pragma unroll
                for (int nt = 0; nt < 8; nt++)
                    MMA_BF16(acc[mt][nt], ah[mt], bl[nt]);
        }
    }

    const int gl  = lid >> 2;
    const int tg  = lid & 3;
    #pragma unroll
    for (int mt = 0; mt < 2; mt++) {
        #pragma unroll
        for (int half = 0; half < 2; half++) {
            const int row = a0 + m_w + mt * 16 + gl + half * 8;
            #pragma unroll
            for (int nt = 0; nt < 8; nt++) {
                const int col = b0 + n_w + nt * 8 + tg * 2;
                float v0 = acc[mt][nt][half * 2 + 0];
                float v1 = acc[mt][nt][half * 2 + 1];
                const float2 bb = *(const float2*)&bias[col];
                v0 += bb.x; v1 += bb.y;
                if (GELU) { v0 = gelu_exact(v0); v1 = gelu_exact(v1); }
                if (RES) {
                    const float2 r2 = *(const float2*)&res[(size_t)row * N + col];
                    v0 += r2.x; v1 += r2.y;
                }
                if (SPLITOUT) {
                    const bf16 h0 = __float2bfloat16(v0);
                    const bf16 h1 = __float2bfloat16(v1);
                    const bf16 l0 = __float2bfloat16(v0 - __bfloat162float(h0));
                    const bf16 l1 = __float2bfloat16(v1 - __bfloat162float(h1));
                    *(uint32_t*)&Chi[(size_t)row * N + col] = pack_bf2(h0, h1);
                    *(uint32_t*)&Clo[(size_t)row * N + col] = pack_bf2(l0, l1);
                } else {
                    float2 o; o.x = v0; o.y = v1;
                    *(float2*)&Cf[(size_t)row * N + col] = o;
                }
            }
        }
    }
}

// ---------------------------------------------------------------------------
// Tensor-core causal flash attention (split bf16, 3-term mma, term-major).
// Reads packed q|k|v (row stride LDQKV). Grid (SEQ/128, NH, B), 8 warps.
// qt reversed so heavy CTAs launch first.
// smem: Qhi|Qlo (32KB) + 3 stages x {Khi,Klo,Vhi,Vlo} (32KB each) = 128KB.
// ---------------------------------------------------------------------------
#define ATT_SMEM (32768 + 3 * 32768)

__global__ __launch_bounds__(256, 1)
void fattn_kernel(const bf16* __restrict__ QKVhi, const bf16* __restrict__ QKVlo,
                  bf16* __restrict__ Ohi, bf16* __restrict__ Olo)
{
    const uint32_t sb = smem_to_u32(dynsmem);
    const int tid = threadIdx.x;
    const int wid = tid >> 5;
    const int lid = tid & 31;
    const int qt = gridDim.x - 1 - blockIdx.x;   // heavy tiles first
    const int h = blockIdx.y, b = blockIdx.z;
    const int q0 = qt * 128;
    const size_t base = ((size_t)b * SEQ) * LDQKV + h * HD;

    const uint32_t sQh = sb, sQl = sb + 16384;
    const int nkt = 2 * qt + 2;   // 64-key tiles

    const int bA  = lid >> 3;
    const int r8  = lid & 7;
    const int rowA_off = ((bA & 1) * 8) + r8;
    const int qA_off   = bA >> 1;
    const int rowB_off = ((bA >> 1) * 8) + r8;
    const int qB_off   = bA & 1;
    const int gl = lid >> 2;
    const int tg = lid & 3;

    // ---- prologue: Q + stage0 + stage1 ----
    #pragma unroll
    for (int i = 0; i < 8; i++) {               // Q: 2048 quads
        const int idx = i * 256 + tid;
        const int arr = idx >> 10;              // 0 hi, 1 lo
        const int rem = idx & 1023;
        const int row = rem >> 3, quad = rem & 7;
        const bf16* src = (arr ? QKVlo : QKVhi) + base + (size_t)(q0 + row) * LDQKV + quad * 8;
        const uint32_t dst = (arr ? sQl : sQh) + row * 128 + ((quad ^ (row & 7)) * 16);
        CP_ASYNC_CG(dst, src);
    }
    #pragma unroll
    for (int stg = 0; stg < 2; stg++) {
        const uint32_t st = sb + 32768 + stg * 32768;
        const int key0 = stg * 64;
        #pragma unroll
        for (int i = 0; i < 8; i++) {
            const int idx = i * 256 + tid;      // 2048 quads: Kh,Kl,Vh,Vl
            const int arr = idx >> 9;
            const int rem = idx & 511;
            const int row = rem >> 3, quad = rem & 7;
            const bf16* src = ((arr & 1) ? QKVlo : QKVhi) + base +
                              ((arr >> 1) ? 2048 : 1024) +         // K at +1024, V at +2048
                              (size_t)(key0 + row) * LDQKV + quad * 8;
            // layout in stage: Kh, Kl, Vh, Vl (8KB each)
            const int slot = (arr >> 1) * 2 + (arr & 1);
            const uint32_t dst = st + slot * 8192 + row * 128 + ((quad ^ (row & 7)) * 16);
            CP_ASYNC_CG(dst, src);
        }
        CP_ASYNC_COMMIT();
    }

    CP_ASYNC_WAIT(1);
    __syncthreads();

    // ---- hoist Q fragments ----
    uint32_t qh[4][4], ql[4][4];
    #pragma unroll
    for (int ks = 0; ks < 4; ks++) {
        const int row  = wid * 16 + rowA_off;
        const int quad = ks * 2 + qA_off;
        const uint32_t off = row * 128 + ((quad ^ (row & 7)) * 16);
        LDMATRIX_X4(qh[ks][0], qh[ks][1], qh[ks][2], qh[ks][3], sQh + off);
        LDMATRIX_X4(ql[ks][0], ql[ks][1], ql[ks][2], ql[ks][3], sQl + off);
    }

    float o[8][4];
    #pragma unroll
    for (int d = 0; d < 8; d++)
        #pragma unroll
        for (int c = 0; c < 4; c++) o[d][c] = 0.f;
    float m0 = -1e30f, m1 = -1e30f, l0 = 0.f, l1 = 0.f;

    const int rowg0 = q0 + wid * 16 + gl;
    const int rowg1 = rowg0 + 8;

    for (int kt = 0; kt < nkt; kt++) {
        if (kt > 0) {
            if (kt + 1 < nkt) { CP_ASYNC_WAIT(1); } else { CP_ASYNC_WAIT(0); }
            __syncthreads();
        }
        if (kt + 2 < nkt) {
            const uint32_t st = sb + 32768 + ((kt + 2) % 3) * 32768;
            const int key0 = (kt + 2) * 64;
            #pragma unroll
            for (int i = 0; i < 8; i++) {
                const int idx = i * 256 + tid;
                const int arr = idx >> 9;
                const int rem = idx & 511;
                const int row = rem >> 3, quad = rem & 7;
                const bf16* src = ((arr & 1) ? QKVlo : QKVhi) + base +
                                  ((arr >> 1) ? 2048 : 1024) +
                                  (size_t)(key0 + row) * LDQKV + quad * 8;
                const int slot = (arr >> 1) * 2 + (arr & 1);
                const uint32_t dst = st + slot * 8192 + row * 128 + ((quad ^ (row & 7)) * 16);
                CP_ASYNC_CG(dst, src);
            }
            CP_ASYNC_COMMIT();
        }

        const uint32_t st = sb + 32768 + (kt % 3) * 32768;
        const uint32_t sKh = st, sKl = st + 8192, sVh = st + 16384, sVl = st + 24576;

        // ---- S = Q K^T (3-term, term-major) ----
        float p[8][4];
        #pragma unroll
        for (int nt = 0; nt < 8; nt++)
            #pragma unroll
            for (int c = 0; c < 4; c++) p[nt][c] = 0.f;

        #pragma unroll
        for (int ks = 0; ks < 4; ks++) {
            const int kq = ks * 2;
            uint32_t kh[8][2], kl[8][2];
            #pragma unroll
            for (int np = 0; np < 4; np++) {
                const int row  = np * 16 + rowB_off;
                const int quad = kq + qB_off;
                const uint32_t off = row * 128 + ((quad ^ (row & 7)) * 16);
                LDMATRIX_X4(kh[np * 2][0], kh[np * 2][1], kh[np * 2 + 1][0], kh[np * 2 + 1][1], sKh + off);
                LDMATRIX_X4(kl[np * 2][0], kl[np * 2][1], kl[np * 2 + 1][0], kl[np * 2 + 1][1], sKl + off);
            }
            #pragma unroll
            for (int nt = 0; nt < 8; nt++)
                MMA_BF16(p[nt], qh[ks], kh[nt]);
            #pragma unroll
            for (int nt = 0; nt < 8; nt++)
                MMA_BF16(p[nt], ql[ks], kh[nt]);
            #pragma unroll
            for (int nt = 0; nt < 8; nt++)
                MMA_BF16(p[nt], qh[ks], kl[nt]);
        }

        // ---- scale + mask + online softmax ----
        const int kt0 = kt * 64;
        const bool msk = (kt >= nkt - 2);
        float tmax0 = -1e30f, tmax1 = -1e30f;
        #pragma unroll
        for (int nt = 0; nt < 8; nt++) {
            #pragma unroll
            for (int c = 0; c < 4; c++) {
                float v = p[nt][c] * 0.125f;
                if (msk) {
                    const int col = kt0 + nt * 8 + tg * 2 + (c & 1);
                    const int rg  = (c < 2) ? rowg0 : rowg1;
                    if (col > rg) v = -1e30f;
                }
                p[nt][c] = v;
                if (c < 2) tmax0 = fmaxf(tmax0, v); else tmax1 = fmaxf(tmax1, v);
            }
        }
        tmax0 = fmaxf(tmax0, __shfl_xor_sync(0xffffffffu, tmax0, 1));
        tmax0 = fmaxf(tmax0, __shfl_xor_sync(0xffffffffu, tmax0, 2));
        tmax1 = fmaxf(tmax1, __shfl_xor_sync(0xffffffffu, tmax1, 1));
        tmax1 = fmaxf(tmax1, __shfl_xor_sync(0xffffffffu, tmax1, 2));

        const float mn0 = fmaxf(m0, tmax0);
        const float mn1 = fmaxf(m1, tmax1);
        const float cr0 = __expf(m0 - mn0);
        const float cr1 = __expf(m1 - mn1);
        m0 = mn0; m1 = mn1;
        l0 *= cr0; l1 *= cr1;
        #pragma unroll
        for (int d = 0; d < 8; d++) {
            o[d][0] *= cr0; o[d][1] *= cr0;
            o[d][2] *= cr1; o[d][3] *= cr1;
        }
        #pragma unroll
        for (int nt = 0; nt < 8; nt++) {
            p[nt][0] = __expf(p[nt][0] - mn0);
            p[nt][1] = __expf(p[nt][1] - mn0);
            p[nt][2] = __expf(p[nt][2] - mn1);
            p[nt][3] = __expf(p[nt][3] - mn1);
            l0 += p[nt][0] + p[nt][1];
            l1 += p[nt][2] + p[nt][3];
        }

        // ---- O += P V (3-term, term-major) ----
        #pragma unroll
        for (int s = 0; s < 4; s++) {
            uint32_t pah[4], pal[4];
            {
                const float v00 = p[2 * s][0],     v01 = p[2 * s][1];
                const float v10 = p[2 * s][2],     v11 = p[2 * s][3];
                const float v20 = p[2 * s + 1][0], v21 = p[2 * s + 1][1];
                const float v30 = p[2 * s + 1][2], v31 = p[2 * s + 1][3];
                const bf16 h00 = __float2bfloat16(v00), h01 = __float2bfloat16(v01);
                const bf16 h10 = __float2bfloat16(v10), h11 = __float2bfloat16(v11);
                const bf16 h20 = __float2bfloat16(v20), h21 = __float2bfloat16(v21);
                const bf16 h30 = __float2bfloat16(v30), h31 = __float2bfloat16(v31);
                pah[0] = pack_bf2(h00, h01); pah[1] = pack_bf2(h10, h11);
                pah[2] = pack_bf2(h20, h21); pah[3] = pack_bf2(h30, h31);
                pal[0] = pack_bf2(__float2bfloat16(v00 - __bfloat162float(h00)),
                                  __float2bfloat16(v01 - __bfloat162float(h01)));
                pal[1] = pack_bf2(__float2bfloat16(v10 - __bfloat162float(h10)),
                                  __float2bfloat16(v11 - __bfloat162float(h11)));
                pal[2] = pack_bf2(__float2bfloat16(v20 - __bfloat162float(h20)),
                                  __float2bfloat16(v21 - __bfloat162float(h21)));
                pal[3] = pack_bf2(__float2bfloat16(v30 - __bfloat162float(h30)),
                                  __float2bfloat16(v31 - __bfloat162float(h31)));
            }
            uint32_t vh[8][2], vl[8][2];
            const int mi = lid >> 3;
            #pragma unroll
            for (int dp = 0; dp < 4; dp++) {
                const int row  = s * 16 + ((mi & 1) * 8) + r8;
                const int quad = dp * 2 + (mi >> 1);
                const uint32_t off = row * 128 + ((quad ^ (row & 7)) * 16);
                LDMATRIX_X4_TRANS(vh[dp * 2][0], vh[dp * 2][1], vh[dp * 2 + 1][0], vh[dp * 2 + 1][1], sVh + off);
                LDMATRIX_X4_TRANS(vl[dp * 2][0], vl[dp * 2][1], vl[dp * 2 + 1][0], vl[dp * 2 + 1][1], sVl + off);
            }
            #pragma unroll
            for (int dt = 0; dt < 8; dt++)
                MMA_BF16(o[dt], pah, vh[dt]);
            #pragma unroll
            for (int dt = 0; dt < 8; dt++)
                MMA_BF16(o[dt], pal, vh[dt]);
            #pragma unroll
            for (int dt = 0; dt < 8; dt++)
                MMA_BF16(o[dt], pah, vl[dt]);
        }
    }

    // ---- finalize ----
    l0 += __shfl_xor_sync(0xffffffffu, l0, 1);
    l0 += __shfl_xor_sync(0xffffffffu, l0, 2);
    l1 += __shfl_xor_sync(0xffffffffu, l1, 1);
    l1 += __shfl_xor_sync(0xffffffffu, l1, 2);
    const float inv0 = 1.0f / l0;
    const float inv1 = 1.0f / l1;

    const size_t tok0 = (size_t)b * SEQ + rowg0;
    const size_t tok1 = tok0 + 8;
    #pragma unroll
    for (int dt = 0; dt < 8; dt++) {
        const int col = h * HD + dt * 8 + tg * 2;
        {
            const float v0 = o[dt][0] * inv0, v1 = o[dt][1] * inv0;
            const bf16 h0 = __float2bfloat16(v0), h1 = __float2bfloat16(v1);
            *(uint32_t*)&Ohi[tok0 * DMODEL + col] = pack_bf2(h0, h1);
            *(uint32_t*)&Olo[tok0 * DMODEL + col] =
                pack_bf2(__float2bfloat16(v0 - __bfloat162float(h0)),
                         __float2bfloat16(v1 - __bfloat162float(h1)));
        }
        {
            const float v0 = o[dt][2] * inv1, v1 = o[dt][3] * inv1;
            const bf16 h0 = __float2bfloat16(v0), h1 = __float2bfloat16(v1);
            *(uint32_t*)&Ohi[tok1 * DMODEL + col] = pack_bf2(h0, h1);
            *(uint32_t*)&Olo[tok1 * DMODEL + col] =
                pack_bf2(__float2bfloat16(v0 - __bfloat162float(h0)),
                         __float2bfloat16(v1 - __bfloat162float(h1)));
        }
    }
}

// ---------------------------------------------------------------------------
// LayerNorm with split bf16 output (hi/lo)
// ---------------------------------------------------------------------------
__global__ __launch_bounds__(256)
void ln_split_kernel(const float* __restrict__ x, const float* __restrict__ g,
                     const float* __restrict__ b, bf16* __restrict__ ohi, bf16* __restrict__ olo)
{
    const int row = blockIdx.x;
    const int t   = threadIdx.x;
    const float4 v = ((const float4*)(x + (size_t)row * DMODEL))[t];

    float s  = v.x + v.y + v.z + v.w;
    float ss = v.x * v.x + v.y * v.y + v.z * v.z + v.w * v.w;
    #pragma unroll
    for (int o = 16; o > 0; o >>= 1) {
        s  += __shfl_xor_sync(0xffffffffu, s,  o);
        ss += __shfl_xor_sync(0xffffffffu, ss, o);
    }
    __shared__ float rs[8], rss[8];
    if ((t & 31) == 0) { rs[t >> 5] = s; rss[t >> 5] = ss; }
    __syncthreads();
    if (t < 32) {
        s  = (t < 8) ? rs[t]  : 0.f;
        ss = (t < 8) ? rss[t] : 0.f;
        #pragma unroll
        for (int o = 4; o > 0; o >>= 1) {
            s  += __shfl_xor_sync(0xffffffffu, s,  o);
            ss += __shfl_xor_sync(0xffffffffu, ss, o);
        }
        if (t == 0) { rs[0] = s; rss[0] = ss; }
    }
    __syncthreads();
    const float mu  = rs[0]  * (1.0f / DMODEL);
    const float var = rss[0] * (1.0f / DMODEL) - mu * mu;
    const float inv = rsqrtf(var + 1e-5f);

    const float4 gv = ((const float4*)g)[t];
    const float4 bv = ((const float4*)b)[t];
    float o[4];
    o[0] = (v.x - mu) * inv * gv.x + bv.x;
    o[1] = (v.y - mu) * inv * gv.y + bv.y;
    o[2] = (v.z - mu) * inv * gv.z + bv.z;
    o[3] = (v.w - mu) * inv * gv.w + bv.w;

    uint32_t hp[2], lp[2];
    #pragma unroll
    for (int i = 0; i < 2; i++) {
        const bf16 h0 = __float2bfloat16(o[2 * i]);
        const bf16 h1 = __float2bfloat16(o[2 * i + 1]);
        hp[i] = pack_bf2(h0, h1);
        lp[i] = pack_bf2(__float2bfloat16(o[2 * i] - __bfloat162float(h0)),
                         __float2bfloat16(o[2 * i + 1] - __bfloat162float(h1)));
    }
    ((uint2*)(ohi + (size_t)row * DMODEL))[t] = make_uint2(hp[0], hp[1]);
    ((uint2*)(olo + (size_t)row * DMODEL))[t] = make_uint2(lp[0], lp[1]);
}

// W[K,N] fp32 -> T[N,K] bf16 hi/lo (tiled transpose)
__global__ __launch_bounds__(256)
void tsplit_kernel(const float* __restrict__ W, bf16* __restrict__ Thi, bf16* __restrict__ Tlo,
                   int K, int N)
{
    __shared__ float tile[32][33];
    const int kx = blockIdx.y * 32;
    const int nx = blockIdx.x * 32;
    const int tx = threadIdx.x;
    const int ty = threadIdx.y;

    #pragma unroll
    for (int j = ty; j < 32; j += 8)
        tile[j][tx] = W[(size_t)(kx + j) * N + nx + tx];
    __syncthreads();

    #pragma unroll
    for (int b = ty; b < 32; b += 8) {
        const float v = tile[tx][b];
        const bf16 h = __float2bfloat16(v);
        const bf16 l = __float2bfloat16(v - __bfloat162float(h));
        Thi[(size_t)(nx + b) * K + kx + tx] = h;
        Tlo[(size_t)(nx + b) * K + kx + tx] = l;
    }
}

// ---------------------------------------------------------------------------
// Orchestration
// ---------------------------------------------------------------------------
extern "C" void kernel_launch(void* const* d_in, const int* in_sizes, int n_in,
                              void* d_out, int out_size)
{
    const float* x     = (const float*)d_in[0];
    const float* wq    = (const float*)d_in[1];
    const float* bq    = (const float*)d_in[2];
    const float* wk    = (const float*)d_in[3];
    const float* bk    = (const float*)d_in[4];
    const float* wv    = (const float*)d_in[5];
    const float* bv    = (const float*)d_in[6];
    const float* wo    = (const float*)d_in[7];
    const float* bo    = (const float*)d_in[8];
    const float* w1    = (const float*)d_in[9];
    const float* b1    = (const float*)d_in[10];
    const float* w2    = (const float*)d_in[11];
    const float* b2    = (const float*)d_in[12];
    const float* ln1_g = (const float*)d_in[13];
    const float* ln1_b = (const float*)d_in[14];
    const float* ln2_g = (const float*)d_in[15];
    const float* ln2_b = (const float*)d_in[16];
    float* out = (float*)d_out;

    float *x1, *bqkv;
    bf16 *nhi, *nlo, *qkvh, *qkvl, *ahi, *alo, *hhi, *hlo;
    bf16 *wqkvh, *wqkvl, *woh, *wol, *w1h, *w1l, *w2h, *w2l;
    cudaGetSymbolAddress((void**)&x1,    g_x1);
    cudaGetSymbolAddress((void**)&bqkv,  g_bqkv);
    cudaGetSymbolAddress((void**)&nhi,   g_nhi);
    cudaGetSymbolAddress((void**)&nlo,   g_nlo);
    cudaGetSymbolAddress((void**)&qkvh,  g_qkvh);
    cudaGetSymbolAddress((void**)&qkvl,  g_qkvl);
    cudaGetSymbolAddress((void**)&ahi,   g_ahi);
    cudaGetSymbolAddress((void**)&alo,   g_alo);
    cudaGetSymbolAddress((void**)&hhi,   g_hhi);
    cudaGetSymbolAddress((void**)&hlo,   g_hlo);
    cudaGetSymbolAddress((void**)&wqkvh, g_wqkvh);
    cudaGetSymbolAddress((void**)&wqkvl, g_wqkvl);
    cudaGetSymbolAddress((void**)&woh,   g_woh);
    cudaGetSymbolAddress((void**)&wol,   g_wol);
    cudaGetSymbolAddress((void**)&w1h,   g_w1h);
    cudaGetSymbolAddress((void**)&w1l,   g_w1l);
    cudaGetSymbolAddress((void**)&w2h,   g_w2h);
    cudaGetSymbolAddress((void**)&w2l,   g_w2l);

    cudaFuncSetAttribute(fattn_kernel, cudaFuncAttributeMaxDynamicSharedMemorySize, ATT_SMEM);
    cudaFuncSetAttribute(tgemm_kernel<false, false, false>,
                         cudaFuncAttributeMaxDynamicSharedMemorySize, TGEMM_SMEM);
    cudaFuncSetAttribute(tgemm_kernel<false, false, true>,
                         cudaFuncAttributeMaxDynamicSharedMemorySize, TGEMM_SMEM);
    cudaFuncSetAttribute(tgemm_kernel<false, true, false>,
                         cudaFuncAttributeMaxDynamicSharedMemorySize, TGEMM_SMEM);
    cudaFuncSetAttribute(tgemm_kernel<true, false, true>,
                         cudaFuncAttributeMaxDynamicSharedMemorySize, TGEMM_SMEM);

    // Concat QKV biases (async D2D, graph-capturable)
    cudaMemcpyAsync(bqkv,        bq, DMODEL * sizeof(float), cudaMemcpyDeviceToDevice);
    cudaMemcpyAsync(bqkv + 1024, bk, DMODEL * sizeof(float), cudaMemcpyDeviceToDevice);
    cudaMemcpyAsync(bqkv + 2048, bv, DMODEL * sizeof(float), cudaMemcpyDeviceToDevice);

    // Weight transpose + split (QKV packed into one [3072,1024] buffer)
    dim3 tb(32, 8);
    tsplit_kernel<<<dim3(32, 32),  tb>>>(wq, wqkvh,                  wqkvl,                  DMODEL, DMODEL);
    tsplit_kernel<<<dim3(32, 32),  tb>>>(wk, wqkvh + 1024 * DMODEL,  wqkvl + 1024 * DMODEL,  DMODEL, DMODEL);
    tsplit_kernel<<<dim3(32, 32),  tb>>>(wv, wqkvh + 2048 * DMODEL,  wqkvl + 2048 * DMODEL,  DMODEL, DMODEL);
    tsplit_kernel<<<dim3(32, 32),  tb>>>(wo, woh, wol, DMODEL, DMODEL);
    tsplit_kernel<<<dim3(128, 32), tb>>>(w1, w1h, w1l, DMODEL, DFF);
    tsplit_kernel<<<dim3(32, 128), tb>>>(w2, w2h, w2l, DFF, DMODEL);

    // LN1 -> split
    ln_split_kernel<<<MTOK, 256>>>(x, ln1_g, ln1_b, nhi, nlo);

    // Fused QKV projection -> packed split bf16 [MTOK, 3072]
    dim3 gQKV(LDQKV / 128, MTOK / 128);
    tgemm_kernel<false, false, true><<<gQKV, 256, TGEMM_SMEM>>>(
        nhi, nlo, wqkvh, wqkvl, bqkv, nullptr, nullptr, qkvh, qkvl, MTOK, LDQKV, DMODEL);

    // Tensor-core causal flash attention -> split bf16
    fattn_kernel<<<dim3(SEQ / 128, NH, 4), 256, ATT_SMEM>>>(qkvh, qkvl, ahi, alo);

    // O-projection + residual (fp32 out)
    dim3 gP(DMODEL / 128, MTOK / 128);
    tgemm_kernel<false, true, false><<<gP, 256, TGEMM_SMEM>>>(
        ahi, alo, woh, wol, bo, x, x1, nullptr, nullptr, MTOK, DMODEL, DMODEL);

    // LN2 -> split
    ln_split_kernel<<<MTOK, 256>>>(x1, ln2_g, ln2_b, nhi, nlo);

    // FF1 with GELU -> split bf16 out
    dim3 gF1(DFF / 128, MTOK / 128);
    tgemm_kernel<true, false, true><<<gF1, 256, TGEMM_SMEM>>>(
        nhi, nlo, w1h, w1l, b1, nullptr, nullptr, hhi, hlo, MTOK, DFF, DMODEL);

    // FF2 + residual -> final fp32 output
    dim3 gF2(DMODEL / 128, MTOK / 128);
    tgemm_kernel<false, true, false><<<gF2, 256, TGEMM_SMEM>>>(
        hhi, hlo, w2h, w2l, b2, x1, out, nullptr, nullptr, MTOK, DMODEL, DFF);
}

// round 9
// speedup vs baseline: 3.2692x; 1.0093x over previous
#include <cuda_runtime.h>
#include <cuda_bf16.h>
#include <math.h>
#include <stdint.h>

// Problem constants
#define MTOK   8192      // B*S
#define DMODEL 1024
#define DFF    4096
#define SEQ    2048
#define NH     16
#define HD     64
#define LDQKV  3072      // packed q|k|v row stride

typedef __nv_bfloat16 bf16;

// ---------------------------------------------------------------------------
// Scratch (static device globals)
// ---------------------------------------------------------------------------
__device__ float g_x1  [(size_t)MTOK * DMODEL];

__device__ bf16 g_nhi [(size_t)MTOK * DMODEL];
__device__ bf16 g_nlo [(size_t)MTOK * DMODEL];
__device__ bf16 g_qkvh[(size_t)MTOK * LDQKV];
__device__ bf16 g_qkvl[(size_t)MTOK * LDQKV];
__device__ bf16 g_ahi [(size_t)MTOK * DMODEL];
__device__ bf16 g_alo [(size_t)MTOK * DMODEL];
__device__ bf16 g_hhi [(size_t)MTOK * DFF];
__device__ bf16 g_hlo [(size_t)MTOK * DFF];

// transposed+split weights [N,K]
__device__ bf16 g_wqkvh[(size_t)LDQKV * DMODEL];
__device__ bf16 g_wqkvl[(size_t)LDQKV * DMODEL];
__device__ bf16 g_woh[(size_t)DMODEL * DMODEL];
__device__ bf16 g_wol[(size_t)DMODEL * DMODEL];
__device__ bf16 g_w1h[(size_t)DFF * DMODEL];
__device__ bf16 g_w1l[(size_t)DFF * DMODEL];
__device__ bf16 g_w2h[(size_t)DMODEL * DFF];
__device__ bf16 g_w2l[(size_t)DMODEL * DFF];
__device__ float g_bqkv[LDQKV];

// ---------------------------------------------------------------------------
// PTX helpers (non-'a'-gated: cp.async, ldmatrix, mma.sync)
// ---------------------------------------------------------------------------
__device__ __forceinline__ uint32_t smem_to_u32(const void* p) {
    uint32_t a;
    asm("{ .reg .u64 t; cvta.to.shared.u64 t, %1; cvt.u32.u64 %0, t; }" : "=r"(a) : "l"(p));
    return a;
}
#define CP_ASYNC_CG(dst, src) \
    asm volatile("cp.async.cg.shared.global [%0], [%1], 16;" :: "r"(dst), "l"(src) : "memory")
#define CP_ASYNC_COMMIT() asm volatile("cp.async.commit_group;" ::: "memory")
#define CP_ASYNC_WAIT(n)  asm volatile("cp.async.wait_group %0;" :: "n"(n) : "memory")

#define LDMATRIX_X4(r0, r1, r2, r3, addr) \
    asm volatile("ldmatrix.sync.aligned.m8n8.x4.shared.b16 {%0,%1,%2,%3}, [%4];" \
                 : "=r"(r0), "=r"(r1), "=r"(r2), "=r"(r3) : "r"(addr))

#define LDMATRIX_X4_TRANS(r0, r1, r2, r3, addr) \
    asm volatile("ldmatrix.sync.aligned.m8n8.x4.trans.shared.b16 {%0,%1,%2,%3}, [%4];" \
                 : "=r"(r0), "=r"(r1), "=r"(r2), "=r"(r3) : "r"(addr))

#define MMA_BF16(c, a, b) \
    asm volatile("mma.sync.aligned.m16n8k16.row.col.f32.bf16.bf16.f32 " \
                 "{%0,%1,%2,%3}, {%4,%5,%6,%7}, {%8,%9}, {%0,%1,%2,%3};" \
                 : "+f"((c)[0]), "+f"((c)[1]), "+f"((c)[2]), "+f"((c)[3]) \
                 : "r"((a)[0]), "r"((a)[1]), "r"((a)[2]), "r"((a)[3]), \
                   "r"((b)[0]), "r"((b)[1]))

__device__ __forceinline__ float gelu_exact(float x) {
    return 0.5f * x * (1.0f + erff(x * 0.70710678118654752f));
}
__device__ __forceinline__ uint32_t pack_bf2(bf16 a, bf16 b) {
    __nv_bfloat162 t; t.x = a; t.y = b;
    return *(uint32_t*)&t;
}

extern __shared__ char dynsmem[];

// ---------------------------------------------------------------------------
// bf16 mma.sync GEMM: C[M,N] = (Ahi+Alo)[M,K] @ (Bhi+Blo)[N,K]^T + bias
// (3-term split, fp32 accum). CTA 128x128, 8 warps, K-chunk 64, 3-stage cp.async.
// ---------------------------------------------------------------------------
#define BK 64
#define STAGES 3
#define STAGE_BYTES 65536
#define TGEMM_SMEM (STAGES * STAGE_BYTES)

__device__ __forceinline__ void issue_stage(
    const bf16* __restrict__ Ahi, const bf16* __restrict__ Alo,
    const bf16* __restrict__ Bhi, const bf16* __restrict__ Blo,
    int K, int k0, uint32_t stage_base, int tid)
{
    #pragma unroll
    for (int i = 0; i < 16; i++) {
        const int idx  = i * 256 + tid;
        const int tile = idx >> 10;
        const int rem  = idx & 1023;
        const int row  = rem >> 3;
        const int quad = rem & 7;
        const bf16* src;
        if      (tile == 0) src = Ahi;
        else if (tile == 1) src = Alo;
        else if (tile == 2) src = Bhi;
        else                src = Blo;
        src += (size_t)row * K + k0 + quad * 8;
        const uint32_t dst = stage_base + tile * 16384 + row * 128 +
                             ((quad ^ (row & 7)) * 16);
        CP_ASYNC_CG(dst, src);
    }
}

template <bool GELU, bool RES, bool SPLITOUT>
__global__ __launch_bounds__(256, 1)
void tgemm_kernel(const bf16* __restrict__ Ahi, const bf16* __restrict__ Alo,
                  const bf16* __restrict__ Bhi, const bf16* __restrict__ Blo,
                  const float* __restrict__ bias, const float* __restrict__ res,
                  float* __restrict__ Cf, bf16* __restrict__ Chi, bf16* __restrict__ Clo,
                  int M, int N, int K)
{
    const uint32_t sb = smem_to_u32(dynsmem);
    const int tid = threadIdx.x;
    const int wid = tid >> 5;
    const int lid = tid & 31;

    const int a0 = blockIdx.y * 128;
    const int b0 = blockIdx.x * 128;
    const int m_w = (wid & 3) * 32;
    const int n_w = (wid >> 2) * 64;

    const bf16* Ah = Ahi + (size_t)a0 * K;
    const bf16* Al = Alo + (size_t)a0 * K;
    const bf16* Bh = Bhi + (size_t)b0 * K;
    const bf16* Bl = Blo + (size_t)b0 * K;

    const int nch = K / BK;

    #pragma unroll
    for (int s = 0; s < STAGES - 1; s++) {
        issue_stage(Ah, Al, Bh, Bl, K, s * BK, sb + s * STAGE_BYTES, tid);
        CP_ASYNC_COMMIT();
    }

    float acc[2][8][4];
    #pragma unroll
    for (int i = 0; i < 2; i++)
        #pragma unroll
        for (int j = 0; j < 8; j++)
            #pragma unroll
            for (int c = 0; c < 4; c++) acc[i][j][c] = 0.f;

    const int bA  = lid >> 3;
    const int r8  = lid & 7;
    const int rowA_off = ((bA & 1) * 8) + r8;
    const int qA_off   = bA >> 1;
    const int rowB_off = ((bA >> 1) * 8) + r8;
    const int qB_off   = bA & 1;

    for (int i = 0; i < nch; i++) {
        if (i + 1 < nch) { CP_ASYNC_WAIT(1); } else { CP_ASYNC_WAIT(0); }
        __syncthreads();

        if (i + STAGES - 1 < nch)
            issue_stage(Ah, Al, Bh, Bl, K, (i + STAGES - 1) * BK,
                        sb + ((i + STAGES - 1) % STAGES) * STAGE_BYTES, tid);
        CP_ASYNC_COMMIT();

        const uint32_t st = sb + (i % STAGES) * STAGE_BYTES;
        const uint32_t sAh = st,           sAl = st + 16384;
        const uint32_t sBh = st + 32768,   sBl = st + 49152;

        #pragma unroll
        for (int ks = 0; ks < 4; ks++) {
            const int kq = ks * 2;
            uint32_t ah[2][4], al[2][4], bh[8][2], bl[8][2];

            #pragma unroll
            for (int mt = 0; mt < 2; mt++) {
                const int row  = m_w + mt * 16 + rowA_off;
                const int quad = kq + qA_off;
                const uint32_t off = row * 128 + ((quad ^ (row & 7)) * 16);
                LDMATRIX_X4(ah[mt][0], ah[mt][1], ah[mt][2], ah[mt][3], sAh + off);
                LDMATRIX_X4(al[mt][0], al[mt][1], al[mt][2], al[mt][3], sAl + off);
            }
            #pragma unroll
            for (int np = 0; np < 4; np++) {
                const int row  = n_w + np * 16 + rowB_off;
                const int quad = kq + qB_off;
                const uint32_t off = row * 128 + ((quad ^ (row & 7)) * 16);
                LDMATRIX_X4(bh[np * 2][0], bh[np * 2][1], bh[np * 2 + 1][0], bh[np * 2 + 1][1], sBh + off);
                LDMATRIX_X4(bl[np * 2][0], bl[np * 2][1], bl[np * 2 + 1][0], bl[np * 2 + 1][1], sBl + off);
            }

            #pragma unroll
            for (int mt = 0; mt < 2; mt++)
                #pragma unroll
                for (int nt = 0; nt < 8; nt++)
                    MMA_BF16(acc[mt][nt], ah[mt], bh[nt]);
            #pragma unroll
            for (int mt = 0; mt < 2; mt++)
                #pragma unroll
                for (int nt = 0; nt < 8; nt++)
                    MMA_BF16(acc[mt][nt], al[mt], bh[nt]);
            #pragma unroll
            for (int mt = 0; mt < 2; mt++)
                #pragma unroll
                for (int nt = 0; nt < 8; nt++)
                    MMA_BF16(acc[mt][nt], ah[mt], bl[nt]);
        }
    }

    const int gl  = lid >> 2;
    const int tg  = lid & 3;
    #pragma unroll
    for (int mt = 0; mt < 2; mt++) {
        #pragma unroll
        for (int half = 0; half < 2; half++) {
            const int row = a0 + m_w + mt * 16 + gl + half * 8;
            #pragma unroll
            for (int nt = 0; nt < 8; nt++) {
                const int col = b0 + n_w + nt * 8 + tg * 2;
                float v0 = acc[mt][nt][half * 2 + 0];
                float v1 = acc[mt][nt][half * 2 + 1];
                const float2 bb = *(const float2*)&bias[col];
                v0 += bb.x; v1 += bb.y;
                if (GELU) { v0 = gelu_exact(v0); v1 = gelu_exact(v1); }
                if (RES) {
                    const float2 r2 = *(const float2*)&res[(size_t)row * N + col];
                    v0 += r2.x; v1 += r2.y;
                }
                if (SPLITOUT) {
                    const bf16 h0 = __float2bfloat16(v0);
                    const bf16 h1 = __float2bfloat16(v1);
                    const bf16 l0 = __float2bfloat16(v0 - __bfloat162float(h0));
                    const bf16 l1 = __float2bfloat16(v1 - __bfloat162float(h1));
                    *(uint32_t*)&Chi[(size_t)row * N + col] = pack_bf2(h0, h1);
                    *(uint32_t*)&Clo[(size_t)row * N + col] = pack_bf2(l0, l1);
                } else {
                    float2 o; o.x = v0; o.y = v1;
                    *(float2*)&Cf[(size_t)row * N + col] = o;
                }
            }
        }
    }
}

// ---------------------------------------------------------------------------
// Tensor-core causal flash attention (split bf16, 3-term mma).
// ---------------------------------------------------------------------------
#define ATT_SMEM (32768 + 3 * 32768)

__global__ __launch_bounds__(256, 1)
void fattn_kernel(const bf16* __restrict__ QKVhi, const bf16* __restrict__ QKVlo,
                  bf16* __restrict__ Ohi, bf16* __restrict__ Olo)
{
    const uint32_t sb = smem_to_u32(dynsmem);
    const int tid = threadIdx.x;
    const int wid = tid >> 5;
    const int lid = tid & 31;
    const int qt = gridDim.x - 1 - blockIdx.x;   // heavy tiles first
    const int h = blockIdx.y, b = blockIdx.z;
    const int q0 = qt * 128;
    const size_t base = ((size_t)b * SEQ) * LDQKV + h * HD;

    const uint32_t sQh = sb, sQl = sb + 16384;
    const int nkt = 2 * qt + 2;

    const int bA  = lid >> 3;
    const int r8  = lid & 7;
    const int rowA_off = ((bA & 1) * 8) + r8;
    const int qA_off   = bA >> 1;
    const int rowB_off = ((bA >> 1) * 8) + r8;
    const int qB_off   = bA & 1;
    const int gl = lid >> 2;
    const int tg = lid & 3;

    #pragma unroll
    for (int i = 0; i < 8; i++) {
        const int idx = i * 256 + tid;
        const int arr = idx >> 10;
        const int rem = idx & 1023;
        const int row = rem >> 3, quad = rem & 7;
        const bf16* src = (arr ? QKVlo : QKVhi) + base + (size_t)(q0 + row) * LDQKV + quad * 8;
        const uint32_t dst = (arr ? sQl : sQh) + row * 128 + ((quad ^ (row & 7)) * 16);
        CP_ASYNC_CG(dst, src);
    }
    #pragma unroll
    for (int stg = 0; stg < 2; stg++) {
        const uint32_t st = sb + 32768 + stg * 32768;
        const int key0 = stg * 64;
        #pragma unroll
        for (int i = 0; i < 8; i++) {
            const int idx = i * 256 + tid;
            const int arr = idx >> 9;
            const int rem = idx & 511;
            const int row = rem >> 3, quad = rem & 7;
            const bf16* src = ((arr & 1) ? QKVlo : QKVhi) + base +
                              ((arr >> 1) ? 2048 : 1024) +
                              (size_t)(key0 + row) * LDQKV + quad * 8;
            const int slot = (arr >> 1) * 2 + (arr & 1);
            const uint32_t dst = st + slot * 8192 + row * 128 + ((quad ^ (row & 7)) * 16);
            CP_ASYNC_CG(dst, src);
        }
        CP_ASYNC_COMMIT();
    }

    CP_ASYNC_WAIT(1);
    __syncthreads();

    uint32_t qh[4][4], ql[4][4];
    #pragma unroll
    for (int ks = 0; ks < 4; ks++) {
        const int row  = wid * 16 + rowA_off;
        const int quad = ks * 2 + qA_off;
        const uint32_t off = row * 128 + ((quad ^ (row & 7)) * 16);
        LDMATRIX_X4(qh[ks][0], qh[ks][1], qh[ks][2], qh[ks][3], sQh + off);
        LDMATRIX_X4(ql[ks][0], ql[ks][1], ql[ks][2], ql[ks][3], sQl + off);
    }

    float o[8][4];
    #pragma unroll
    for (int d = 0; d < 8; d++)
        #pragma unroll
        for (int c = 0; c < 4; c++) o[d][c] = 0.f;
    float m0 = -1e30f, m1 = -1e30f, l0 = 0.f, l1 = 0.f;

    const int rowg0 = q0 + wid * 16 + gl;
    const int rowg1 = rowg0 + 8;

    for (int kt = 0; kt < nkt; kt++) {
        if (kt > 0) {
            if (kt + 1 < nkt) { CP_ASYNC_WAIT(1); } else { CP_ASYNC_WAIT(0); }
            __syncthreads();
        }
        if (kt + 2 < nkt) {
            const uint32_t st = sb + 32768 + ((kt + 2) % 3) * 32768;
            const int key0 = (kt + 2) * 64;
            #pragma unroll
            for (int i = 0; i < 8; i++) {
                const int idx = i * 256 + tid;
                const int arr = idx >> 9;
                const int rem = idx & 511;
                const int row = rem >> 3, quad = rem & 7;
                const bf16* src = ((arr & 1) ? QKVlo : QKVhi) + base +
                                  ((arr >> 1) ? 2048 : 1024) +
                                  (size_t)(key0 + row) * LDQKV + quad * 8;
                const int slot = (arr >> 1) * 2 + (arr & 1);
                const uint32_t dst = st + slot * 8192 + row * 128 + ((quad ^ (row & 7)) * 16);
                CP_ASYNC_CG(dst, src);
            }
            CP_ASYNC_COMMIT();
        }

        const uint32_t st = sb + 32768 + (kt % 3) * 32768;
        const uint32_t sKh = st, sKl = st + 8192, sVh = st + 16384, sVl = st + 24576;

        float p[8][4];
        #pragma unroll
        for (int nt = 0; nt < 8; nt++)
            #pragma unroll
            for (int c = 0; c < 4; c++) p[nt][c] = 0.f;

        #pragma unroll
        for (int ks = 0; ks < 4; ks++) {
            const int kq = ks * 2;
            uint32_t kh[8][2], kl[8][2];
            #pragma unroll
            for (int np = 0; np < 4; np++) {
                const int row  = np * 16 + rowB_off;
                const int quad = kq + qB_off;
                const uint32_t off = row * 128 + ((quad ^ (row & 7)) * 16);
                LDMATRIX_X4(kh[np * 2][0], kh[np * 2][1], kh[np * 2 + 1][0], kh[np * 2 + 1][1], sKh + off);
                LDMATRIX_X4(kl[np * 2][0], kl[np * 2][1], kl[np * 2 + 1][0], kl[np * 2 + 1][1], sKl + off);
            }
            #pragma unroll
            for (int nt = 0; nt < 8; nt++)
                MMA_BF16(p[nt], qh[ks], kh[nt]);
            #pragma unroll
            for (int nt = 0; nt < 8; nt++)
                MMA_BF16(p[nt], ql[ks], kh[nt]);
            #pragma unroll
            for (int nt = 0; nt < 8; nt++)
                MMA_BF16(p[nt], qh[ks], kl[nt]);
        }

        const int kt0 = kt * 64;
        const bool msk = (kt >= nkt - 2);
        float tmax0 = -1e30f, tmax1 = -1e30f;
        #pragma unroll
        for (int nt = 0; nt < 8; nt++) {
            #pragma unroll
            for (int c = 0; c < 4; c++) {
                float v = p[nt][c] * 0.125f;
                if (msk) {
                    const int col = kt0 + nt * 8 + tg * 2 + (c & 1);
                    const int rg  = (c < 2) ? rowg0 : rowg1;
                    if (col > rg) v = -1e30f;
                }
                p[nt][c] = v;
                if (c < 2) tmax0 = fmaxf(tmax0, v); else tmax1 = fmaxf(tmax1, v);
            }
        }
        tmax0 = fmaxf(tmax0, __shfl_xor_sync(0xffffffffu, tmax0, 1));
        tmax0 = fmaxf(tmax0, __shfl_xor_sync(0xffffffffu, tmax0, 2));
        tmax1 = fmaxf(tmax1, __shfl_xor_sync(0xffffffffu, tmax1, 1));
        tmax1 = fmaxf(tmax1, __shfl_xor_sync(0xffffffffu, tmax1, 2));

        const float mn0 = fmaxf(m0, tmax0);
        const float mn1 = fmaxf(m1, tmax1);
        const float cr0 = __expf(m0 - mn0);
        const float cr1 = __expf(m1 - mn1);
        m0 = mn0; m1 = mn1;
        l0 *= cr0; l1 *= cr1;
        #pragma unroll
        for (int d = 0; d < 8; d++) {
            o[d][0] *= cr0; o[d][1] *= cr0;
            o[d][2] *= cr1; o[d][3] *= cr1;
        }
        #pragma unroll
        for (int nt = 0; nt < 8; nt++) {
            p[nt][0] = __expf(p[nt][0] - mn0);
            p[nt][1] = __expf(p[nt][1] - mn0);
            p[nt][2] = __expf(p[nt][2] - mn1);
            p[nt][3] = __expf(p[nt][3] - mn1);
            l0 += p[nt][0] + p[nt][1];
            l1 += p[nt][2] + p[nt][3];
        }

        #pragma unroll
        for (int s = 0; s < 4; s++) {
            uint32_t pah[4], pal[4];
            {
                const float v00 = p[2 * s][0],     v01 = p[2 * s][1];
                const float v10 = p[2 * s][2],     v11 = p[2 * s][3];
                const float v20 = p[2 * s + 1][0], v21 = p[2 * s + 1][1];
                const float v30 = p[2 * s + 1][2], v31 = p[2 * s + 1][3];
                const bf16 h00 = __float2bfloat16(v00), h01 = __float2bfloat16(v01);
                const bf16 h10 = __float2bfloat16(v10), h11 = __float2bfloat16(v11);
                const bf16 h20 = __float2bfloat16(v20), h21 = __float2bfloat16(v21);
                const bf16 h30 = __float2bfloat16(v30), h31 = __float2bfloat16(v31);
                pah[0] = pack_bf2(h00, h01); pah[1] = pack_bf2(h10, h11);
                pah[2] = pack_bf2(h20, h21); pah[3] = pack_bf2(h30, h31);
                pal[0] = pack_bf2(__float2bfloat16(v00 - __bfloat162float(h00)),
                                  __float2bfloat16(v01 - __bfloat162float(h01)));
                pal[1] = pack_bf2(__float2bfloat16(v10 - __bfloat162float(h10)),
                                  __float2bfloat16(v11 - __bfloat162float(h11)));
                pal[2] = pack_bf2(__float2bfloat16(v20 - __bfloat162float(h20)),
                                  __float2bfloat16(v21 - __bfloat162float(h21)));
                pal[3] = pack_bf2(__float2bfloat16(v30 - __bfloat162float(h30)),
                                  __float2bfloat16(v31 - __bfloat162float(h31)));
            }
            uint32_t vh[8][2], vl[8][2];
            const int mi = lid >> 3;
            #pragma unroll
            for (int dp = 0; dp < 4; dp++) {
                const int row  = s * 16 + ((mi & 1) * 8) + r8;
                const int quad = dp * 2 + (mi >> 1);
                const uint32_t off = row * 128 + ((quad ^ (row & 7)) * 16);
                LDMATRIX_X4_TRANS(vh[dp * 2][0], vh[dp * 2][1], vh[dp * 2 + 1][0], vh[dp * 2 + 1][1], sVh + off);
                LDMATRIX_X4_TRANS(vl[dp * 2][0], vl[dp * 2][1], vl[dp * 2 + 1][0], vl[dp * 2 + 1][1], sVl + off);
            }
            #pragma unroll
            for (int dt = 0; dt < 8; dt++)
                MMA_BF16(o[dt], pah, vh[dt]);
            #pragma unroll
            for (int dt = 0; dt < 8; dt++)
                MMA_BF16(o[dt], pal, vh[dt]);
            #pragma unroll
            for (int dt = 0; dt < 8; dt++)
                MMA_BF16(o[dt], pah, vl[dt]);
        }
    }

    l0 += __shfl_xor_sync(0xffffffffu, l0, 1);
    l0 += __shfl_xor_sync(0xffffffffu, l0, 2);
    l1 += __shfl_xor_sync(0xffffffffu, l1, 1);
    l1 += __shfl_xor_sync(0xffffffffu, l1, 2);
    const float inv0 = 1.0f / l0;
    const float inv1 = 1.0f / l1;

    const size_t tok0 = (size_t)b * SEQ + rowg0;
    const size_t tok1 = tok0 + 8;
    #pragma unroll
    for (int dt = 0; dt < 8; dt++) {
        const int col = h * HD + dt * 8 + tg * 2;
        {
            const float v0 = o[dt][0] * inv0, v1 = o[dt][1] * inv0;
            const bf16 h0 = __float2bfloat16(v0), h1 = __float2bfloat16(v1);
            *(uint32_t*)&Ohi[tok0 * DMODEL + col] = pack_bf2(h0, h1);
            *(uint32_t*)&Olo[tok0 * DMODEL + col] =
                pack_bf2(__float2bfloat16(v0 - __bfloat162float(h0)),
                         __float2bfloat16(v1 - __bfloat162float(h1)));
        }
        {
            const float v0 = o[dt][2] * inv1, v1 = o[dt][3] * inv1;
            const bf16 h0 = __float2bfloat16(v0), h1 = __float2bfloat16(v1);
            *(uint32_t*)&Ohi[tok1 * DMODEL + col] = pack_bf2(h0, h1);
            *(uint32_t*)&Olo[tok1 * DMODEL + col] =
                pack_bf2(__float2bfloat16(v0 - __bfloat162float(h0)),
                         __float2bfloat16(v1 - __bfloat162float(h1)));
        }
    }
}

// ---------------------------------------------------------------------------
// LayerNorm with split bf16 output (hi/lo)
// ---------------------------------------------------------------------------
__global__ __launch_bounds__(256)
void ln_split_kernel(const float* __restrict__ x, const float* __restrict__ g,
                     const float* __restrict__ b, bf16* __restrict__ ohi, bf16* __restrict__ olo)
{
    const int row = blockIdx.x;
    const int t   = threadIdx.x;
    const float4 v = ((const float4*)(x + (size_t)row * DMODEL))[t];

    float s  = v.x + v.y + v.z + v.w;
    float ss = v.x * v.x + v.y * v.y + v.z * v.z + v.w * v.w;
    #pragma unroll
    for (int o = 16; o > 0; o >>= 1) {
        s  += __shfl_xor_sync(0xffffffffu, s,  o);
        ss += __shfl_xor_sync(0xffffffffu, ss, o);
    }
    __shared__ float rs[8], rss[8];
    if ((t & 31) == 0) { rs[t >> 5] = s; rss[t >> 5] = ss; }
    __syncthreads();
    if (t < 32) {
        s  = (t < 8) ? rs[t]  : 0.f;
        ss = (t < 8) ? rss[t] : 0.f;
        #pragma unroll
        for (int o = 4; o > 0; o >>= 1) {
            s  += __shfl_xor_sync(0xffffffffu, s,  o);
            ss += __shfl_xor_sync(0xffffffffu, ss, o);
        }
        if (t == 0) { rs[0] = s; rss[0] = ss; }
    }
    __syncthreads();
    const float mu  = rs[0]  * (1.0f / DMODEL);
    const float var = rss[0] * (1.0f / DMODEL) - mu * mu;
    const float inv = rsqrtf(var + 1e-5f);

    const float4 gv = ((const float4*)g)[t];
    const float4 bv = ((const float4*)b)[t];
    float o[4];
    o[0] = (v.x - mu) * inv * gv.x + bv.x;
    o[1] = (v.y - mu) * inv * gv.y + bv.y;
    o[2] = (v.z - mu) * inv * gv.z + bv.z;
    o[3] = (v.w - mu) * inv * gv.w + bv.w;

    uint32_t hp[2], lp[2];
    #pragma unroll
    for (int i = 0; i < 2; i++) {
        const bf16 h0 = __float2bfloat16(o[2 * i]);
        const bf16 h1 = __float2bfloat16(o[2 * i + 1]);
        hp[i] = pack_bf2(h0, h1);
        lp[i] = pack_bf2(__float2bfloat16(o[2 * i] - __bfloat162float(h0)),
                         __float2bfloat16(o[2 * i + 1] - __bfloat162float(h1)));
    }
    ((uint2*)(ohi + (size_t)row * DMODEL))[t] = make_uint2(hp[0], hp[1]);
    ((uint2*)(olo + (size_t)row * DMODEL))[t] = make_uint2(lp[0], lp[1]);
}

// ---------------------------------------------------------------------------
// Weight prep: transpose + split, flattened into 2 launches.
// ---------------------------------------------------------------------------
__device__ __forceinline__ void tsplit_tile(const float* __restrict__ W,
                                            bf16* __restrict__ Thi, bf16* __restrict__ Tlo,
                                            int K, int N, int bx, int by, int tx, int ty)
{
    __shared__ float tile[32][33];
    const int kx = by * 32;
    const int nx = bx * 32;

    #pragma unroll
    for (int j = ty; j < 32; j += 8)
        tile[j][tx] = W[(size_t)(kx + j) * N + nx + tx];
    __syncthreads();

    #pragma unroll
    for (int b = ty; b < 32; b += 8) {
        const float v = tile[tx][b];
        const bf16 h = __float2bfloat16(v);
        const bf16 l = __float2bfloat16(v - __bfloat162float(h));
        Thi[(size_t)(nx + b) * K + kx + tx] = h;
        Tlo[(size_t)(nx + b) * K + kx + tx] = l;
    }
}

// prep1: wq|wk|wv -> packed wqkv (3*1024 tiles) + bias concat
__global__ void prep1_kernel(const float* __restrict__ wq, const float* __restrict__ wk,
                             const float* __restrict__ wv,
                             const float* __restrict__ bq, const float* __restrict__ bk,
                             const float* __restrict__ bv,
                             bf16* __restrict__ wqkvh, bf16* __restrict__ wqkvl,
                             float* __restrict__ bqkv)
{
    const int id = blockIdx.x;
    const int z  = id >> 10;          // 0..2
    const int t  = id & 1023;
    const int bx = t & 31, by = t >> 5;
    const int tx = threadIdx.x, ty = threadIdx.y;
    const int tid = ty * 32 + tx;

    const float* W = (z == 0) ? wq : (z == 1) ? wk : wv;
    tsplit_tile(W, wqkvh + (size_t)z * 1024 * DMODEL, wqkvl + (size_t)z * 1024 * DMODEL,
                DMODEL, DMODEL, bx, by, tx, ty);

    if (t == 0) {
        const float* src = (z == 0) ? bq : (z == 1) ? bk : bv;
        for (int i = tid; i < 1024; i += 256)
            bqkv[z * 1024 + i] = src[i];
    }
}

// prep2: wo (1024 tiles) | w1 (4096 tiles) | w2 (4096 tiles)
__global__ void prep2_kernel(const float* __restrict__ wo, const float* __restrict__ w1,
                             const float* __restrict__ w2,
                             bf16* __restrict__ woh, bf16* __restrict__ wol,
                             bf16* __restrict__ w1h, bf16* __restrict__ w1l,
                             bf16* __restrict__ w2h, bf16* __restrict__ w2l)
{
    const int id = blockIdx.x;
    const int tx = threadIdx.x, ty = threadIdx.y;

    if (id < 1024) {
        tsplit_tile(wo, woh, wol, DMODEL, DMODEL, id & 31, id >> 5, tx, ty);
    } else if (id < 5120) {
        const int t = id - 1024;
        tsplit_tile(w1, w1h, w1l, DMODEL, DFF, t & 127, t >> 7, tx, ty);
    } else {
        const int t = id - 5120;
        tsplit_tile(w2, w2h, w2l, DFF, DMODEL, t & 31, t >> 5, tx, ty);
    }
}

// ---------------------------------------------------------------------------
// Orchestration
// ---------------------------------------------------------------------------
extern "C" void kernel_launch(void* const* d_in, const int* in_sizes, int n_in,
                              void* d_out, int out_size)
{
    const float* x     = (const float*)d_in[0];
    const float* wq    = (const float*)d_in[1];
    const float* bq    = (const float*)d_in[2];
    const float* wk    = (const float*)d_in[3];
    const float* bk    = (const float*)d_in[4];
    const float* wv    = (const float*)d_in[5];
    const float* bv    = (const float*)d_in[6];
    const float* wo    = (const float*)d_in[7];
    const float* bo    = (const float*)d_in[8];
    const float* w1    = (const float*)d_in[9];
    const float* b1    = (const float*)d_in[10];
    const float* w2    = (const float*)d_in[11];
    const float* b2    = (const float*)d_in[12];
    const float* ln1_g = (const float*)d_in[13];
    const float* ln1_b = (const float*)d_in[14];
    const float* ln2_g = (const float*)d_in[15];
    const float* ln2_b = (const float*)d_in[16];
    float* out = (float*)d_out;

    float *x1, *bqkv;
    bf16 *nhi, *nlo, *qkvh, *qkvl, *ahi, *alo, *hhi, *hlo;
    bf16 *wqkvh, *wqkvl, *woh, *wol, *w1h, *w1l, *w2h, *w2l;
    cudaGetSymbolAddress((void**)&x1,    g_x1);
    cudaGetSymbolAddress((void**)&bqkv,  g_bqkv);
    cudaGetSymbolAddress((void**)&nhi,   g_nhi);
    cudaGetSymbolAddress((void**)&nlo,   g_nlo);
    cudaGetSymbolAddress((void**)&qkvh,  g_qkvh);
    cudaGetSymbolAddress((void**)&qkvl,  g_qkvl);
    cudaGetSymbolAddress((void**)&ahi,   g_ahi);
    cudaGetSymbolAddress((void**)&alo,   g_alo);
    cudaGetSymbolAddress((void**)&hhi,   g_hhi);
    cudaGetSymbolAddress((void**)&hlo,   g_hlo);
    cudaGetSymbolAddress((void**)&wqkvh, g_wqkvh);
    cudaGetSymbolAddress((void**)&wqkvl, g_wqkvl);
    cudaGetSymbolAddress((void**)&woh,   g_woh);
    cudaGetSymbolAddress((void**)&wol,   g_wol);
    cudaGetSymbolAddress((void**)&w1h,   g_w1h);
    cudaGetSymbolAddress((void**)&w1l,   g_w1l);
    cudaGetSymbolAddress((void**)&w2h,   g_w2h);
    cudaGetSymbolAddress((void**)&w2l,   g_w2l);

    cudaFuncSetAttribute(fattn_kernel, cudaFuncAttributeMaxDynamicSharedMemorySize, ATT_SMEM);
    cudaFuncSetAttribute(tgemm_kernel<false, false, false>,
                         cudaFuncAttributeMaxDynamicSharedMemorySize, TGEMM_SMEM);
    cudaFuncSetAttribute(tgemm_kernel<false, false, true>,
                         cudaFuncAttributeMaxDynamicSharedMemorySize, TGEMM_SMEM);
    cudaFuncSetAttribute(tgemm_kernel<false, true, false>,
                         cudaFuncAttributeMaxDynamicSharedMemorySize, TGEMM_SMEM);
    cudaFuncSetAttribute(tgemm_kernel<true, false, true>,
                         cudaFuncAttributeMaxDynamicSharedMemorySize, TGEMM_SMEM);

    dim3 tb(32, 8);
    // #1: QKV weights + bias concat
    prep1_kernel<<<3072, tb>>>(wq, wk, wv, bq, bk, bv, wqkvh, wqkvl, bqkv);
    // #2: wo | w1 | w2
    prep2_kernel<<<9216, tb>>>(wo, w1, w2, woh, wol, w1h, w1l, w2h, w2l);

    // #3: LN1 -> split
    ln_split_kernel<<<MTOK, 256>>>(x, ln1_g, ln1_b, nhi, nlo);

    // #4: Fused QKV projection -> packed split bf16 [MTOK, 3072]
    dim3 gQKV(LDQKV / 128, MTOK / 128);
    tgemm_kernel<false, false, true><<<gQKV, 256, TGEMM_SMEM>>>(
        nhi, nlo, wqkvh, wqkvl, bqkv, nullptr, nullptr, qkvh, qkvl, MTOK, LDQKV, DMODEL);

    // #5: Tensor-core causal flash attention -> split bf16
    fattn_kernel<<<dim3(SEQ / 128, NH, 4), 256, ATT_SMEM>>>(qkvh, qkvl, ahi, alo);

    // #6 (ncu -s 5 -c 1 target): O-projection + residual (fp32 out)
    dim3 gP(DMODEL / 128, MTOK / 128);
    tgemm_kernel<false, true, false><<<gP, 256, TGEMM_SMEM>>>(
        ahi, alo, woh, wol, bo, x, x1, nullptr, nullptr, MTOK, DMODEL, DMODEL);

    // LN2 -> split
    ln_split_kernel<<<MTOK, 256>>>(x1, ln2_g, ln2_b, nhi, nlo);

    // FF1 with GELU -> split bf16 out
    dim3 gF1(DFF / 128, MTOK / 128);
    tgemm_kernel<true, false, true><<<gF1, 256, TGEMM_SMEM>>>(
        nhi, nlo, w1h, w1l, b1, nullptr, nullptr, hhi, hlo, MTOK, DFF, DMODEL);

    // FF2 + residual -> final fp32 output
    dim3 gF2(DMODEL / 128, MTOK / 128);
    tgemm_kernel<false, true, false><<<gF2, 256, TGEMM_SMEM>>>(
        hhi, hlo, w2h, w2l, b2, x1, out, nullptr, nullptr, MTOK, DMODEL, DFF);
}

// round 11
// speedup vs baseline: 4.8077x; 1.4706x over previous
#include <cuda_runtime.h>
#include <cuda_bf16.h>
#include <cuda_fp16.h>
#include <math.h>
#include <stdint.h>

// Problem constants
#define MTOK   8192      // B*S
#define DMODEL 1024
#define DFF    4096
#define SEQ    2048
#define NH     16
#define HD     64
#define LDQKV  3072      // packed q|k|v row stride

typedef __nv_bfloat16 bf16;

// ---------------------------------------------------------------------------
// Scratch (static device globals)
// ---------------------------------------------------------------------------
__device__ float g_x1  [(size_t)MTOK * DMODEL];

__device__ bf16 g_nhi [(size_t)MTOK * DMODEL];
__device__ bf16 g_nlo [(size_t)MTOK * DMODEL];
__device__ bf16 g_qkvh[(size_t)MTOK * LDQKV];
__device__ bf16 g_qkvl[(size_t)MTOK * LDQKV];
__device__ bf16 g_ahi [(size_t)MTOK * DMODEL];
__device__ bf16 g_alo [(size_t)MTOK * DMODEL];
__device__ __half g_n2h[(size_t)MTOK * DMODEL];   // LN2 out, fp16 single
__device__ __half g_hh [(size_t)MTOK * DFF];      // FF1 out, fp16 single

// transposed+split weights [N,K]
__device__ bf16 g_wqkvh[(size_t)LDQKV * DMODEL];
__device__ bf16 g_wqkvl[(size_t)LDQKV * DMODEL];
__device__ bf16 g_woh[(size_t)DMODEL * DMODEL];
__device__ bf16 g_wol[(size_t)DMODEL * DMODEL];
__device__ __half g_w1s[(size_t)DFF * DMODEL];    // fp16 single
__device__ __half g_w2s[(size_t)DMODEL * DFF];    // fp16 single
__device__ float g_bqkv[LDQKV];

// ---------------------------------------------------------------------------
// PTX helpers (non-'a'-gated: cp.async, ldmatrix, mma.sync)
// ---------------------------------------------------------------------------
__device__ __forceinline__ uint32_t smem_to_u32(const void* p) {
    uint32_t a;
    asm("{ .reg .u64 t; cvta.to.shared.u64 t, %1; cvt.u32.u64 %0, t; }" : "=r"(a) : "l"(p));
    return a;
}
#define CP_ASYNC_CG(dst, src) \
    asm volatile("cp.async.cg.shared.global [%0], [%1], 16;" :: "r"(dst), "l"(src) : "memory")
#define CP_ASYNC_COMMIT() asm volatile("cp.async.commit_group;" ::: "memory")
#define CP_ASYNC_WAIT(n)  asm volatile("cp.async.wait_group %0;" :: "n"(n) : "memory")

#define LDMATRIX_X4(r0, r1, r2, r3, addr) \
    asm volatile("ldmatrix.sync.aligned.m8n8.x4.shared.b16 {%0,%1,%2,%3}, [%4];" \
                 : "=r"(r0), "=r"(r1), "=r"(r2), "=r"(r3) : "r"(addr))

#define LDMATRIX_X4_TRANS(r0, r1, r2, r3, addr) \
    asm volatile("ldmatrix.sync.aligned.m8n8.x4.trans.shared.b16 {%0,%1,%2,%3}, [%4];" \
                 : "=r"(r0), "=r"(r1), "=r"(r2), "=r"(r3) : "r"(addr))

#define MMA_BF16(c, a, b) \
    asm volatile("mma.sync.aligned.m16n8k16.row.col.f32.bf16.bf16.f32 " \
                 "{%0,%1,%2,%3}, {%4,%5,%6,%7}, {%8,%9}, {%0,%1,%2,%3};" \
                 : "+f"((c)[0]), "+f"((c)[1]), "+f"((c)[2]), "+f"((c)[3]) \
                 : "r"((a)[0]), "r"((a)[1]), "r"((a)[2]), "r"((a)[3]), \
                   "r"((b)[0]), "r"((b)[1]))

#define MMA_F16(c, a, b) \
    asm volatile("mma.sync.aligned.m16n8k16.row.col.f32.f16.f16.f32 " \
                 "{%0,%1,%2,%3}, {%4,%5,%6,%7}, {%8,%9}, {%0,%1,%2,%3};" \
                 : "+f"((c)[0]), "+f"((c)[1]), "+f"((c)[2]), "+f"((c)[3]) \
                 : "r"((a)[0]), "r"((a)[1]), "r"((a)[2]), "r"((a)[3]), \
                   "r"((b)[0]), "r"((b)[1]))

__device__ __forceinline__ float gelu_exact(float x) {
    return 0.5f * x * (1.0f + erff(x * 0.70710678118654752f));
}
__device__ __forceinline__ uint32_t pack_bf2(bf16 a, bf16 b) {
    __nv_bfloat162 t; t.x = a; t.y = b;
    return *(uint32_t*)&t;
}
__device__ __forceinline__ uint32_t pack_h2(__half a, __half b) {
    __half2 t; t.x = a; t.y = b;
    return *(uint32_t*)&t;
}

extern __shared__ char dynsmem[];

// ---------------------------------------------------------------------------
// bf16 3-term split GEMM (unchanged from R9): QKV + O-proj path
// ---------------------------------------------------------------------------
#define BK 64
#define STAGES 3
#define STAGE_BYTES 65536
#define TGEMM_SMEM (STAGES * STAGE_BYTES)

__device__ __forceinline__ void issue_stage(
    const bf16* __restrict__ Ahi, const bf16* __restrict__ Alo,
    const bf16* __restrict__ Bhi, const bf16* __restrict__ Blo,
    int K, int k0, uint32_t stage_base, int tid)
{
    #pragma unroll
    for (int i = 0; i < 16; i++) {
        const int idx  = i * 256 + tid;
        const int tile = idx >> 10;
        const int rem  = idx & 1023;
        const int row  = rem >> 3;
        const int quad = rem & 7;
        const bf16* src;
        if      (tile == 0) src = Ahi;
        else if (tile == 1) src = Alo;
        else if (tile == 2) src = Bhi;
        else                src = Blo;
        src += (size_t)row * K + k0 + quad * 8;
        const uint32_t dst = stage_base + tile * 16384 + row * 128 +
                             ((quad ^ (row & 7)) * 16);
        CP_ASYNC_CG(dst, src);
    }
}

template <bool RES, bool SPLITOUT>
__global__ __launch_bounds__(256, 1)
void tgemm_kernel(const bf16* __restrict__ Ahi, const bf16* __restrict__ Alo,
                  const bf16* __restrict__ Bhi, const bf16* __restrict__ Blo,
                  const float* __restrict__ bias, const float* __restrict__ res,
                  float* __restrict__ Cf, bf16* __restrict__ Chi, bf16* __restrict__ Clo,
                  int M, int N, int K)
{
    const uint32_t sb = smem_to_u32(dynsmem);
    const int tid = threadIdx.x;
    const int wid = tid >> 5;
    const int lid = tid & 31;

    const int a0 = blockIdx.y * 128;
    const int b0 = blockIdx.x * 128;
    const int m_w = (wid & 3) * 32;
    const int n_w = (wid >> 2) * 64;

    const bf16* Ah = Ahi + (size_t)a0 * K;
    const bf16* Al = Alo + (size_t)a0 * K;
    const bf16* Bh = Bhi + (size_t)b0 * K;
    const bf16* Bl = Blo + (size_t)b0 * K;

    const int nch = K / BK;

    #pragma unroll
    for (int s = 0; s < STAGES - 1; s++) {
        issue_stage(Ah, Al, Bh, Bl, K, s * BK, sb + s * STAGE_BYTES, tid);
        CP_ASYNC_COMMIT();
    }

    float acc[2][8][4];
    #pragma unroll
    for (int i = 0; i < 2; i++)
        #pragma unroll
        for (int j = 0; j < 8; j++)
            #pragma unroll
            for (int c = 0; c < 4; c++) acc[i][j][c] = 0.f;

    const int bA  = lid >> 3;
    const int r8  = lid & 7;
    const int rowA_off = ((bA & 1) * 8) + r8;
    const int qA_off   = bA >> 1;
    const int rowB_off = ((bA >> 1) * 8) + r8;
    const int qB_off   = bA & 1;

    for (int i = 0; i < nch; i++) {
        if (i + 1 < nch) { CP_ASYNC_WAIT(1); } else { CP_ASYNC_WAIT(0); }
        __syncthreads();

        if (i + STAGES - 1 < nch)
            issue_stage(Ah, Al, Bh, Bl, K, (i + STAGES - 1) * BK,
                        sb + ((i + STAGES - 1) % STAGES) * STAGE_BYTES, tid);
        CP_ASYNC_COMMIT();

        const uint32_t st = sb + (i % STAGES) * STAGE_BYTES;
        const uint32_t sAh = st,           sAl = st + 16384;
        const uint32_t sBh = st + 32768,   sBl = st + 49152;

        #pragma unroll
        for (int ks = 0; ks < 4; ks++) {
            const int kq = ks * 2;
            uint32_t ah[2][4], al[2][4], bh[8][2], bl[8][2];

            #pragma unroll
            for (int mt = 0; mt < 2; mt++) {
                const int row  = m_w + mt * 16 + rowA_off;
                const int quad = kq + qA_off;
                const uint32_t off = row * 128 + ((quad ^ (row & 7)) * 16);
                LDMATRIX_X4(ah[mt][0], ah[mt][1], ah[mt][2], ah[mt][3], sAh + off);
                LDMATRIX_X4(al[mt][0], al[mt][1], al[mt][2], al[mt][3], sAl + off);
            }
            #pragma unroll
            for (int np = 0; np < 4; np++) {
                const int row  = n_w + np * 16 + rowB_off;
                const int quad = kq + qB_off;
                const uint32_t off = row * 128 + ((quad ^ (row & 7)) * 16);
                LDMATRIX_X4(bh[np * 2][0], bh[np * 2][1], bh[np * 2 + 1][0], bh[np * 2 + 1][1], sBh + off);
                LDMATRIX_X4(bl[np * 2][0], bl[np * 2][1], bl[np * 2 + 1][0], bl[np * 2 + 1][1], sBl + off);
            }

            #pragma unroll
            for (int mt = 0; mt < 2; mt++)
                #pragma unroll
                for (int nt = 0; nt < 8; nt++)
                    MMA_BF16(acc[mt][nt], ah[mt], bh[nt]);
            #pragma unroll
            for (int mt = 0; mt < 2; mt++)
                #pragma unroll
                for (int nt = 0; nt < 8; nt++)
                    MMA_BF16(acc[mt][nt], al[mt], bh[nt]);
            #pragma unroll
            for (int mt = 0; mt < 2; mt++)
                #pragma unroll
                for (int nt = 0; nt < 8; nt++)
                    MMA_BF16(acc[mt][nt], ah[mt], bl[nt]);
        }
    }

    const int gl  = lid >> 2;
    const int tg  = lid & 3;
    #pragma unroll
    for (int mt = 0; mt < 2; mt++) {
        #pragma unroll
        for (int half = 0; half < 2; half++) {
            const int row = a0 + m_w + mt * 16 + gl + half * 8;
            #pragma unroll
            for (int nt = 0; nt < 8; nt++) {
                const int col = b0 + n_w + nt * 8 + tg * 2;
                float v0 = acc[mt][nt][half * 2 + 0];
                float v1 = acc[mt][nt][half * 2 + 1];
                const float2 bb = *(const float2*)&bias[col];
                v0 += bb.x; v1 += bb.y;
                if (RES) {
                    const float2 r2 = *(const float2*)&res[(size_t)row * N + col];
                    v0 += r2.x; v1 += r2.y;
                }
                if (SPLITOUT) {
                    const bf16 h0 = __float2bfloat16(v0);
                    const bf16 h1 = __float2bfloat16(v1);
                    const bf16 l0 = __float2bfloat16(v0 - __bfloat162float(h0));
                    const bf16 l1 = __float2bfloat16(v1 - __bfloat162float(h1));
                    *(uint32_t*)&Chi[(size_t)row * N + col] = pack_bf2(h0, h1);
                    *(uint32_t*)&Clo[(size_t)row * N + col] = pack_bf2(l0, l1);
                } else {
                    float2 o; o.x = v0; o.y = v1;
                    *(float2*)&Cf[(size_t)row * N + col] = o;
                }
            }
        }
    }
}

// ---------------------------------------------------------------------------
// fp16 single-product GEMM (FF path): C = A[M,K] @ B[N,K]^T + bias.
// Stage = A 16KB + B 16KB = 32KB; 3 stages = 96KB -> 2 CTAs/SM.
// ---------------------------------------------------------------------------
#define HSTAGE_BYTES 32768
#define HGEMM_SMEM (3 * HSTAGE_BYTES)

__device__ __forceinline__ void issue_stage_h(
    const __half* __restrict__ A, const __half* __restrict__ B,
    int K, int k0, uint32_t stage_base, int tid)
{
    #pragma unroll
    for (int i = 0; i < 8; i++) {
        const int idx  = i * 256 + tid;     // 0..2047
        const int tile = idx >> 10;         // 0:A 1:B
        const int rem  = idx & 1023;
        const int row  = rem >> 3;
        const int quad = rem & 7;
        const __half* src = (tile ? B : A) + (size_t)row * K + k0 + quad * 8;
        const uint32_t dst = stage_base + tile * 16384 + row * 128 +
                             ((quad ^ (row & 7)) * 16);
        CP_ASYNC_CG(dst, src);
    }
}

template <bool GELU, bool RES, bool HALFOUT>
__global__ __launch_bounds__(256, 2)
void hgemm_kernel(const __half* __restrict__ A, const __half* __restrict__ B,
                  const float* __restrict__ bias, const float* __restrict__ res,
                  float* __restrict__ Cf, __half* __restrict__ Ch,
                  int M, int N, int K)
{
    const uint32_t sb = smem_to_u32(dynsmem);
    const int tid = threadIdx.x;
    const int wid = tid >> 5;
    const int lid = tid & 31;

    const int a0 = blockIdx.y * 128;
    const int b0 = blockIdx.x * 128;
    const int m_w = (wid & 3) * 32;
    const int n_w = (wid >> 2) * 64;

    const __half* Ap = A + (size_t)a0 * K;
    const __half* Bp = B + (size_t)b0 * K;

    const int nch = K / BK;

    #pragma unroll
    for (int s = 0; s < 2; s++) {
        issue_stage_h(Ap, Bp, K, s * BK, sb + s * HSTAGE_BYTES, tid);
        CP_ASYNC_COMMIT();
    }

    float acc[2][8][4];
    #pragma unroll
    for (int i = 0; i < 2; i++)
        #pragma unroll
        for (int j = 0; j < 8; j++)
            #pragma unroll
            for (int c = 0; c < 4; c++) acc[i][j][c] = 0.f;

    const int bA  = lid >> 3;
    const int r8  = lid & 7;
    const int rowA_off = ((bA & 1) * 8) + r8;
    const int qA_off   = bA >> 1;
    const int rowB_off = ((bA >> 1) * 8) + r8;
    const int qB_off   = bA & 1;

    for (int i = 0; i < nch; i++) {
        if (i + 1 < nch) { CP_ASYNC_WAIT(1); } else { CP_ASYNC_WAIT(0); }
        __syncthreads();

        if (i + 2 < nch)
            issue_stage_h(Ap, Bp, K, (i + 2) * BK,
                          sb + ((i + 2) % 3) * HSTAGE_BYTES, tid);
        CP_ASYNC_COMMIT();

        const uint32_t st = sb + (i % 3) * HSTAGE_BYTES;
        const uint32_t sA = st, sB = st + 16384;

        #pragma unroll
        for (int ks = 0; ks < 4; ks++) {
            const int kq = ks * 2;
            uint32_t ah[2][4], bh[8][2];

            #pragma unroll
            for (int mt = 0; mt < 2; mt++) {
                const int row  = m_w + mt * 16 + rowA_off;
                const int quad = kq + qA_off;
                const uint32_t off = row * 128 + ((quad ^ (row & 7)) * 16);
                LDMATRIX_X4(ah[mt][0], ah[mt][1], ah[mt][2], ah[mt][3], sA + off);
            }
            #pragma unroll
            for (int np = 0; np < 4; np++) {
                const int row  = n_w + np * 16 + rowB_off;
                const int quad = kq + qB_off;
                const uint32_t off = row * 128 + ((quad ^ (row & 7)) * 16);
                LDMATRIX_X4(bh[np * 2][0], bh[np * 2][1], bh[np * 2 + 1][0], bh[np * 2 + 1][1], sB + off);
            }

            #pragma unroll
            for (int mt = 0; mt < 2; mt++)
                #pragma unroll
                for (int nt = 0; nt < 8; nt++)
                    MMA_F16(acc[mt][nt], ah[mt], bh[nt]);
        }
    }

    const int gl  = lid >> 2;
    const int tg  = lid & 3;
    #pragma unroll
    for (int mt = 0; mt < 2; mt++) {
        #pragma unroll
        for (int half = 0; half < 2; half++) {
            const int row = a0 + m_w + mt * 16 + gl + half * 8;
            #pragma unroll
            for (int nt = 0; nt < 8; nt++) {
                const int col = b0 + n_w + nt * 8 + tg * 2;
                float v0 = acc[mt][nt][half * 2 + 0];
                float v1 = acc[mt][nt][half * 2 + 1];
                const float2 bb = *(const float2*)&bias[col];
                v0 += bb.x; v1 += bb.y;
                if (GELU) { v0 = gelu_exact(v0); v1 = gelu_exact(v1); }
                if (RES) {
                    const float2 r2 = *(const float2*)&res[(size_t)row * N + col];
                    v0 += r2.x; v1 += r2.y;
                }
                if (HALFOUT) {
                    *(uint32_t*)&Ch[(size_t)row * N + col] =
                        pack_h2(__float2half(v0), __float2half(v1));
                } else {
                    float2 o; o.x = v0; o.y = v1;
                    *(float2*)&Cf[(size_t)row * N + col] = o;
                }
            }
        }
    }
}

// ---------------------------------------------------------------------------
// Tensor-core causal flash attention (split bf16, 3-term mma) — unchanged.
// ---------------------------------------------------------------------------
#define ATT_SMEM (32768 + 3 * 32768)

__global__ __launch_bounds__(256, 1)
void fattn_kernel(const bf16* __restrict__ QKVhi, const bf16* __restrict__ QKVlo,
                  bf16* __restrict__ Ohi, bf16* __restrict__ Olo)
{
    const uint32_t sb = smem_to_u32(dynsmem);
    const int tid = threadIdx.x;
    const int wid = tid >> 5;
    const int lid = tid & 31;
    const int qt = gridDim.x - 1 - blockIdx.x;
    const int h = blockIdx.y, b = blockIdx.z;
    const int q0 = qt * 128;
    const size_t base = ((size_t)b * SEQ) * LDQKV + h * HD;

    const uint32_t sQh = sb, sQl = sb + 16384;
    const int nkt = 2 * qt + 2;

    const int bA  = lid >> 3;
    const int r8  = lid & 7;
    const int rowA_off = ((bA & 1) * 8) + r8;
    const int qA_off   = bA >> 1;
    const int rowB_off = ((bA >> 1) * 8) + r8;
    const int qB_off   = bA & 1;
    const int gl = lid >> 2;
    const int tg = lid & 3;

    #pragma unroll
    for (int i = 0; i < 8; i++) {
        const int idx = i * 256 + tid;
        const int arr = idx >> 10;
        const int rem = idx & 1023;
        const int row = rem >> 3, quad = rem & 7;
        const bf16* src = (arr ? QKVlo : QKVhi) + base + (size_t)(q0 + row) * LDQKV + quad * 8;
        const uint32_t dst = (arr ? sQl : sQh) + row * 128 + ((quad ^ (row & 7)) * 16);
        CP_ASYNC_CG(dst, src);
    }
    #pragma unroll
    for (int stg = 0; stg < 2; stg++) {
        const uint32_t st = sb + 32768 + stg * 32768;
        const int key0 = stg * 64;
        #pragma unroll
        for (int i = 0; i < 8; i++) {
            const int idx = i * 256 + tid;
            const int arr = idx >> 9;
            const int rem = idx & 511;
            const int row = rem >> 3, quad = rem & 7;
            const bf16* src = ((arr & 1) ? QKVlo : QKVhi) + base +
                              ((arr >> 1) ? 2048 : 1024) +
                              (size_t)(key0 + row) * LDQKV + quad * 8;
            const int slot = (arr >> 1) * 2 + (arr & 1);
            const uint32_t dst = st + slot * 8192 + row * 128 + ((quad ^ (row & 7)) * 16);
            CP_ASYNC_CG(dst, src);
        }
        CP_ASYNC_COMMIT();
    }

    CP_ASYNC_WAIT(1);
    __syncthreads();

    uint32_t qh[4][4], ql[4][4];
    #pragma unroll
    for (int ks = 0; ks < 4; ks++) {
        const int row  = wid * 16 + rowA_off;
        const int quad = ks * 2 + qA_off;
        const uint32_t off = row * 128 + ((quad ^ (row & 7)) * 16);
        LDMATRIX_X4(qh[ks][0], qh[ks][1], qh[ks][2], qh[ks][3], sQh + off);
        LDMATRIX_X4(ql[ks][0], ql[ks][1], ql[ks][2], ql[ks][3], sQl + off);
    }

    float o[8][4];
    #pragma unroll
    for (int d = 0; d < 8; d++)
        #pragma unroll
        for (int c = 0; c < 4; c++) o[d][c] = 0.f;
    float m0 = -1e30f, m1 = -1e30f, l0 = 0.f, l1 = 0.f;

    const int rowg0 = q0 + wid * 16 + gl;
    const int rowg1 = rowg0 + 8;

    for (int kt = 0; kt < nkt; kt++) {
        if (kt > 0) {
            if (kt + 1 < nkt) { CP_ASYNC_WAIT(1); } else { CP_ASYNC_WAIT(0); }
            __syncthreads();
        }
        if (kt + 2 < nkt) {
            const uint32_t st = sb + 32768 + ((kt + 2) % 3) * 32768;
            const int key0 = (kt + 2) * 64;
            #pragma unroll
            for (int i = 0; i < 8; i++) {
                const int idx = i * 256 + tid;
                const int arr = idx >> 9;
                const int rem = idx & 511;
                const int row = rem >> 3, quad = rem & 7;
                const bf16* src = ((arr & 1) ? QKVlo : QKVhi) + base +
                                  ((arr >> 1) ? 2048 : 1024) +
                                  (size_t)(key0 + row) * LDQKV + quad * 8;
                const int slot = (arr >> 1) * 2 + (arr & 1);
                const uint32_t dst = st + slot * 8192 + row * 128 + ((quad ^ (row & 7)) * 16);
                CP_ASYNC_CG(dst, src);
            }
            CP_ASYNC_COMMIT();
        }

        const uint32_t st = sb + 32768 + (kt % 3) * 32768;
        const uint32_t sKh = st, sKl = st + 8192, sVh = st + 16384, sVl = st + 24576;

        float p[8][4];
        #pragma unroll
        for (int nt = 0; nt < 8; nt++)
            #pragma unroll
            for (int c = 0; c < 4; c++) p[nt][c] = 0.f;

        #pragma unroll
        for (int ks = 0; ks < 4; ks++) {
            const int kq = ks * 2;
            uint32_t kh[8][2], kl[8][2];
            #pragma unroll
            for (int np = 0; np < 4; np++) {
                const int row  = np * 16 + rowB_off;
                const int quad = kq + qB_off;
                const uint32_t off = row * 128 + ((quad ^ (row & 7)) * 16);
                LDMATRIX_X4(kh[np * 2][0], kh[np * 2][1], kh[np * 2 + 1][0], kh[np * 2 + 1][1], sKh + off);
                LDMATRIX_X4(kl[np * 2][0], kl[np * 2][1], kl[np * 2 + 1][0], kl[np * 2 + 1][1], sKl + off);
            }
            #pragma unroll
            for (int nt = 0; nt < 8; nt++)
                MMA_BF16(p[nt], qh[ks], kh[nt]);
            #pragma unroll
            for (int nt = 0; nt < 8; nt++)
                MMA_BF16(p[nt], ql[ks], kh[nt]);
            #pragma unroll
            for (int nt = 0; nt < 8; nt++)
                MMA_BF16(p[nt], qh[ks], kl[nt]);
        }

        const int kt0 = kt * 64;
        const bool msk = (kt >= nkt - 2);
        float tmax0 = -1e30f, tmax1 = -1e30f;
        #pragma unroll
        for (int nt = 0; nt < 8; nt++) {
            #pragma unroll
            for (int c = 0; c < 4; c++) {
                float v = p[nt][c] * 0.125f;
                if (msk) {
                    const int col = kt0 + nt * 8 + tg * 2 + (c & 1);
                    const int rg  = (c < 2) ? rowg0 : rowg1;
                    if (col > rg) v = -1e30f;
                }
                p[nt][c] = v;
                if (c < 2) tmax0 = fmaxf(tmax0, v); else tmax1 = fmaxf(tmax1, v);
            }
        }
        tmax0 = fmaxf(tmax0, __shfl_xor_sync(0xffffffffu, tmax0, 1));
        tmax0 = fmaxf(tmax0, __shfl_xor_sync(0xffffffffu, tmax0, 2));
        tmax1 = fmaxf(tmax1, __shfl_xor_sync(0xffffffffu, tmax1, 1));
        tmax1 = fmaxf(tmax1, __shfl_xor_sync(0xffffffffu, tmax1, 2));

        const float mn0 = fmaxf(m0, tmax0);
        const float mn1 = fmaxf(m1, tmax1);
        const float cr0 = __expf(m0 - mn0);
        const float cr1 = __expf(m1 - mn1);
        m0 = mn0; m1 = mn1;
        l0 *= cr0; l1 *= cr1;
        #pragma unroll
        for (int d = 0; d < 8; d++) {
            o[d][0] *= cr0; o[d][1] *= cr0;
            o[d][2] *= cr1; o[d][3] *= cr1;
        }
        #pragma unroll
        for (int nt = 0; nt < 8; nt++) {
            p[nt][0] = __expf(p[nt][0] - mn0);
            p[nt][1] = __expf(p[nt][1] - mn0);
            p[nt][2] = __expf(p[nt][2] - mn1);
            p[nt][3] = __expf(p[nt][3] - mn1);
            l0 += p[nt][0] + p[nt][1];
            l1 += p[nt][2] + p[nt][3];
        }

        #pragma unroll
        for (int s = 0; s < 4; s++) {
            uint32_t pah[4], pal[4];
            {
                const float v00 = p[2 * s][0],     v01 = p[2 * s][1];
                const float v10 = p[2 * s][2],     v11 = p[2 * s][3];
                const float v20 = p[2 * s + 1][0], v21 = p[2 * s + 1][1];
                const float v30 = p[2 * s + 1][2], v31 = p[2 * s + 1][3];
                const bf16 h00 = __float2bfloat16(v00), h01 = __float2bfloat16(v01);
                const bf16 h10 = __float2bfloat16(v10), h11 = __float2bfloat16(v11);
                const bf16 h20 = __float2bfloat16(v20), h21 = __float2bfloat16(v21);
                const bf16 h30 = __float2bfloat16(v30), h31 = __float2bfloat16(v31);
                pah[0] = pack_bf2(h00, h01); pah[1] = pack_bf2(h10, h11);
                pah[2] = pack_bf2(h20, h21); pah[3] = pack_bf2(h30, h31);
                pal[0] = pack_bf2(__float2bfloat16(v00 - __bfloat162float(h00)),
                                  __float2bfloat16(v01 - __bfloat162float(h01)));
                pal[1] = pack_bf2(__float2bfloat16(v10 - __bfloat162float(h10)),
                                  __float2bfloat16(v11 - __bfloat162float(h11)));
                pal[2] = pack_bf2(__float2bfloat16(v20 - __bfloat162float(h20)),
                                  __float2bfloat16(v21 - __bfloat162float(h21)));
                pal[3] = pack_bf2(__float2bfloat16(v30 - __bfloat162float(h30)),
                                  __float2bfloat16(v31 - __bfloat162float(h31)));
            }
            uint32_t vh[8][2], vl[8][2];
            const int mi = lid >> 3;
            #pragma unroll
            for (int dp = 0; dp < 4; dp++) {
                const int row  = s * 16 + ((mi & 1) * 8) + r8;
                const int quad = dp * 2 + (mi >> 1);
                const uint32_t off = row * 128 + ((quad ^ (row & 7)) * 16);
                LDMATRIX_X4_TRANS(vh[dp * 2][0], vh[dp * 2][1], vh[dp * 2 + 1][0], vh[dp * 2 + 1][1], sVh + off);
                LDMATRIX_X4_TRANS(vl[dp * 2][0], vl[dp * 2][1], vl[dp * 2 + 1][0], vl[dp * 2 + 1][1], sVl + off);
            }
            #pragma unroll
            for (int dt = 0; dt < 8; dt++)
                MMA_BF16(o[dt], pah, vh[dt]);
            #pragma unroll
            for (int dt = 0; dt < 8; dt++)
                MMA_BF16(o[dt], pal, vh[dt]);
            #pragma unroll
            for (int dt = 0; dt < 8; dt++)
                MMA_BF16(o[dt], pah, vl[dt]);
        }
    }

    l0 += __shfl_xor_sync(0xffffffffu, l0, 1);
    l0 += __shfl_xor_sync(0xffffffffu, l0, 2);
    l1 += __shfl_xor_sync(0xffffffffu, l1, 1);
    l1 += __shfl_xor_sync(0xffffffffu, l1, 2);
    const float inv0 = 1.0f / l0;
    const float inv1 = 1.0f / l1;

    const size_t tok0 = (size_t)b * SEQ + rowg0;
    const size_t tok1 = tok0 + 8;
    #pragma unroll
    for (int dt = 0; dt < 8; dt++) {
        const int col = h * HD + dt * 8 + tg * 2;
        {
            const float v0 = o[dt][0] * inv0, v1 = o[dt][1] * inv0;
            const bf16 h0 = __float2bfloat16(v0), h1 = __float2bfloat16(v1);
            *(uint32_t*)&Ohi[tok0 * DMODEL + col] = pack_bf2(h0, h1);
            *(uint32_t*)&Olo[tok0 * DMODEL + col] =
                pack_bf2(__float2bfloat16(v0 - __bfloat162float(h0)),
                         __float2bfloat16(v1 - __bfloat162float(h1)));
        }
        {
            const float v0 = o[dt][2] * inv1, v1 = o[dt][3] * inv1;
            const bf16 h0 = __float2bfloat16(v0), h1 = __float2bfloat16(v1);
            *(uint32_t*)&Ohi[tok1 * DMODEL + col] = pack_bf2(h0, h1);
            *(uint32_t*)&Olo[tok1 * DMODEL + col] =
                pack_bf2(__float2bfloat16(v0 - __bfloat162float(h0)),
                         __float2bfloat16(v1 - __bfloat162float(h1)));
        }
    }
}

// ---------------------------------------------------------------------------
// LayerNorm variants
// ---------------------------------------------------------------------------
__device__ __forceinline__ void ln_core(const float4 v, int t, float* rs, float* rss,
                                        float& mu, float& inv)
{
    float s  = v.x + v.y + v.z + v.w;
    float ss = v.x * v.x + v.y * v.y + v.z * v.z + v.w * v.w;
    #pragma unroll
    for (int o = 16; o > 0; o >>= 1) {
        s  += __shfl_xor_sync(0xffffffffu, s,  o);
        ss += __shfl_xor_sync(0xffffffffu, ss, o);
    }
    if ((t & 31) == 0) { rs[t >> 5] = s; rss[t >> 5] = ss; }
    __syncthreads();
    if (t < 32) {
        s  = (t < 8) ? rs[t]  : 0.f;
        ss = (t < 8) ? rss[t] : 0.f;
        #pragma unroll
        for (int o = 4; o > 0; o >>= 1) {
            s  += __shfl_xor_sync(0xffffffffu, s,  o);
            ss += __shfl_xor_sync(0xffffffffu, ss, o);
        }
        if (t == 0) { rs[0] = s; rss[0] = ss; }
    }
    __syncthreads();
    mu = rs[0] * (1.0f / DMODEL);
    const float var = rss[0] * (1.0f / DMODEL) - mu * mu;
    inv = rsqrtf(var + 1e-5f);
}

__global__ __launch_bounds__(256)
void ln_split_kernel(const float* __restrict__ x, const float* __restrict__ g,
                     const float* __restrict__ b, bf16* __restrict__ ohi, bf16* __restrict__ olo)
{
    const int row = blockIdx.x;
    const int t   = threadIdx.x;
    const float4 v = ((const float4*)(x + (size_t)row * DMODEL))[t];
    __shared__ float rs[8], rss[8];
    float mu, inv;
    ln_core(v, t, rs, rss, mu, inv);

    const float4 gv = ((const float4*)g)[t];
    const float4 bv = ((const float4*)b)[t];
    float o[4];
    o[0] = (v.x - mu) * inv * gv.x + bv.x;
    o[1] = (v.y - mu) * inv * gv.y + bv.y;
    o[2] = (v.z - mu) * inv * gv.z + bv.z;
    o[3] = (v.w - mu) * inv * gv.w + bv.w;

    uint32_t hp[2], lp[2];
    #pragma unroll
    for (int i = 0; i < 2; i++) {
        const bf16 h0 = __float2bfloat16(o[2 * i]);
        const bf16 h1 = __float2bfloat16(o[2 * i + 1]);
        hp[i] = pack_bf2(h0, h1);
        lp[i] = pack_bf2(__float2bfloat16(o[2 * i] - __bfloat162float(h0)),
                         __float2bfloat16(o[2 * i + 1] - __bfloat162float(h1)));
    }
    ((uint2*)(ohi + (size_t)row * DMODEL))[t] = make_uint2(hp[0], hp[1]);
    ((uint2*)(olo + (size_t)row * DMODEL))[t] = make_uint2(lp[0], lp[1]);
}

__global__ __launch_bounds__(256)
void ln_half_kernel(const float* __restrict__ x, const float* __restrict__ g,
                    const float* __restrict__ b, __half* __restrict__ oh)
{
    const int row = blockIdx.x;
    const int t   = threadIdx.x;
    const float4 v = ((const float4*)(x + (size_t)row * DMODEL))[t];
    __shared__ float rs[8], rss[8];
    float mu, inv;
    ln_core(v, t, rs, rss, mu, inv);

    const float4 gv = ((const float4*)g)[t];
    const float4 bv = ((const float4*)b)[t];
    float o[4];
    o[0] = (v.x - mu) * inv * gv.x + bv.x;
    o[1] = (v.y - mu) * inv * gv.y + bv.y;
    o[2] = (v.z - mu) * inv * gv.z + bv.z;
    o[3] = (v.w - mu) * inv * gv.w + bv.w;

    uint2 pk;
    pk.x = pack_h2(__float2half(o[0]), __float2half(o[1]));
    pk.y = pack_h2(__float2half(o[2]), __float2half(o[3]));
    ((uint2*)(oh + (size_t)row * DMODEL))[t] = pk;
}

// ---------------------------------------------------------------------------
// Weight prep
// ---------------------------------------------------------------------------
__device__ __forceinline__ void tsplit_tile(const float* __restrict__ W,
                                            bf16* __restrict__ Thi, bf16* __restrict__ Tlo,
                                            int K, int N, int bx, int by, int tx, int ty)
{
    __shared__ float tile[32][33];
    const int kx = by * 32;
    const int nx = bx * 32;

    #pragma unroll
    for (int j = ty; j < 32; j += 8)
        tile[j][tx] = W[(size_t)(kx + j) * N + nx + tx];
    __syncthreads();

    #pragma unroll
    for (int b = ty; b < 32; b += 8) {
        const float v = tile[tx][b];
        const bf16 h = __float2bfloat16(v);
        const bf16 l = __float2bfloat16(v - __bfloat162float(h));
        Thi[(size_t)(nx + b) * K + kx + tx] = h;
        Tlo[(size_t)(nx + b) * K + kx + tx] = l;
    }
}

__device__ __forceinline__ void htile(const float* __restrict__ W, __half* __restrict__ T,
                                      int K, int N, int bx, int by, int tx, int ty)
{
    __shared__ float tile2[32][33];
    const int kx = by * 32;
    const int nx = bx * 32;

    #pragma unroll
    for (int j = ty; j < 32; j += 8)
        tile2[j][tx] = W[(size_t)(kx + j) * N + nx + tx];
    __syncthreads();

    #pragma unroll
    for (int b = ty; b < 32; b += 8)
        T[(size_t)(nx + b) * K + kx + tx] = __float2half(tile2[tx][b]);
}

// prep1: wq|wk|wv -> packed wqkv (bf16 hi/lo) + bias concat
__global__ void prep1_kernel(const float* __restrict__ wq, const float* __restrict__ wk,
                             const float* __restrict__ wv,
                             const float* __restrict__ bq, const float* __restrict__ bk,
                             const float* __restrict__ bv,
                             bf16* __restrict__ wqkvh, bf16* __restrict__ wqkvl,
                             float* __restrict__ bqkv)
{
    const int id = blockIdx.x;
    const int z  = id >> 10;
    const int t  = id & 1023;
    const int bx = t & 31, by = t >> 5;
    const int tx = threadIdx.x, ty = threadIdx.y;
    const int tid = ty * 32 + tx;

    const float* W = (z == 0) ? wq : (z == 1) ? wk : wv;
    tsplit_tile(W, wqkvh + (size_t)z * 1024 * DMODEL, wqkvl + (size_t)z * 1024 * DMODEL,
                DMODEL, DMODEL, bx, by, tx, ty);

    if (t == 0) {
        const float* src = (z == 0) ? bq : (z == 1) ? bk : bv;
        for (int i = tid; i < 1024; i += 256)
            bqkv[z * 1024 + i] = src[i];
    }
}

// prep2: wo (bf16 hi/lo, 1024 tiles) | w1 (fp16, 4096 tiles) | w2 (fp16, 4096 tiles)
__global__ void prep2_kernel(const float* __restrict__ wo, const float* __restrict__ w1,
                             const float* __restrict__ w2,
                             bf16* __restrict__ woh, bf16* __restrict__ wol,
                             __half* __restrict__ w1s, __half* __restrict__ w2s)
{
    const int id = blockIdx.x;
    const int tx = threadIdx.x, ty = threadIdx.y;

    if (id < 1024) {
        tsplit_tile(wo, woh, wol, DMODEL, DMODEL, id & 31, id >> 5, tx, ty);
    } else if (id < 5120) {
        const int t = id - 1024;
        htile(w1, w1s, DMODEL, DFF, t & 127, t >> 7, tx, ty);
    } else {
        const int t = id - 5120;
        htile(w2, w2s, DFF, DMODEL, t & 31, t >> 5, tx, ty);
    }
}

// ---------------------------------------------------------------------------
// Orchestration
// ---------------------------------------------------------------------------
extern "C" void kernel_launch(void* const* d_in, const int* in_sizes, int n_in,
                              void* d_out, int out_size)
{
    const float* x     = (const float*)d_in[0];
    const float* wq    = (const float*)d_in[1];
    const float* bq    = (const float*)d_in[2];
    const float* wk    = (const float*)d_in[3];
    const float* bk    = (const float*)d_in[4];
    const float* wv    = (const float*)d_in[5];
    const float* bv    = (const float*)d_in[6];
    const float* wo    = (const float*)d_in[7];
    const float* bo    = (const float*)d_in[8];
    const float* w1    = (const float*)d_in[9];
    const float* b1    = (const float*)d_in[10];
    const float* w2    = (const float*)d_in[11];
    const float* b2    = (const float*)d_in[12];
    const float* ln1_g = (const float*)d_in[13];
    const float* ln1_b = (const float*)d_in[14];
    const float* ln2_g = (const float*)d_in[15];
    const float* ln2_b = (const float*)d_in[16];
    float* out = (float*)d_out;

    float *x1, *bqkv;
    bf16 *nhi, *nlo, *qkvh, *qkvl, *ahi, *alo;
    bf16 *wqkvh, *wqkvl, *woh, *wol;
    __half *n2h, *hh, *w1s, *w2s;
    cudaGetSymbolAddress((void**)&x1,    g_x1);
    cudaGetSymbolAddress((void**)&bqkv,  g_bqkv);
    cudaGetSymbolAddress((void**)&nhi,   g_nhi);
    cudaGetSymbolAddress((void**)&nlo,   g_nlo);
    cudaGetSymbolAddress((void**)&qkvh,  g_qkvh);
    cudaGetSymbolAddress((void**)&qkvl,  g_qkvl);
    cudaGetSymbolAddress((void**)&ahi,   g_ahi);
    cudaGetSymbolAddress((void**)&alo,   g_alo);
    cudaGetSymbolAddress((void**)&n2h,   g_n2h);
    cudaGetSymbolAddress((void**)&hh,    g_hh);
    cudaGetSymbolAddress((void**)&wqkvh, g_wqkvh);
    cudaGetSymbolAddress((void**)&wqkvl, g_wqkvl);
    cudaGetSymbolAddress((void**)&woh,   g_woh);
    cudaGetSymbolAddress((void**)&wol,   g_wol);
    cudaGetSymbolAddress((void**)&w1s,   g_w1s);
    cudaGetSymbolAddress((void**)&w2s,   g_w2s);

    cudaFuncSetAttribute(fattn_kernel, cudaFuncAttributeMaxDynamicSharedMemorySize, ATT_SMEM);
    cudaFuncSetAttribute(tgemm_kernel<false, true>,
                         cudaFuncAttributeMaxDynamicSharedMemorySize, TGEMM_SMEM);
    cudaFuncSetAttribute(tgemm_kernel<true, false>,
                         cudaFuncAttributeMaxDynamicSharedMemorySize, TGEMM_SMEM);
    cudaFuncSetAttribute(hgemm_kernel<true, false, true>,
                         cudaFuncAttributeMaxDynamicSharedMemorySize, HGEMM_SMEM);
    cudaFuncSetAttribute(hgemm_kernel<false, true, false>,
                         cudaFuncAttributeMaxDynamicSharedMemorySize, HGEMM_SMEM);

    dim3 tb(32, 8);
    prep1_kernel<<<3072, tb>>>(wq, wk, wv, bq, bk, bv, wqkvh, wqkvl, bqkv);
    prep2_kernel<<<9216, tb>>>(wo, w1, w2, woh, wol, w1s, w2s);

    // LN1 -> split bf16
    ln_split_kernel<<<MTOK, 256>>>(x, ln1_g, ln1_b, nhi, nlo);

    // Fused QKV projection (bf16 3-term) -> packed split bf16
    dim3 gQKV(LDQKV / 128, MTOK / 128);
    tgemm_kernel<false, true><<<gQKV, 256, TGEMM_SMEM>>>(
        nhi, nlo, wqkvh, wqkvl, bqkv, nullptr, nullptr, qkvh, qkvl, MTOK, LDQKV, DMODEL);

    // Causal flash attention (bf16 3-term)
    fattn_kernel<<<dim3(SEQ / 128, NH, 4), 256, ATT_SMEM>>>(qkvh, qkvl, ahi, alo);

    // O-projection + residual (bf16 3-term, fp32 out)
    dim3 gP(DMODEL / 128, MTOK / 128);
    tgemm_kernel<true, false><<<gP, 256, TGEMM_SMEM>>>(
        ahi, alo, woh, wol, bo, x, x1, nullptr, nullptr, MTOK, DMODEL, DMODEL);

    // LN2 -> fp16 single
    ln_half_kernel<<<MTOK, 256>>>(x1, ln2_g, ln2_b, n2h);

    // FF1 (fp16 single) with GELU -> fp16 single out
    dim3 gF1(DFF / 128, MTOK / 128);
    hgemm_kernel<true, false, true><<<gF1, 256, HGEMM_SMEM>>>(
        n2h, w1s, b1, nullptr, nullptr, hh, MTOK, DFF, DMODEL);

    // FF2 (fp16 single) + residual -> final fp32 output
    dim3 gF2(DMODEL / 128, MTOK / 128);
    hgemm_kernel<false, true, false><<<gF2, 256, HGEMM_SMEM>>>(
        hh, w2s, b2, x1, out, nullptr, MTOK, DMODEL, DFF);
}

// round 12
// speedup vs baseline: 6.0774x; 1.2641x over previous
#include <cuda_runtime.h>
#include <cuda_bf16.h>
#include <cuda_fp16.h>
#include <math.h>
#include <stdint.h>

// Problem constants
#define MTOK   8192      // B*S
#define DMODEL 1024
#define DFF    4096
#define SEQ    2048
#define NH     16
#define HD     64
#define LDQKV  3072      // packed q|k|v row stride

typedef __nv_bfloat16 bf16;

// ---------------------------------------------------------------------------
// Scratch (static device globals)
// ---------------------------------------------------------------------------
__device__ float g_x1  [(size_t)MTOK * DMODEL];

__device__ bf16   g_nhi [(size_t)MTOK * DMODEL];
__device__ bf16   g_nlo [(size_t)MTOK * DMODEL];
__device__ __half g_qkv [(size_t)MTOK * LDQKV];   // QKV out, fp16 single
__device__ __half g_ao  [(size_t)MTOK * DMODEL];  // attention out, fp16 single
__device__ __half g_n2h [(size_t)MTOK * DMODEL];  // LN2 out, fp16 single
__device__ __half g_hh  [(size_t)MTOK * DFF];     // FF1 out, fp16 single

// transposed weights [N,K]
__device__ bf16   g_wqkvh[(size_t)LDQKV * DMODEL];
__device__ bf16   g_wqkvl[(size_t)LDQKV * DMODEL];
__device__ __half g_wos[(size_t)DMODEL * DMODEL]; // fp16 single
__device__ __half g_w1s[(size_t)DFF * DMODEL];
__device__ __half g_w2s[(size_t)DMODEL * DFF];
__device__ float  g_bqkv[LDQKV];

// ---------------------------------------------------------------------------
// PTX helpers (non-'a'-gated: cp.async, ldmatrix, mma.sync)
// ---------------------------------------------------------------------------
__device__ __forceinline__ uint32_t smem_to_u32(const void* p) {
    uint32_t a;
    asm("{ .reg .u64 t; cvta.to.shared.u64 t, %1; cvt.u32.u64 %0, t; }" : "=r"(a) : "l"(p));
    return a;
}
#define CP_ASYNC_CG(dst, src) \
    asm volatile("cp.async.cg.shared.global [%0], [%1], 16;" :: "r"(dst), "l"(src) : "memory")
#define CP_ASYNC_COMMIT() asm volatile("cp.async.commit_group;" ::: "memory")
#define CP_ASYNC_WAIT(n)  asm volatile("cp.async.wait_group %0;" :: "n"(n) : "memory")

#define LDMATRIX_X4(r0, r1, r2, r3, addr) \
    asm volatile("ldmatrix.sync.aligned.m8n8.x4.shared.b16 {%0,%1,%2,%3}, [%4];" \
                 : "=r"(r0), "=r"(r1), "=r"(r2), "=r"(r3) : "r"(addr))

#define LDMATRIX_X4_TRANS(r0, r1, r2, r3, addr) \
    asm volatile("ldmatrix.sync.aligned.m8n8.x4.trans.shared.b16 {%0,%1,%2,%3}, [%4];" \
                 : "=r"(r0), "=r"(r1), "=r"(r2), "=r"(r3) : "r"(addr))

#define MMA_BF16(c, a, b) \
    asm volatile("mma.sync.aligned.m16n8k16.row.col.f32.bf16.bf16.f32 " \
                 "{%0,%1,%2,%3}, {%4,%5,%6,%7}, {%8,%9}, {%0,%1,%2,%3};" \
                 : "+f"((c)[0]), "+f"((c)[1]), "+f"((c)[2]), "+f"((c)[3]) \
                 : "r"((a)[0]), "r"((a)[1]), "r"((a)[2]), "r"((a)[3]), \
                   "r"((b)[0]), "r"((b)[1]))

#define MMA_F16(c, a, b) \
    asm volatile("mma.sync.aligned.m16n8k16.row.col.f32.f16.f16.f32 " \
                 "{%0,%1,%2,%3}, {%4,%5,%6,%7}, {%8,%9}, {%0,%1,%2,%3};" \
                 : "+f"((c)[0]), "+f"((c)[1]), "+f"((c)[2]), "+f"((c)[3]) \
                 : "r"((a)[0]), "r"((a)[1]), "r"((a)[2]), "r"((a)[3]), \
                   "r"((b)[0]), "r"((b)[1]))

__device__ __forceinline__ float gelu_exact(float x) {
    return 0.5f * x * (1.0f + erff(x * 0.70710678118654752f));
}
__device__ __forceinline__ uint32_t pack_bf2(bf16 a, bf16 b) {
    __nv_bfloat162 t; t.x = a; t.y = b;
    return *(uint32_t*)&t;
}
__device__ __forceinline__ uint32_t pack_h2(__half a, __half b) {
    __half2 t; t.x = a; t.y = b;
    return *(uint32_t*)&t;
}

extern __shared__ char dynsmem[];

// ---------------------------------------------------------------------------
// bf16 3-term split GEMM (QKV only): fp16-single output.
// CTA 128x128, 8 warps, K-chunk 64, 3-stage cp.async, 192KB smem.
// ---------------------------------------------------------------------------
#define BK 64
#define STAGES 3
#define STAGE_BYTES 65536
#define TGEMM_SMEM (STAGES * STAGE_BYTES)

__device__ __forceinline__ void issue_stage(
    const bf16* __restrict__ Ahi, const bf16* __restrict__ Alo,
    const bf16* __restrict__ Bhi, const bf16* __restrict__ Blo,
    int K, int k0, uint32_t stage_base, int tid)
{
    #pragma unroll
    for (int i = 0; i < 16; i++) {
        const int idx  = i * 256 + tid;
        const int tile = idx >> 10;
        const int rem  = idx & 1023;
        const int row  = rem >> 3;
        const int quad = rem & 7;
        const bf16* src;
        if      (tile == 0) src = Ahi;
        else if (tile == 1) src = Alo;
        else if (tile == 2) src = Bhi;
        else                src = Blo;
        src += (size_t)row * K + k0 + quad * 8;
        const uint32_t dst = stage_base + tile * 16384 + row * 128 +
                             ((quad ^ (row & 7)) * 16);
        CP_ASYNC_CG(dst, src);
    }
}

__global__ __launch_bounds__(256, 1)
void tgemm_kernel(const bf16* __restrict__ Ahi, const bf16* __restrict__ Alo,
                  const bf16* __restrict__ Bhi, const bf16* __restrict__ Blo,
                  const float* __restrict__ bias, __half* __restrict__ Ch,
                  int M, int N, int K)
{
    const uint32_t sb = smem_to_u32(dynsmem);
    const int tid = threadIdx.x;
    const int wid = tid >> 5;
    const int lid = tid & 31;

    const int a0 = blockIdx.y * 128;
    const int b0 = blockIdx.x * 128;
    const int m_w = (wid & 3) * 32;
    const int n_w = (wid >> 2) * 64;

    const bf16* Ah = Ahi + (size_t)a0 * K;
    const bf16* Al = Alo + (size_t)a0 * K;
    const bf16* Bh = Bhi + (size_t)b0 * K;
    const bf16* Bl = Blo + (size_t)b0 * K;

    const int nch = K / BK;

    #pragma unroll
    for (int s = 0; s < STAGES - 1; s++) {
        issue_stage(Ah, Al, Bh, Bl, K, s * BK, sb + s * STAGE_BYTES, tid);
        CP_ASYNC_COMMIT();
    }

    float acc[2][8][4];
    #pragma unroll
    for (int i = 0; i < 2; i++)
        #pragma unroll
        for (int j = 0; j < 8; j++)
            #pragma unroll
            for (int c = 0; c < 4; c++) acc[i][j][c] = 0.f;

    const int bA  = lid >> 3;
    const int r8  = lid & 7;
    const int rowA_off = ((bA & 1) * 8) + r8;
    const int qA_off   = bA >> 1;
    const int rowB_off = ((bA >> 1) * 8) + r8;
    const int qB_off   = bA & 1;

    for (int i = 0; i < nch; i++) {
        if (i + 1 < nch) { CP_ASYNC_WAIT(1); } else { CP_ASYNC_WAIT(0); }
        __syncthreads();

        if (i + STAGES - 1 < nch)
            issue_stage(Ah, Al, Bh, Bl, K, (i + STAGES - 1) * BK,
                        sb + ((i + STAGES - 1) % STAGES) * STAGE_BYTES, tid);
        CP_ASYNC_COMMIT();

        const uint32_t st = sb + (i % STAGES) * STAGE_BYTES;
        const uint32_t sAh = st,           sAl = st + 16384;
        const uint32_t sBh = st + 32768,   sBl = st + 49152;

        #pragma unroll
        for (int ks = 0; ks < 4; ks++) {
            const int kq = ks * 2;
            uint32_t ah[2][4], al[2][4], bh[8][2], bl[8][2];

            #pragma unroll
            for (int mt = 0; mt < 2; mt++) {
                const int row  = m_w + mt * 16 + rowA_off;
                const int quad = kq + qA_off;
                const uint32_t off = row * 128 + ((quad ^ (row & 7)) * 16);
                LDMATRIX_X4(ah[mt][0], ah[mt][1], ah[mt][2], ah[mt][3], sAh + off);
                LDMATRIX_X4(al[mt][0], al[mt][1], al[mt][2], al[mt][3], sAl + off);
            }
            #pragma unroll
            for (int np = 0; np < 4; np++) {
                const int row  = n_w + np * 16 + rowB_off;
                const int quad = kq + qB_off;
                const uint32_t off = row * 128 + ((quad ^ (row & 7)) * 16);
                LDMATRIX_X4(bh[np * 2][0], bh[np * 2][1], bh[np * 2 + 1][0], bh[np * 2 + 1][1], sBh + off);
                LDMATRIX_X4(bl[np * 2][0], bl[np * 2][1], bl[np * 2 + 1][0], bl[np * 2 + 1][1], sBl + off);
            }

            #pragma unroll
            for (int mt = 0; mt < 2; mt++)
                #pragma unroll
                for (int nt = 0; nt < 8; nt++)
                    MMA_BF16(acc[mt][nt], ah[mt], bh[nt]);
            #pragma unroll
            for (int mt = 0; mt < 2; mt++)
                #pragma unroll
                for (int nt = 0; nt < 8; nt++)
                    MMA_BF16(acc[mt][nt], al[mt], bh[nt]);
            #pragma unroll
            for (int mt = 0; mt < 2; mt++)
                #pragma unroll
                for (int nt = 0; nt < 8; nt++)
                    MMA_BF16(acc[mt][nt], ah[mt], bl[nt]);
        }
    }

    const int gl  = lid >> 2;
    const int tg  = lid & 3;
    #pragma unroll
    for (int mt = 0; mt < 2; mt++) {
        #pragma unroll
        for (int half = 0; half < 2; half++) {
            const int row = a0 + m_w + mt * 16 + gl + half * 8;
            #pragma unroll
            for (int nt = 0; nt < 8; nt++) {
                const int col = b0 + n_w + nt * 8 + tg * 2;
                float v0 = acc[mt][nt][half * 2 + 0];
                float v1 = acc[mt][nt][half * 2 + 1];
                const float2 bb = *(const float2*)&bias[col];
                v0 += bb.x; v1 += bb.y;
                *(uint32_t*)&Ch[(size_t)row * N + col] =
                    pack_h2(__float2half(v0), __float2half(v1));
            }
        }
    }
}

// ---------------------------------------------------------------------------
// fp16 single-product GEMM: C = A[M,K] @ B[N,K]^T + bias (O-proj + FF path).
// Stage = A 16KB + B 16KB = 32KB; 3 stages = 96KB -> 2 CTAs/SM.
// ---------------------------------------------------------------------------
#define HSTAGE_BYTES 32768
#define HGEMM_SMEM (3 * HSTAGE_BYTES)

__device__ __forceinline__ void issue_stage_h(
    const __half* __restrict__ A, const __half* __restrict__ B,
    int K, int k0, uint32_t stage_base, int tid)
{
    #pragma unroll
    for (int i = 0; i < 8; i++) {
        const int idx  = i * 256 + tid;
        const int tile = idx >> 10;
        const int rem  = idx & 1023;
        const int row  = rem >> 3;
        const int quad = rem & 7;
        const __half* src = (tile ? B : A) + (size_t)row * K + k0 + quad * 8;
        const uint32_t dst = stage_base + tile * 16384 + row * 128 +
                             ((quad ^ (row & 7)) * 16);
        CP_ASYNC_CG(dst, src);
    }
}

template <bool GELU, bool RES, bool HALFOUT>
__global__ __launch_bounds__(256, 2)
void hgemm_kernel(const __half* __restrict__ A, const __half* __restrict__ B,
                  const float* __restrict__ bias, const float* __restrict__ res,
                  float* __restrict__ Cf, __half* __restrict__ Ch,
                  int M, int N, int K)
{
    const uint32_t sb = smem_to_u32(dynsmem);
    const int tid = threadIdx.x;
    const int wid = tid >> 5;
    const int lid = tid & 31;

    const int a0 = blockIdx.y * 128;
    const int b0 = blockIdx.x * 128;
    const int m_w = (wid & 3) * 32;
    const int n_w = (wid >> 2) * 64;

    const __half* Ap = A + (size_t)a0 * K;
    const __half* Bp = B + (size_t)b0 * K;

    const int nch = K / BK;

    #pragma unroll
    for (int s = 0; s < 2; s++) {
        issue_stage_h(Ap, Bp, K, s * BK, sb + s * HSTAGE_BYTES, tid);
        CP_ASYNC_COMMIT();
    }

    float acc[2][8][4];
    #pragma unroll
    for (int i = 0; i < 2; i++)
        #pragma unroll
        for (int j = 0; j < 8; j++)
            #pragma unroll
            for (int c = 0; c < 4; c++) acc[i][j][c] = 0.f;

    const int bA  = lid >> 3;
    const int r8  = lid & 7;
    const int rowA_off = ((bA & 1) * 8) + r8;
    const int qA_off   = bA >> 1;
    const int rowB_off = ((bA >> 1) * 8) + r8;
    const int qB_off   = bA & 1;

    for (int i = 0; i < nch; i++) {
        if (i + 1 < nch) { CP_ASYNC_WAIT(1); } else { CP_ASYNC_WAIT(0); }
        __syncthreads();

        if (i + 2 < nch)
            issue_stage_h(Ap, Bp, K, (i + 2) * BK,
                          sb + ((i + 2) % 3) * HSTAGE_BYTES, tid);
        CP_ASYNC_COMMIT();

        const uint32_t st = sb + (i % 3) * HSTAGE_BYTES;
        const uint32_t sA = st, sB = st + 16384;

        #pragma unroll
        for (int ks = 0; ks < 4; ks++) {
            const int kq = ks * 2;
            uint32_t ah[2][4], bh[8][2];

            #pragma unroll
            for (int mt = 0; mt < 2; mt++) {
                const int row  = m_w + mt * 16 + rowA_off;
                const int quad = kq + qA_off;
                const uint32_t off = row * 128 + ((quad ^ (row & 7)) * 16);
                LDMATRIX_X4(ah[mt][0], ah[mt][1], ah[mt][2], ah[mt][3], sA + off);
            }
            #pragma unroll
            for (int np = 0; np < 4; np++) {
                const int row  = n_w + np * 16 + rowB_off;
                const int quad = kq + qB_off;
                const uint32_t off = row * 128 + ((quad ^ (row & 7)) * 16);
                LDMATRIX_X4(bh[np * 2][0], bh[np * 2][1], bh[np * 2 + 1][0], bh[np * 2 + 1][1], sB + off);
            }

            #pragma unroll
            for (int mt = 0; mt < 2; mt++)
                #pragma unroll
                for (int nt = 0; nt < 8; nt++)
                    MMA_F16(acc[mt][nt], ah[mt], bh[nt]);
        }
    }

    const int gl  = lid >> 2;
    const int tg  = lid & 3;
    #pragma unroll
    for (int mt = 0; mt < 2; mt++) {
        #pragma unroll
        for (int half = 0; half < 2; half++) {
            const int row = a0 + m_w + mt * 16 + gl + half * 8;
            #pragma unroll
            for (int nt = 0; nt < 8; nt++) {
                const int col = b0 + n_w + nt * 8 + tg * 2;
                float v0 = acc[mt][nt][half * 2 + 0];
                float v1 = acc[mt][nt][half * 2 + 1];
                const float2 bb = *(const float2*)&bias[col];
                v0 += bb.x; v1 += bb.y;
                if (GELU) { v0 = gelu_exact(v0); v1 = gelu_exact(v1); }
                if (RES) {
                    const float2 r2 = *(const float2*)&res[(size_t)row * N + col];
                    v0 += r2.x; v1 += r2.y;
                }
                if (HALFOUT) {
                    *(uint32_t*)&Ch[(size_t)row * N + col] =
                        pack_h2(__float2half(v0), __float2half(v1));
                } else {
                    float2 o; o.x = v0; o.y = v1;
                    *(float2*)&Cf[(size_t)row * N + col] = o;
                }
            }
        }
    }
}

// ---------------------------------------------------------------------------
// fp16 single-product causal flash attention.
// Grid (SEQ/128, NH, B), 8 warps; warp w owns query rows [16w, 16w+16).
// smem: Q 16KB + 3 stages x {K,V} (16KB each) = 64KB -> 2 CTAs/SM.
// ---------------------------------------------------------------------------
#define ATTH_SMEM (16384 + 3 * 16384)

__global__ __launch_bounds__(256, 2)
void fattn_kernel(const __half* __restrict__ QKV, __half* __restrict__ O)
{
    const uint32_t sb = smem_to_u32(dynsmem);
    const int tid = threadIdx.x;
    const int wid = tid >> 5;
    const int lid = tid & 31;
    const int qt = gridDim.x - 1 - blockIdx.x;   // heavy tiles first
    const int h = blockIdx.y, b = blockIdx.z;
    const int q0 = qt * 128;
    const size_t base = ((size_t)b * SEQ) * LDQKV + h * HD;

    const uint32_t sQ = sb;
    const int nkt = 2 * qt + 2;

    const int bA  = lid >> 3;
    const int r8  = lid & 7;
    const int rowA_off = ((bA & 1) * 8) + r8;
    const int qA_off   = bA >> 1;
    const int rowB_off = ((bA >> 1) * 8) + r8;
    const int qB_off   = bA & 1;
    const int gl = lid >> 2;
    const int tg = lid & 3;

    // ---- prologue: Q (4 iters) + stage0 + stage1 ----
    #pragma unroll
    for (int i = 0; i < 4; i++) {
        const int idx = i * 256 + tid;          // 1024 quads
        const int row = idx >> 3, quad = idx & 7;
        const __half* src = QKV + base + (size_t)(q0 + row) * LDQKV + quad * 8;
        const uint32_t dst = sQ + row * 128 + ((quad ^ (row & 7)) * 16);
        CP_ASYNC_CG(dst, src);
    }
    #pragma unroll
    for (int stg = 0; stg < 2; stg++) {
        const uint32_t st = sb + 16384 + stg * 16384;
        const int key0 = stg * 64;
        #pragma unroll
        for (int i = 0; i < 4; i++) {
            const int idx = i * 256 + tid;      // 1024 quads: K(512) V(512)
            const int tile = idx >> 9;          // 0:K 1:V
            const int rem = idx & 511;
            const int row = rem >> 3, quad = rem & 7;
            const __half* src = QKV + base + (tile ? 2048 : 1024) +
                                (size_t)(key0 + row) * LDQKV + quad * 8;
            const uint32_t dst = st + tile * 8192 + row * 128 + ((quad ^ (row & 7)) * 16);
            CP_ASYNC_CG(dst, src);
        }
        CP_ASYNC_COMMIT();
    }

    CP_ASYNC_WAIT(1);
    __syncthreads();

    // ---- hoist Q fragments (per warp m16 x k64) ----
    uint32_t qh[4][4];
    #pragma unroll
    for (int ks = 0; ks < 4; ks++) {
        const int row  = wid * 16 + rowA_off;
        const int quad = ks * 2 + qA_off;
        const uint32_t off = row * 128 + ((quad ^ (row & 7)) * 16);
        LDMATRIX_X4(qh[ks][0], qh[ks][1], qh[ks][2], qh[ks][3], sQ + off);
    }

    float o[8][4];
    #pragma unroll
    for (int d = 0; d < 8; d++)
        #pragma unroll
        for (int c = 0; c < 4; c++) o[d][c] = 0.f;
    float m0 = -1e30f, m1 = -1e30f, l0 = 0.f, l1 = 0.f;

    const int rowg0 = q0 + wid * 16 + gl;
    const int rowg1 = rowg0 + 8;

    for (int kt = 0; kt < nkt; kt++) {
        if (kt > 0) {
            if (kt + 1 < nkt) { CP_ASYNC_WAIT(1); } else { CP_ASYNC_WAIT(0); }
            __syncthreads();
        }
        if (kt + 2 < nkt) {
            const uint32_t st = sb + 16384 + ((kt + 2) % 3) * 16384;
            const int key0 = (kt + 2) * 64;
            #pragma unroll
            for (int i = 0; i < 4; i++) {
                const int idx = i * 256 + tid;
                const int tile = idx >> 9;
                const int rem = idx & 511;
                const int row = rem >> 3, quad = rem & 7;
                const __half* src = QKV + base + (tile ? 2048 : 1024) +
                                    (size_t)(key0 + row) * LDQKV + quad * 8;
                const uint32_t dst = st + tile * 8192 + row * 128 + ((quad ^ (row & 7)) * 16);
                CP_ASYNC_CG(dst, src);
            }
            CP_ASYNC_COMMIT();
        }

        const uint32_t st = sb + 16384 + (kt % 3) * 16384;
        const uint32_t sK = st, sV = st + 8192;

        // ---- S = Q K^T ----
        float p[8][4];
        #pragma unroll
        for (int nt = 0; nt < 8; nt++)
            #pragma unroll
            for (int c = 0; c < 4; c++) p[nt][c] = 0.f;

        #pragma unroll
        for (int ks = 0; ks < 4; ks++) {
            const int kq = ks * 2;
            uint32_t kh[8][2];
            #pragma unroll
            for (int np = 0; np < 4; np++) {
                const int row  = np * 16 + rowB_off;
                const int quad = kq + qB_off;
                const uint32_t off = row * 128 + ((quad ^ (row & 7)) * 16);
                LDMATRIX_X4(kh[np * 2][0], kh[np * 2][1], kh[np * 2 + 1][0], kh[np * 2 + 1][1], sK + off);
            }
            #pragma unroll
            for (int nt = 0; nt < 8; nt++)
                MMA_F16(p[nt], qh[ks], kh[nt]);
        }

        // ---- scale + mask + online softmax ----
        const int kt0 = kt * 64;
        const bool msk = (kt >= nkt - 2);
        float tmax0 = -1e30f, tmax1 = -1e30f;
        #pragma unroll
        for (int nt = 0; nt < 8; nt++) {
            #pragma unroll
            for (int c = 0; c < 4; c++) {
                float v = p[nt][c] * 0.125f;
                if (msk) {
                    const int col = kt0 + nt * 8 + tg * 2 + (c & 1);
                    const int rg  = (c < 2) ? rowg0 : rowg1;
                    if (col > rg) v = -1e30f;
                }
                p[nt][c] = v;
                if (c < 2) tmax0 = fmaxf(tmax0, v); else tmax1 = fmaxf(tmax1, v);
            }
        }
        tmax0 = fmaxf(tmax0, __shfl_xor_sync(0xffffffffu, tmax0, 1));
        tmax0 = fmaxf(tmax0, __shfl_xor_sync(0xffffffffu, tmax0, 2));
        tmax1 = fmaxf(tmax1, __shfl_xor_sync(0xffffffffu, tmax1, 1));
        tmax1 = fmaxf(tmax1, __shfl_xor_sync(0xffffffffu, tmax1, 2));

        const float mn0 = fmaxf(m0, tmax0);
        const float mn1 = fmaxf(m1, tmax1);
        const float cr0 = __expf(m0 - mn0);
        const float cr1 = __expf(m1 - mn1);
        m0 = mn0; m1 = mn1;
        l0 *= cr0; l1 *= cr1;
        #pragma unroll
        for (int d = 0; d < 8; d++) {
            o[d][0] *= cr0; o[d][1] *= cr0;
            o[d][2] *= cr1; o[d][3] *= cr1;
        }
        #pragma unroll
        for (int nt = 0; nt < 8; nt++) {
            p[nt][0] = __expf(p[nt][0] - mn0);
            p[nt][1] = __expf(p[nt][1] - mn0);
            p[nt][2] = __expf(p[nt][2] - mn1);
            p[nt][3] = __expf(p[nt][3] - mn1);
            l0 += p[nt][0] + p[nt][1];
            l1 += p[nt][2] + p[nt][3];
        }

        // ---- O += P V ----
        #pragma unroll
        for (int s = 0; s < 4; s++) {
            uint32_t pa[4];
            pa[0] = pack_h2(__float2half(p[2 * s][0]),     __float2half(p[2 * s][1]));
            pa[1] = pack_h2(__float2half(p[2 * s][2]),     __float2half(p[2 * s][3]));
            pa[2] = pack_h2(__float2half(p[2 * s + 1][0]), __float2half(p[2 * s + 1][1]));
            pa[3] = pack_h2(__float2half(p[2 * s + 1][2]), __float2half(p[2 * s + 1][3]));

            uint32_t vh[8][2];
            const int mi = lid >> 3;
            #pragma unroll
            for (int dp = 0; dp < 4; dp++) {
                const int row  = s * 16 + ((mi & 1) * 8) + r8;
                const int quad = dp * 2 + (mi >> 1);
                const uint32_t off = row * 128 + ((quad ^ (row & 7)) * 16);
                LDMATRIX_X4_TRANS(vh[dp * 2][0], vh[dp * 2][1], vh[dp * 2 + 1][0], vh[dp * 2 + 1][1], sV + off);
            }
            #pragma unroll
            for (int dt = 0; dt < 8; dt++)
                MMA_F16(o[dt], pa, vh[dt]);
        }
    }

    // ---- finalize: fp16 output ----
    l0 += __shfl_xor_sync(0xffffffffu, l0, 1);
    l0 += __shfl_xor_sync(0xffffffffu, l0, 2);
    l1 += __shfl_xor_sync(0xffffffffu, l1, 1);
    l1 += __shfl_xor_sync(0xffffffffu, l1, 2);
    const float inv0 = 1.0f / l0;
    const float inv1 = 1.0f / l1;

    const size_t tok0 = (size_t)b * SEQ + rowg0;
    const size_t tok1 = tok0 + 8;
    #pragma unroll
    for (int dt = 0; dt < 8; dt++) {
        const int col = h * HD + dt * 8 + tg * 2;
        *(uint32_t*)&O[tok0 * DMODEL + col] =
            pack_h2(__float2half(o[dt][0] * inv0), __float2half(o[dt][1] * inv0));
        *(uint32_t*)&O[tok1 * DMODEL + col] =
            pack_h2(__float2half(o[dt][2] * inv1), __float2half(o[dt][3] * inv1));
    }
}

// ---------------------------------------------------------------------------
// LayerNorm variants
// ---------------------------------------------------------------------------
__device__ __forceinline__ void ln_core(const float4 v, int t, float* rs, float* rss,
                                        float& mu, float& inv)
{
    float s  = v.x + v.y + v.z + v.w;
    float ss = v.x * v.x + v.y * v.y + v.z * v.z + v.w * v.w;
    #pragma unroll
    for (int o = 16; o > 0; o >>= 1) {
        s  += __shfl_xor_sync(0xffffffffu, s,  o);
        ss += __shfl_xor_sync(0xffffffffu, ss, o);
    }
    if ((t & 31) == 0) { rs[t >> 5] = s; rss[t >> 5] = ss; }
    __syncthreads();
    if (t < 32) {
        s  = (t < 8) ? rs[t]  : 0.f;
        ss = (t < 8) ? rss[t] : 0.f;
        #pragma unroll
        for (int o = 4; o > 0; o >>= 1) {
            s  += __shfl_xor_sync(0xffffffffu, s,  o);
            ss += __shfl_xor_sync(0xffffffffu, ss, o);
        }
        if (t == 0) { rs[0] = s; rss[0] = ss; }
    }
    __syncthreads();
    mu = rs[0] * (1.0f / DMODEL);
    const float var = rss[0] * (1.0f / DMODEL) - mu * mu;
    inv = rsqrtf(var + 1e-5f);
}

__global__ __launch_bounds__(256)
void ln_split_kernel(const float* __restrict__ x, const float* __restrict__ g,
                     const float* __restrict__ b, bf16* __restrict__ ohi, bf16* __restrict__ olo)
{
    const int row = blockIdx.x;
    const int t   = threadIdx.x;
    const float4 v = ((const float4*)(x + (size_t)row * DMODEL))[t];
    __shared__ float rs[8], rss[8];
    float mu, inv;
    ln_core(v, t, rs, rss, mu, inv);

    const float4 gv = ((const float4*)g)[t];
    const float4 bv = ((const float4*)b)[t];
    float o[4];
    o[0] = (v.x - mu) * inv * gv.x + bv.x;
    o[1] = (v.y - mu) * inv * gv.y + bv.y;
    o[2] = (v.z - mu) * inv * gv.z + bv.z;
    o[3] = (v.w - mu) * inv * gv.w + bv.w;

    uint32_t hp[2], lp[2];
    #pragma unroll
    for (int i = 0; i < 2; i++) {
        const bf16 h0 = __float2bfloat16(o[2 * i]);
        const bf16 h1 = __float2bfloat16(o[2 * i + 1]);
        hp[i] = pack_bf2(h0, h1);
        lp[i] = pack_bf2(__float2bfloat16(o[2 * i] - __bfloat162float(h0)),
                         __float2bfloat16(o[2 * i + 1] - __bfloat162float(h1)));
    }
    ((uint2*)(ohi + (size_t)row * DMODEL))[t] = make_uint2(hp[0], hp[1]);
    ((uint2*)(olo + (size_t)row * DMODEL))[t] = make_uint2(lp[0], lp[1]);
}

__global__ __launch_bounds__(256)
void ln_half_kernel(const float* __restrict__ x, const float* __restrict__ g,
                    const float* __restrict__ b, __half* __restrict__ oh)
{
    const int row = blockIdx.x;
    const int t   = threadIdx.x;
    const float4 v = ((const float4*)(x + (size_t)row * DMODEL))[t];
    __shared__ float rs[8], rss[8];
    float mu, inv;
    ln_core(v, t, rs, rss, mu, inv);

    const float4 gv = ((const float4*)g)[t];
    const float4 bv = ((const float4*)b)[t];
    float o[4];
    o[0] = (v.x - mu) * inv * gv.x + bv.x;
    o[1] = (v.y - mu) * inv * gv.y + bv.y;
    o[2] = (v.z - mu) * inv * gv.z + bv.z;
    o[3] = (v.w - mu) * inv * gv.w + bv.w;

    uint2 pk;
    pk.x = pack_h2(__float2half(o[0]), __float2half(o[1]));
    pk.y = pack_h2(__float2half(o[2]), __float2half(o[3]));
    ((uint2*)(oh + (size_t)row * DMODEL))[t] = pk;
}

// ---------------------------------------------------------------------------
// Weight prep
// ---------------------------------------------------------------------------
__device__ __forceinline__ void tsplit_tile(const float* __restrict__ W,
                                            bf16* __restrict__ Thi, bf16* __restrict__ Tlo,
                                            int K, int N, int bx, int by, int tx, int ty)
{
    __shared__ float tile[32][33];
    const int kx = by * 32;
    const int nx = bx * 32;

    #pragma unroll
    for (int j = ty; j < 32; j += 8)
        tile[j][tx] = W[(size_t)(kx + j) * N + nx + tx];
    __syncthreads();

    #pragma unroll
    for (int b = ty; b < 32; b += 8) {
        const float v = tile[tx][b];
        const bf16 h = __float2bfloat16(v);
        const bf16 l = __float2bfloat16(v - __bfloat162float(h));
        Thi[(size_t)(nx + b) * K + kx + tx] = h;
        Tlo[(size_t)(nx + b) * K + kx + tx] = l;
    }
}

__device__ __forceinline__ void htile(const float* __restrict__ W, __half* __restrict__ T,
                                      int K, int N, int bx, int by, int tx, int ty)
{
    __shared__ float tile2[32][33];
    const int kx = by * 32;
    const int nx = bx * 32;

    #pragma unroll
    for (int j = ty; j < 32; j += 8)
        tile2[j][tx] = W[(size_t)(kx + j) * N + nx + tx];
    __syncthreads();

    #pragma unroll
    for (int b = ty; b < 32; b += 8)
        T[(size_t)(nx + b) * K + kx + tx] = __float2half(tile2[tx][b]);
}

// prep1: wq|wk|wv -> packed wqkv (bf16 hi/lo) + bias concat
__global__ void prep1_kernel(const float* __restrict__ wq, const float* __restrict__ wk,
                             const float* __restrict__ wv,
                             const float* __restrict__ bq, const float* __restrict__ bk,
                             const float* __restrict__ bv,
                             bf16* __restrict__ wqkvh, bf16* __restrict__ wqkvl,
                             float* __restrict__ bqkv)
{
    const int id = blockIdx.x;
    const int z  = id >> 10;
    const int t  = id & 1023;
    const int bx = t & 31, by = t >> 5;
    const int tx = threadIdx.x, ty = threadIdx.y;
    const int tid = ty * 32 + tx;

    const float* W = (z == 0) ? wq : (z == 1) ? wk : wv;
    tsplit_tile(W, wqkvh + (size_t)z * 1024 * DMODEL, wqkvl + (size_t)z * 1024 * DMODEL,
                DMODEL, DMODEL, bx, by, tx, ty);

    if (t == 0) {
        const float* src = (z == 0) ? bq : (z == 1) ? bk : bv;
        for (int i = tid; i < 1024; i += 256)
            bqkv[z * 1024 + i] = src[i];
    }
}

// prep2: wo (fp16, 1024 tiles) | w1 (fp16, 4096 tiles) | w2 (fp16, 4096 tiles)
__global__ void prep2_kernel(const float* __restrict__ wo, const float* __restrict__ w1,
                             const float* __restrict__ w2,
                             __half* __restrict__ wos,
                             __half* __restrict__ w1s, __half* __restrict__ w2s)
{
    const int id = blockIdx.x;
    const int tx = threadIdx.x, ty = threadIdx.y;

    if (id < 1024) {
        htile(wo, wos, DMODEL, DMODEL, id & 31, id >> 5, tx, ty);
    } else if (id < 5120) {
        const int t = id - 1024;
        htile(w1, w1s, DMODEL, DFF, t & 127, t >> 7, tx, ty);
    } else {
        const int t = id - 5120;
        htile(w2, w2s, DFF, DMODEL, t & 31, t >> 5, tx, ty);
    }
}

// ---------------------------------------------------------------------------
// Orchestration
// ---------------------------------------------------------------------------
extern "C" void kernel_launch(void* const* d_in, const int* in_sizes, int n_in,
                              void* d_out, int out_size)
{
    const float* x     = (const float*)d_in[0];
    const float* wq    = (const float*)d_in[1];
    const float* bq    = (const float*)d_in[2];
    const float* wk    = (const float*)d_in[3];
    const float* bk    = (const float*)d_in[4];
    const float* wv    = (const float*)d_in[5];
    const float* bv    = (const float*)d_in[6];
    const float* wo    = (const float*)d_in[7];
    const float* bo    = (const float*)d_in[8];
    const float* w1    = (const float*)d_in[9];
    const float* b1    = (const float*)d_in[10];
    const float* w2    = (const float*)d_in[11];
    const float* b2    = (const float*)d_in[12];
    const float* ln1_g = (const float*)d_in[13];
    const float* ln1_b = (const float*)d_in[14];
    const float* ln2_g = (const float*)d_in[15];
    const float* ln2_b = (const float*)d_in[16];
    float* out = (float*)d_out;

    float *x1, *bqkv;
    bf16 *nhi, *nlo, *wqkvh, *wqkvl;
    __half *qkv, *ao, *n2h, *hh, *wos, *w1s, *w2s;
    cudaGetSymbolAddress((void**)&x1,    g_x1);
    cudaGetSymbolAddress((void**)&bqkv,  g_bqkv);
    cudaGetSymbolAddress((void**)&nhi,   g_nhi);
    cudaGetSymbolAddress((void**)&nlo,   g_nlo);
    cudaGetSymbolAddress((void**)&qkv,   g_qkv);
    cudaGetSymbolAddress((void**)&ao,    g_ao);
    cudaGetSymbolAddress((void**)&n2h,   g_n2h);
    cudaGetSymbolAddress((void**)&hh,    g_hh);
    cudaGetSymbolAddress((void**)&wqkvh, g_wqkvh);
    cudaGetSymbolAddress((void**)&wqkvl, g_wqkvl);
    cudaGetSymbolAddress((void**)&wos,   g_wos);
    cudaGetSymbolAddress((void**)&w1s,   g_w1s);
    cudaGetSymbolAddress((void**)&w2s,   g_w2s);

    cudaFuncSetAttribute(fattn_kernel, cudaFuncAttributeMaxDynamicSharedMemorySize, ATTH_SMEM);
    cudaFuncSetAttribute(tgemm_kernel, cudaFuncAttributeMaxDynamicSharedMemorySize, TGEMM_SMEM);
    cudaFuncSetAttribute(hgemm_kernel<true, false, true>,
                         cudaFuncAttributeMaxDynamicSharedMemorySize, HGEMM_SMEM);
    cudaFuncSetAttribute(hgemm_kernel<false, true, false>,
                         cudaFuncAttributeMaxDynamicSharedMemorySize, HGEMM_SMEM);

    dim3 tb(32, 8);
    prep1_kernel<<<3072, tb>>>(wq, wk, wv, bq, bk, bv, wqkvh, wqkvl, bqkv);
    prep2_kernel<<<9216, tb>>>(wo, w1, w2, wos, w1s, w2s);

    // LN1 -> split bf16
    ln_split_kernel<<<MTOK, 256>>>(x, ln1_g, ln1_b, nhi, nlo);

    // Fused QKV projection (bf16 3-term) -> packed fp16 single
    dim3 gQKV(LDQKV / 128, MTOK / 128);
    tgemm_kernel<<<gQKV, 256, TGEMM_SMEM>>>(
        nhi, nlo, wqkvh, wqkvl, bqkv, qkv, MTOK, LDQKV, DMODEL);

    // Causal flash attention (fp16 single) -> fp16
    fattn_kernel<<<dim3(SEQ / 128, NH, 4), 256, ATTH_SMEM>>>(qkv, ao);

    // O-projection (fp16 single) + residual -> fp32
    dim3 gP(DMODEL / 128, MTOK / 128);
    hgemm_kernel<false, true, false><<<gP, 256, HGEMM_SMEM>>>(
        ao, wos, bo, x, x1, nullptr, MTOK, DMODEL, DMODEL);

    // LN2 -> fp16 single
    ln_half_kernel<<<MTOK, 256>>>(x1, ln2_g, ln2_b, n2h);

    // FF1 (fp16 single) with GELU -> fp16
    dim3 gF1(DFF / 128, MTOK / 128);
    hgemm_kernel<true, false, true><<<gF1, 256, HGEMM_SMEM>>>(
        n2h, w1s, b1, nullptr, nullptr, hh, MTOK, DFF, DMODEL);

    // FF2 (fp16 single) + residual -> final fp32 output
    dim3 gF2(DMODEL / 128, MTOK / 128);
    hgemm_kernel<false, true, false><<<gF2, 256, HGEMM_SMEM>>>(
        hh, w2s, b2, x1, out, nullptr, MTOK, DMODEL, DFF);
}